// round 12
// baseline (speedup 1.0000x reference)
#include <cuda_runtime.h>
#include <cuda_bf16.h>
#include <math.h>
#include <stdint.h>

#define B_      1024
#define P_      11
#define C_      8
#define H_      512
#define T_      200
#define L_      2000
#define STRIDE_ 180
#define M_      (B_*P_*C_)

typedef unsigned long long u64;
typedef unsigned int u32;
typedef __nv_bfloat16 bf16;

// ---------------- scratch (device globals) ----------------
__device__ bf16 g_Xh[(size_t)M_ * 512];
__device__ bf16 g_Xl[(size_t)M_ * 512];
__device__ bf16 g_Hh[(size_t)M_ * 512];
__device__ bf16 g_Hl[(size_t)M_ * 512];
__device__ bf16 g_W1th[512 * 512];
__device__ bf16 g_W1tl[512 * 512];
__device__ bf16 g_W2th[256 * 512];
__device__ bf16 g_W2tl[256 * 512];
__device__ float g_patches[(size_t)M_ * T_];
__device__ bf16 g_rech[(size_t)B_ * L_ * 8];
__device__ bf16 g_recl[(size_t)B_ * L_ * 8];
__device__ bf16 g_r1h[(size_t)B_ * L_ * 32];
__device__ bf16 g_r1l[(size_t)B_ * L_ * 32];
__device__ bf16 g_r2h[(size_t)B_ * L_ * 16];
__device__ bf16 g_r2l[(size_t)B_ * L_ * 16];
__device__ bf16 g_cw1h[32 * 128];
__device__ bf16 g_cw1l[32 * 128];
__device__ bf16 g_w2h[16 * 480];
__device__ bf16 g_w2l[16 * 480];
__device__ bf16 g_cw3h[8 * 240];
__device__ bf16 g_cw3l[8 * 240];

__device__ __forceinline__ float gelu_erf(float x) {
    return 0.5f * x * (1.0f + erff(x * 0.7071067811865476f));
}

// ---------------- warp MMA primitives ----------------
__device__ __forceinline__ uint32_t smem_u32(const void* p) {
    uint32_t a;
    asm("{ .reg .u64 t; cvta.to.shared.u64 t, %1; cvt.u32.u64 %0, t; }" : "=r"(a) : "l"(p));
    return a;
}
__device__ __forceinline__ void ldsm_x4(u32& r0, u32& r1, u32& r2, u32& r3, u32 addr) {
    asm volatile("ldmatrix.sync.aligned.m8n8.x4.shared.b16 {%0,%1,%2,%3}, [%4];"
        : "=r"(r0), "=r"(r1), "=r"(r2), "=r"(r3) : "r"(addr));
}
__device__ __forceinline__ void ldsm_x2(u32& r0, u32& r1, u32 addr) {
    asm volatile("ldmatrix.sync.aligned.m8n8.x2.shared.b16 {%0,%1}, [%2];"
        : "=r"(r0), "=r"(r1) : "r"(addr));
}
__device__ __forceinline__ void mma_bf16(float* d, const u32* a, const u32* b) {
    asm volatile("mma.sync.aligned.m16n8k16.row.col.f32.bf16.bf16.f32 "
        "{%0,%1,%2,%3}, {%4,%5,%6,%7}, {%8,%9}, {%0,%1,%2,%3};"
        : "+f"(d[0]), "+f"(d[1]), "+f"(d[2]), "+f"(d[3])
        : "r"(a[0]), "r"(a[1]), "r"(a[2]), "r"(a[3]), "r"(b[0]), "r"(b[1]));
}
__device__ __forceinline__ void split_bf16(float v, bf16& h, bf16& l) {
    h = __float2bfloat16(v);
    l = __float2bfloat16(v - __bfloat162float(h));
}
#define CP_ASYNC16(s, g) \
    asm volatile("cp.async.cg.shared.global [%0], [%1], 16;" :: "r"(s), "l"(g))
#define CP_COMMIT() asm volatile("cp.async.commit_group;")
#define CP_WAIT0()  asm volatile("cp.async.wait_group 0;" ::: "memory")

// ================= prep kernels =================
__global__ void split_f32_kernel(const float* __restrict__ x,
                                 bf16* __restrict__ hh, bf16* __restrict__ hl, int n4)
{
    int i = blockIdx.x * 256 + threadIdx.x;
    if (i >= n4) return;
    float4 v = reinterpret_cast<const float4*>(x)[i];
    float f[4] = {v.x, v.y, v.z, v.w};
    bf16 h[4], l[4];
#pragma unroll
    for (int j = 0; j < 4; j++) split_bf16(f[j], h[j], l[j]);
    __nv_bfloat162* ph = reinterpret_cast<__nv_bfloat162*>(hh) + 2 * (size_t)i;
    __nv_bfloat162* pl = reinterpret_cast<__nv_bfloat162*>(hl) + 2 * (size_t)i;
    ph[0] = __halves2bfloat162(h[0], h[1]); ph[1] = __halves2bfloat162(h[2], h[3]);
    pl[0] = __halves2bfloat162(l[0], l[1]); pl[1] = __halves2bfloat162(l[2], l[3]);
}

__global__ void transp_split_kernel(const float* __restrict__ W,
                                    bf16* __restrict__ th, bf16* __restrict__ tl,
                                    int Kdim, int Nsrc, int Npad)
{
    int idx = blockIdx.x * 256 + threadIdx.x;
    if (idx >= Npad * Kdim) return;
    int n = idx / Kdim, k = idx - n * Kdim;
    float f = (n < Nsrc) ? W[(size_t)k * Nsrc + n] : 0.0f;
    split_bf16(f, th[idx], tl[idx]);
}

__global__ void w1c_prep_kernel(const float* __restrict__ w,
                                bf16* __restrict__ wh, bf16* __restrict__ wl)
{
    int idx = blockIdx.x * 256 + threadIdx.x;
    if (idx >= 32 * 128) return;
    int co = idx >> 7, c = idx & 127;
    int ks = c >> 4, rem = c & 15;
    int tap = 2 * ks + (rem >> 3);
    int ic = rem & 7;
    float f = (tap < 15) ? w[((size_t)co * 8 + ic) * 15 + tap] : 0.0f;
    split_bf16(f, wh[idx], wl[idx]);
}

__global__ void w2_prep_kernel(const float* __restrict__ w,
                               bf16* __restrict__ wh, bf16* __restrict__ wl)
{
    int idx = blockIdx.x * 256 + threadIdx.x;
    if (idx >= 16 * 480) return;
    int co = idx / 480, c = idx - co * 480;
    int k = c >> 5, ic = c & 31;
    float f = w[((size_t)co * 32 + ic) * 15 + k];
    split_bf16(f, wh[idx], wl[idx]);
}

__global__ void w3c_prep_kernel(const float* __restrict__ w,
                                bf16* __restrict__ wh, bf16* __restrict__ wl)
{
    int idx = blockIdx.x * 256 + threadIdx.x;
    if (idx >= 8 * 240) return;
    int co = idx / 240, c = idx - co * 240;
    int k = c >> 4, ic = c & 15;
    float f = w[((size_t)co * 16 + ic) * 15 + k];
    split_bf16(f, wh[idx], wl[idx]);
}

// ================= HMMA GEMM v3: block 256x64, warp m64n32, cp.async pipeline =================
#define ASTR 40
#define A_ELE (256 * ASTR)     // 10240 elements per buffer per split
#define B_ELE (64 * ASTR)      // 2560
#define A_BYTES (A_ELE * 2)    // 20480
#define B_BYTES (B_ELE * 2)    // 5120
#define GEMM_SMEM ((2 * A_ELE * 2 + 2 * B_ELE * 2) * 2)   // 102400 bytes

template<bool GELU_SPLIT>
__global__ void __launch_bounds__(256, 2) gemm_hmma(
    const bf16* __restrict__ Ah, const bf16* __restrict__ Al,
    const bf16* __restrict__ Bh, const bf16* __restrict__ Bl,
    const float* __restrict__ bias, int Nvalid,
    bf16* __restrict__ outHh, bf16* __restrict__ outHl, float* __restrict__ outF)
{
    extern __shared__ __align__(16) char dynsm[];
    bf16* sA_h = (bf16*)dynsm;            // [2][A_ELE]
    bf16* sA_l = sA_h + 2 * A_ELE;
    bf16* sB_h = sA_l + 2 * A_ELE;        // [2][B_ELE]
    bf16* sB_l = sB_h + 2 * B_ELE;

    const int tid  = threadIdx.x;
    const int lane = tid & 31;
    const int wid  = tid >> 5;
    const int wm   = wid & 3;             // 4 m-warps, 64 rows each
    const int wn   = wid >> 2;            // 2 n-warps, 32 cols each
    const int bm   = blockIdx.y * 256;
    const int bn   = blockIdx.x * 64;

    float acc[4][4][4];
#pragma unroll
    for (int mi = 0; mi < 4; mi++)
#pragma unroll
        for (int ni = 0; ni < 4; ni++)
#pragma unroll
            for (int q = 0; q < 4; q++) acc[mi][ni][q] = 0.0f;

    const u32 sbAh = smem_u32(sA_h), sbAl = smem_u32(sA_l);
    const u32 sbBh = smem_u32(sB_h), sbBl = smem_u32(sB_l);

    // cp.async loader mapping: A chunks (16B = 8 bf16). 1024 chunks/split, 4/thread.
    const int arow = tid >> 2;            // base row 0..63 (advance by 64 per j)
    const int acnk = tid & 3;             // chunk 0..3 within row (8 bf16 each)
    const int brow = tid >> 2;            // B row 0..63
    // smem byte offsets (within one buffer)
    const u32 saOff = (u32)(arow * ASTR + acnk * 8) * 2;
    const u32 sbOff = (u32)(brow * ASTR + acnk * 8) * 2;

    // ldsm addresses
    const int lrow = lane & 15;
    const int lhalf = (lane >> 4) * 8;
    const u32 aoffB0 = ((wn * 32 +      lrow) * ASTR + lhalf) * 2;
    const u32 aoffB1 = ((wn * 32 + 16 + lrow) * ASTR + lhalf) * 2;

    // issue tile 0
    {
        const int k0 = 0;
#pragma unroll
        for (int j = 0; j < 4; j++) {
            int row = arow + j * 64;
            size_t g = (size_t)(bm + row) * 512 + k0 + acnk * 8;
            u32 s = saOff + (u32)(j * 64 * ASTR) * 2;
            CP_ASYNC16(sbAh + s, Ah + g);
            CP_ASYNC16(sbAl + s, Al + g);
        }
        size_t gb = (size_t)(bn + brow) * 512 + k0 + acnk * 8;
        CP_ASYNC16(sbBh + sbOff, Bh + gb);
        CP_ASYNC16(sbBl + sbOff, Bl + gb);
        CP_COMMIT();
    }

    for (int kt = 0; kt < 16; kt++) {
        const int cur = kt & 1;
        CP_WAIT0();
        __syncthreads();          // tile kt visible to all

        if (kt < 15) {            // issue tile kt+1 into other buffer
            const int nxt = cur ^ 1;
            const int k0 = (kt + 1) * 32;
            const u32 aB = (u32)(nxt * A_BYTES), bB = (u32)(nxt * B_BYTES);
#pragma unroll
            for (int j = 0; j < 4; j++) {
                int row = arow + j * 64;
                size_t g = (size_t)(bm + row) * 512 + k0 + acnk * 8;
                u32 s = aB + saOff + (u32)(j * 64 * ASTR) * 2;
                CP_ASYNC16(sbAh + s, Ah + g);
                CP_ASYNC16(sbAl + s, Al + g);
            }
            size_t gb = (size_t)(bn + brow) * 512 + k0 + acnk * 8;
            CP_ASYNC16(sbBh + bB + sbOff, Bh + gb);
            CP_ASYNC16(sbBl + bB + sbOff, Bl + gb);
            CP_COMMIT();
        }

        const u32 aB = (u32)(cur * A_BYTES), bB = (u32)(cur * B_BYTES);
#pragma unroll
        for (int kk = 0; kk < 2; kk++) {
            const u32 kadd = kk * 32;
            u32 t0, t1, t2, t3;
            u32 bh[4][2], bl[4][2];
            ldsm_x4(t0, t1, t2, t3, sbBh + bB + aoffB0 + kadd);
            bh[0][0] = t0; bh[0][1] = t2; bh[1][0] = t1; bh[1][1] = t3;
            ldsm_x4(t0, t1, t2, t3, sbBh + bB + aoffB1 + kadd);
            bh[2][0] = t0; bh[2][1] = t2; bh[3][0] = t1; bh[3][1] = t3;
            ldsm_x4(t0, t1, t2, t3, sbBl + bB + aoffB0 + kadd);
            bl[0][0] = t0; bl[0][1] = t2; bl[1][0] = t1; bl[1][1] = t3;
            ldsm_x4(t0, t1, t2, t3, sbBl + bB + aoffB1 + kadd);
            bl[2][0] = t0; bl[2][1] = t2; bl[3][0] = t1; bl[3][1] = t3;

#pragma unroll
            for (int mi = 0; mi < 4; mi++) {
                const u32 aoffA = ((wm * 64 + mi * 16 + lrow) * ASTR + lhalf) * 2 + kadd;
                u32 ah[4], al[4];
                ldsm_x4(ah[0], ah[1], ah[2], ah[3], sbAh + aB + aoffA);
                ldsm_x4(al[0], al[1], al[2], al[3], sbAl + aB + aoffA);
#pragma unroll
                for (int ni = 0; ni < 4; ni++) mma_bf16(acc[mi][ni], ah, bh[ni]);
#pragma unroll
                for (int ni = 0; ni < 4; ni++) mma_bf16(acc[mi][ni], ah, bl[ni]);
#pragma unroll
                for (int ni = 0; ni < 4; ni++) mma_bf16(acc[mi][ni], al, bh[ni]);
            }
        }
        __syncthreads();          // all reads of buf[cur] done before it's rewritten
    }

    const int grp = lane >> 2;
    const int qc  = (lane & 3) * 2;
#pragma unroll
    for (int mi = 0; mi < 4; mi++) {
        const int r0 = bm + wm * 64 + mi * 16 + grp;
        const int r1 = r0 + 8;
#pragma unroll
        for (int ni = 0; ni < 4; ni++) {
            const int col = bn + wn * 32 + ni * 8 + qc;
            float bv0 = __ldg(&bias[col]), bv1 = __ldg(&bias[col + 1]);
            float v00 = acc[mi][ni][0] + bv0, v01 = acc[mi][ni][1] + bv1;
            float v10 = acc[mi][ni][2] + bv0, v11 = acc[mi][ni][3] + bv1;
            if (GELU_SPLIT) {
                v00 = gelu_erf(v00); v01 = gelu_erf(v01);
                v10 = gelu_erf(v10); v11 = gelu_erf(v11);
                bf16 h0, h1, l0, l1;
                split_bf16(v00, h0, l0); split_bf16(v01, h1, l1);
                size_t i0 = (size_t)r0 * 256 + (col >> 1);
                reinterpret_cast<__nv_bfloat162*>(outHh)[i0] = __halves2bfloat162(h0, h1);
                reinterpret_cast<__nv_bfloat162*>(outHl)[i0] = __halves2bfloat162(l0, l1);
                split_bf16(v10, h0, l0); split_bf16(v11, h1, l1);
                size_t i1 = (size_t)r1 * 256 + (col >> 1);
                reinterpret_cast<__nv_bfloat162*>(outHh)[i1] = __halves2bfloat162(h0, h1);
                reinterpret_cast<__nv_bfloat162*>(outHl)[i1] = __halves2bfloat162(l0, l1);
            } else {
                if (col < Nvalid) {
                    *(float2*)(outF + (size_t)r0 * Nvalid + col) = make_float2(v00, v01);
                    *(float2*)(outF + (size_t)r1 * Nvalid + col) = make_float2(v10, v11);
                }
            }
        }
    }
}

// ================= overlap-add -> rec bf16 split [b][l][8] =================
__global__ void overlap_add_v3(const float* __restrict__ patches,
                               bf16* __restrict__ rech, bf16* __restrict__ recl)
{
    const int b  = blockIdx.y;
    const int l  = blockIdx.x * 256 + threadIdx.x;
    if (l >= L_) return;

    int i_lo = l - (T_ - 1);
    i_lo = (i_lo > 0) ? (i_lo + STRIDE_ - 1) / STRIDE_ : 0;
    int i_hi = l / STRIDE_;
    if (i_hi > P_ - 1) i_hi = P_ - 1;

    int np = 0, pi[2], pt[2];
    float wv[2], ws = 0.0f;
    for (int i = i_lo; i <= i_hi; i++) {
        int t = l - i * STRIDE_;
        float w;
        if (t < 50)        w = (float)t * (1.0f / 49.0f);
        else if (t >= 150) w = (float)(199 - t) * (1.0f / 49.0f);
        else               w = 1.0f;
        pi[np] = i; pt[np] = t; wv[np] = w; ws += w; np++;
    }
    float ews = fmaxf(ws, 1e-8f);

    unsigned short hh[8], ll[8];
#pragma unroll
    for (int c = 0; c < 8; c++) {
        float v = 0.0f;
        for (int j = 0; j < np; j++)
            v += patches[(((size_t)b * P_ + pi[j]) * C_ + c) * T_ + pt[j]] * wv[j];
        v = v / ews;
        bf16 h, lo; split_bf16(v, h, lo);
        hh[c] = __bfloat16_as_ushort(h);
        ll[c] = __bfloat16_as_ushort(lo);
    }
    size_t o = ((size_t)b * L_ + l) * 8;
    *(uint4*)(rech + o) = *(uint4*)hh;
    *(uint4*)(recl + o) = *(uint4*)ll;
}

// ================= conv1 (R11): 256-pos tile, warp m32 =================
#define C1ROWS 271
#define C1SM (2 * (C1ROWS * 40 * 2) + 2 * (32 * 136 * 2))
__global__ void __launch_bounds__(256) conv1_hmma(
    const bf16* __restrict__ rech, const bf16* __restrict__ recl,
    const bf16* __restrict__ wh, const bf16* __restrict__ wl,
    const float* __restrict__ bias,
    bf16* __restrict__ r1h, bf16* __restrict__ r1l)
{
    extern __shared__ __align__(16) char dsm1[];
    bf16* sXh = (bf16*)dsm1;
    bf16* sXl = sXh + C1ROWS * 40;
    bf16* sWh = sXl + C1ROWS * 40;
    bf16* sWl = sWh + 32 * 136;

    const int tid  = threadIdx.x;
    const int lane = tid & 31;
    const int wm   = tid >> 5;
    const int b    = blockIdx.y;
    const int t0   = blockIdx.x * 256;

    for (int i = tid; i < 32 * 64; i += 256) {
        int r = i >> 6, q = i & 63;
        ((u32*)sWh)[r * 68 + q] = ((const u32*)wh)[r * 64 + q];
        ((u32*)sWl)[r * 68 + q] = ((const u32*)wl)[r * 64 + q];
    }
    for (int i = tid; i < C1ROWS * 2; i += 256) {
        int r = i >> 1, half = i & 1;
        int gp = t0 + r - 7 + half;
        uint4 vh = make_uint4(0,0,0,0), vl = vh;
        if (gp >= 0 && gp < L_) {
            size_t o = ((size_t)b * L_ + gp) * 8;
            vh = *(const uint4*)(rech + o);
            vl = *(const uint4*)(recl + o);
        }
        *(uint4*)(sXh + r * 40 + half * 8) = vh;
        *(uint4*)(sXl + r * 40 + half * 8) = vl;
    }
    __syncthreads();

    const u32 sbXh = smem_u32(sXh), sbXl = smem_u32(sXl);
    const u32 sbWh = smem_u32(sWh), sbWl = smem_u32(sWl);
    const int lrow = lane & 15;
    const int lhalf = (lane >> 4) * 8;
    const int grp = lane >> 2, qc = (lane & 3) * 2;

    float acc[2][4][4];
#pragma unroll
    for (int mi = 0; mi < 2; mi++)
#pragma unroll
        for (int ni = 0; ni < 4; ni++)
#pragma unroll
            for (int q = 0; q < 4; q++) acc[mi][ni][q] = 0.0f;

#pragma unroll
    for (int k = 0; k < 8; k++) {
        u32 ah[2][4], al[2][4];
#pragma unroll
        for (int mi = 0; mi < 2; mi++) {
            u32 aadd = (u32)((wm * 32 + mi * 16 + lrow + 2 * k) * 40 + lhalf) * 2;
            ldsm_x4(ah[mi][0], ah[mi][1], ah[mi][2], ah[mi][3], sbXh + aadd);
            ldsm_x4(al[mi][0], al[mi][1], al[mi][2], al[mi][3], sbXl + aadd);
        }
        u32 t0r, t1r, t2r, t3r;
        u32 bh[4][2], bl[4][2];
#pragma unroll
        for (int na2 = 0; na2 < 2; na2++) {
            u32 badd = (u32)((na2 * 16 + lrow) * 136 + k * 16 + lhalf) * 2;
            ldsm_x4(t0r, t1r, t2r, t3r, sbWh + badd);
            bh[na2*2][0] = t0r; bh[na2*2][1] = t2r;
            bh[na2*2+1][0] = t1r; bh[na2*2+1][1] = t3r;
            ldsm_x4(t0r, t1r, t2r, t3r, sbWl + badd);
            bl[na2*2][0] = t0r; bl[na2*2][1] = t2r;
            bl[na2*2+1][0] = t1r; bl[na2*2+1][1] = t3r;
        }
#pragma unroll
        for (int s = 0; s < 3; s++)
#pragma unroll
            for (int mi = 0; mi < 2; mi++)
#pragma unroll
                for (int ni = 0; ni < 4; ni++) {
                    const u32* aa = (s == 2) ? al[mi] : ah[mi];
                    const u32* bb = (s == 1) ? bl[ni] : bh[ni];
                    mma_bf16(acc[mi][ni], aa, bb);
                }
    }
    __syncthreads();

    u32* stgh = (u32*)sXh;
    u32* stgl = (u32*)sXl;
#pragma unroll
    for (int mi = 0; mi < 2; mi++)
#pragma unroll
        for (int ni = 0; ni < 4; ni++) {
            int ch = ni * 8 + qc;
            float bv0 = __ldg(&bias[ch]), bv1 = __ldg(&bias[ch + 1]);
            int p0 = wm * 32 + mi * 16 + grp, p1 = p0 + 8;
            float v00 = gelu_erf(acc[mi][ni][0] + bv0), v01 = gelu_erf(acc[mi][ni][1] + bv1);
            float v10 = gelu_erf(acc[mi][ni][2] + bv0), v11 = gelu_erf(acc[mi][ni][3] + bv1);
            bf16 h0, h1, l0, l1;
            split_bf16(v00, h0, l0); split_bf16(v01, h1, l1);
            __nv_bfloat162 th = __halves2bfloat162(h0, h1), tl = __halves2bfloat162(l0, l1);
            stgh[p0 * 17 + ni * 4 + (lane & 3)] = *(u32*)&th;
            stgl[p0 * 17 + ni * 4 + (lane & 3)] = *(u32*)&tl;
            split_bf16(v10, h0, l0); split_bf16(v11, h1, l1);
            th = __halves2bfloat162(h0, h1); tl = __halves2bfloat162(l0, l1);
            stgh[p1 * 17 + ni * 4 + (lane & 3)] = *(u32*)&th;
            stgl[p1 * 17 + ni * 4 + (lane & 3)] = *(u32*)&tl;
        }
    __syncthreads();
    for (int i = tid; i < 256 * 16; i += 256) {
        int p = i >> 4, q = i & 15;
        int l = t0 + p;
        if (l < L_) {
            size_t o = ((size_t)b * L_ + l) * 16 + q;
            ((u32*)r1h)[o] = stgh[p * 17 + q];
            ((u32*)r1l)[o] = stgl[p * 17 + q];
        }
    }
}

// ================= conv2 (R11): 256-pos tile, warp m32 =================
#define C2ROWS 272
#define C2SM (2 * (C2ROWS * 40 * 2) + 2 * (16 * 488 * 2))
__global__ void __launch_bounds__(256) conv2_hmma(
    const bf16* __restrict__ r1h, const bf16* __restrict__ r1l,
    const bf16* __restrict__ wh, const bf16* __restrict__ wl,
    const float* __restrict__ bias,
    bf16* __restrict__ r2h, bf16* __restrict__ r2l)
{
    extern __shared__ __align__(16) char dsm2[];
    bf16* sXh = (bf16*)dsm2;
    bf16* sXl = sXh + C2ROWS * 40;
    bf16* sWh = sXl + C2ROWS * 40;
    bf16* sWl = sWh + 16 * 488;

    const int tid  = threadIdx.x;
    const int lane = tid & 31;
    const int wm   = tid >> 5;
    const int b    = blockIdx.y;
    const int t0   = blockIdx.x * 256;

    for (int i = tid; i < 16 * 240; i += 256) {
        int r = i / 240, c = i - r * 240;
        ((u32*)sWh)[r * 244 + c] = ((const u32*)wh)[r * 240 + c];
        ((u32*)sWl)[r * 244 + c] = ((const u32*)wl)[r * 240 + c];
    }
    for (int i = tid; i < C2ROWS * 4; i += 256) {
        int r = i >> 2, q = i & 3;
        int gp = t0 + r - 7;
        uint4 vh = make_uint4(0,0,0,0), vl = vh;
        if (gp >= 0 && gp < L_) {
            size_t o = ((size_t)b * L_ + gp) * 32 + q * 8;
            vh = *(const uint4*)(r1h + o);
            vl = *(const uint4*)(r1l + o);
        }
        *(uint4*)(sXh + r * 40 + q * 8) = vh;
        *(uint4*)(sXl + r * 40 + q * 8) = vl;
    }
    __syncthreads();

    const u32 sbXh = smem_u32(sXh), sbXl = smem_u32(sXl);
    const u32 sbWh = smem_u32(sWh), sbWl = smem_u32(sWl);
    const int lrow = lane & 15;
    const int lhalf = (lane >> 4) * 8;
    const u32 boff  = sbWh + ((lane & 15) * 488 + lhalf) * 2;
    const u32 boffl = sbWl + ((lane & 15) * 488 + lhalf) * 2;
    const int grp = lane >> 2, qc = (lane & 3) * 2;

    float acc[2][2][4];
#pragma unroll
    for (int mi = 0; mi < 2; mi++)
#pragma unroll
        for (int ni = 0; ni < 2; ni++)
#pragma unroll
            for (int q = 0; q < 4; q++) acc[mi][ni][q] = 0.0f;

#pragma unroll 2
    for (int ks = 0; ks < 30; ks++) {
        const int k   = ks >> 1;
        const int icb = (ks & 1) * 16;
        u32 ah[2][4], al[2][4];
#pragma unroll
        for (int mi = 0; mi < 2; mi++) {
            u32 aadd = (u32)((wm * 32 + mi * 16 + lrow + k) * 40 + icb + lhalf) * 2;
            ldsm_x4(ah[mi][0], ah[mi][1], ah[mi][2], ah[mi][3], sbXh + aadd);
            ldsm_x4(al[mi][0], al[mi][1], al[mi][2], al[mi][3], sbXl + aadd);
        }
        u32 t0r, t1r, t2r, t3r;
        u32 bh[2][2], bl[2][2];
        ldsm_x4(t0r, t1r, t2r, t3r, boff + ks * 32);
        bh[0][0] = t0r; bh[0][1] = t2r; bh[1][0] = t1r; bh[1][1] = t3r;
        ldsm_x4(t0r, t1r, t2r, t3r, boffl + ks * 32);
        bl[0][0] = t0r; bl[0][1] = t2r; bl[1][0] = t1r; bl[1][1] = t3r;

#pragma unroll
        for (int s = 0; s < 3; s++)
#pragma unroll
            for (int mi = 0; mi < 2; mi++)
#pragma unroll
                for (int ni = 0; ni < 2; ni++) {
                    const u32* aa = (s == 2) ? al[mi] : ah[mi];
                    const u32* bb = (s == 1) ? bl[ni] : bh[ni];
                    mma_bf16(acc[mi][ni], aa, bb);
                }
    }
    __syncthreads();

    u32* stgh = (u32*)sXh;
    u32* stgl = (u32*)sXl;
#pragma unroll
    for (int mi = 0; mi < 2; mi++)
#pragma unroll
        for (int ni = 0; ni < 2; ni++) {
            int ch = ni * 8 + qc;
            float bv0 = __ldg(&bias[ch]), bv1 = __ldg(&bias[ch + 1]);
            int p0 = wm * 32 + mi * 16 + grp, p1 = p0 + 8;
            float v00 = gelu_erf(acc[mi][ni][0] + bv0), v01 = gelu_erf(acc[mi][ni][1] + bv1);
            float v10 = gelu_erf(acc[mi][ni][2] + bv0), v11 = gelu_erf(acc[mi][ni][3] + bv1);
            bf16 h0, h1, l0, l1;
            split_bf16(v00, h0, l0); split_bf16(v01, h1, l1);
            __nv_bfloat162 th = __halves2bfloat162(h0, h1), tl = __halves2bfloat162(l0, l1);
            stgh[p0 * 9 + ni * 4 + (lane & 3)] = *(u32*)&th;
            stgl[p0 * 9 + ni * 4 + (lane & 3)] = *(u32*)&tl;
            split_bf16(v10, h0, l0); split_bf16(v11, h1, l1);
            th = __halves2bfloat162(h0, h1); tl = __halves2bfloat162(l0, l1);
            stgh[p1 * 9 + ni * 4 + (lane & 3)] = *(u32*)&th;
            stgl[p1 * 9 + ni * 4 + (lane & 3)] = *(u32*)&tl;
        }
    __syncthreads();
    for (int i = tid; i < 256 * 8; i += 256) {
        int p = i >> 3, q = i & 7;
        int l = t0 + p;
        if (l < L_) {
            size_t o = ((size_t)b * L_ + l) * 8 + q;
            ((u32*)r2h)[o] = stgh[p * 9 + q];
            ((u32*)r2l)[o] = stgl[p * 9 + q];
        }
    }
}

// ================= conv3 (R11): 256-pos tile + residual + pointwise =================
#define C3ROWS 271
#define C3SM (2 * (C3ROWS * 40 * 2) + 2 * (8 * 248 * 2) + 256 * 9 * 4)
__global__ void __launch_bounds__(256) conv3_hmma(
    const bf16* __restrict__ r2h, const bf16* __restrict__ r2l,
    const bf16* __restrict__ wh, const bf16* __restrict__ wl,
    const float* __restrict__ bias,
    const bf16* __restrict__ rech, const bf16* __restrict__ recl,
    const float* __restrict__ pw, const float* __restrict__ pb,
    float* __restrict__ out)
{
    extern __shared__ __align__(16) char dsm3[];
    bf16* sXh = (bf16*)dsm3;
    bf16* sXl = sXh + C3ROWS * 40;
    bf16* sWh = sXl + C3ROWS * 40;
    bf16* sWl = sWh + 8 * 248;
    float* sF = (float*)(sWl + 8 * 248);

    const int tid  = threadIdx.x;
    const int lane = tid & 31;
    const int wm   = tid >> 5;
    const int b    = blockIdx.y;
    const int t0   = blockIdx.x * 256;

    for (int i = tid; i < 8 * 120; i += 256) {
        int r = i / 120, c = i - r * 120;
        ((u32*)sWh)[r * 124 + c] = ((const u32*)wh)[r * 120 + c];
        ((u32*)sWl)[r * 124 + c] = ((const u32*)wl)[r * 120 + c];
    }
    for (int i = tid; i < C3ROWS * 2; i += 256) {
        int r = i >> 1, q = i & 1;
        int gp = t0 + r - 7;
        uint4 vh = make_uint4(0,0,0,0), vl = vh;
        if (gp >= 0 && gp < L_) {
            size_t o = ((size_t)b * L_ + gp) * 16 + q * 8;
            vh = *(const uint4*)(r2h + o);
            vl = *(const uint4*)(r2l + o);
        }
        *(uint4*)(sXh + r * 40 + q * 8) = vh;
        *(uint4*)(sXl + r * 40 + q * 8) = vl;
    }
    __syncthreads();

    const u32 sbXh = smem_u32(sXh), sbXl = smem_u32(sXl);
    const u32 sbWh = smem_u32(sWh), sbWl = smem_u32(sWl);
    const int lrow = lane & 15;
    const int lhalf = (lane >> 4) * 8;
    const u32 bbase = ((lane & 7) * 248 + ((lane >> 3) & 1) * 8) * 2;
    const int grp = lane >> 2, qc = (lane & 3) * 2;

    float acc[2][4];
#pragma unroll
    for (int mi = 0; mi < 2; mi++)
#pragma unroll
        for (int q = 0; q < 4; q++) acc[mi][q] = 0.0f;

#pragma unroll
    for (int k = 0; k < 15; k++) {
        u32 ah[2][4], al[2][4];
#pragma unroll
        for (int mi = 0; mi < 2; mi++) {
            u32 aadd = (u32)((wm * 32 + mi * 16 + lrow + k) * 40 + lhalf) * 2;
            ldsm_x4(ah[mi][0], ah[mi][1], ah[mi][2], ah[mi][3], sbXh + aadd);
            ldsm_x4(al[mi][0], al[mi][1], al[mi][2], al[mi][3], sbXl + aadd);
        }
        u32 bh[2], bl[2];
        ldsm_x2(bh[0], bh[1], sbWh + bbase + k * 32);
        ldsm_x2(bl[0], bl[1], sbWl + bbase + k * 32);
#pragma unroll
        for (int mi = 0; mi < 2; mi++) mma_bf16(acc[mi], ah[mi], bh);
#pragma unroll
        for (int mi = 0; mi < 2; mi++) mma_bf16(acc[mi], ah[mi], bl);
#pragma unroll
        for (int mi = 0; mi < 2; mi++) mma_bf16(acc[mi], al[mi], bh);
    }
    __syncthreads();

    {
        float bv0 = __ldg(&bias[qc]), bv1 = __ldg(&bias[qc + 1]);
#pragma unroll
        for (int mi = 0; mi < 2; mi++) {
            int p0 = wm * 32 + mi * 16 + grp, p1 = p0 + 8;
            sF[p0 * 9 + qc]     = acc[mi][0] + bv0;
            sF[p0 * 9 + qc + 1] = acc[mi][1] + bv1;
            sF[p1 * 9 + qc]     = acc[mi][2] + bv0;
            sF[p1 * 9 + qc + 1] = acc[mi][3] + bv1;
        }
    }
    __syncthreads();

    {
        int l = t0 + tid;
        if (l < L_) {
            size_t ro = ((size_t)b * L_ + l) * 8;
            uint4 vh = *(const uint4*)(rech + ro);
            uint4 vl = *(const uint4*)(recl + ro);
            const unsigned short* hs = (const unsigned short*)&vh;
            const unsigned short* ls = (const unsigned short*)&vl;
            float resid[8];
#pragma unroll
            for (int c = 0; c < 8; c++) {
                float rv = __bfloat162float(__ushort_as_bfloat16(hs[c]))
                         + __bfloat162float(__ushort_as_bfloat16(ls[c]));
                resid[c] = rv + sF[tid * 9 + c];
            }
#pragma unroll
            for (int o = 0; o < 8; o++) {
                float v = __ldg(&pb[o]);
#pragma unroll
                for (int c = 0; c < 8; c++)
                    v += __ldg(&pw[o * C_ + c]) * resid[c];
                out[((size_t)b * C_ + o) * L_ + l] = v;
            }
        }
    }
}

// ---------------- launcher ----------------
extern "C" void kernel_launch(void* const* d_in, const int* in_sizes, int n_in,
                              void* d_out, int out_size)
{
    const float* X   = (const float*)d_in[0];
    const float* W1  = (const float*)d_in[1];
    const float* b1  = (const float*)d_in[2];
    const float* W2  = (const float*)d_in[3];
    const float* b2  = (const float*)d_in[4];
    const float* rw1 = (const float*)d_in[5];
    const float* rb1 = (const float*)d_in[6];
    const float* rw2 = (const float*)d_in[7];
    const float* rb2 = (const float*)d_in[8];
    const float* rw3 = (const float*)d_in[9];
    const float* rb3 = (const float*)d_in[10];
    const float* pw  = (const float*)d_in[11];
    const float* pb  = (const float*)d_in[12];
    float* out = (float*)d_out;

    bf16 *pXh, *pXl, *pHh, *pHl, *pW1th, *pW1tl, *pW2th, *pW2tl;
    bf16 *pRech, *pRecl, *pR1h, *pR1l, *pR2h, *pR2l;
    bf16 *pCw1h, *pCw1l, *pW2h, *pW2l, *pCw3h, *pCw3l;
    float *pPatches;
    cudaGetSymbolAddress((void**)&pXh,   g_Xh);
    cudaGetSymbolAddress((void**)&pXl,   g_Xl);
    cudaGetSymbolAddress((void**)&pHh,   g_Hh);
    cudaGetSymbolAddress((void**)&pHl,   g_Hl);
    cudaGetSymbolAddress((void**)&pW1th, g_W1th);
    cudaGetSymbolAddress((void**)&pW1tl, g_W1tl);
    cudaGetSymbolAddress((void**)&pW2th, g_W2th);
    cudaGetSymbolAddress((void**)&pW2tl, g_W2tl);
    cudaGetSymbolAddress((void**)&pPatches, g_patches);
    cudaGetSymbolAddress((void**)&pRech, g_rech);
    cudaGetSymbolAddress((void**)&pRecl, g_recl);
    cudaGetSymbolAddress((void**)&pR1h,  g_r1h);
    cudaGetSymbolAddress((void**)&pR1l,  g_r1l);
    cudaGetSymbolAddress((void**)&pR2h,  g_r2h);
    cudaGetSymbolAddress((void**)&pR2l,  g_r2l);
    cudaGetSymbolAddress((void**)&pCw1h, g_cw1h);
    cudaGetSymbolAddress((void**)&pCw1l, g_cw1l);
    cudaGetSymbolAddress((void**)&pW2h,  g_w2h);
    cudaGetSymbolAddress((void**)&pW2l,  g_w2l);
    cudaGetSymbolAddress((void**)&pCw3h, g_cw3h);
    cudaGetSymbolAddress((void**)&pCw3l, g_cw3l);

    cudaFuncSetAttribute(gemm_hmma<true>,
                         cudaFuncAttributeMaxDynamicSharedMemorySize, GEMM_SMEM);
    cudaFuncSetAttribute(gemm_hmma<false>,
                         cudaFuncAttributeMaxDynamicSharedMemorySize, GEMM_SMEM);
    cudaFuncSetAttribute(conv1_hmma, cudaFuncAttributeMaxDynamicSharedMemorySize, C1SM);
    cudaFuncSetAttribute(conv2_hmma, cudaFuncAttributeMaxDynamicSharedMemorySize, C2SM);
    cudaFuncSetAttribute(conv3_hmma, cudaFuncAttributeMaxDynamicSharedMemorySize, C3SM);

    const int convGrid = (L_ + 255) / 256;   // 8

    // 1: split X fp32 -> bf16 hi/lo
    {
        int n4 = (int)((size_t)M_ * 512 / 4);
        split_f32_kernel<<<(n4 + 255) / 256, 256>>>(X, pXh, pXl, n4);
    }
    // 2-3: weight transposes
    transp_split_kernel<<<(512*512 + 255) / 256, 256>>>(W1, pW1th, pW1tl, 512, 512, 512);
    transp_split_kernel<<<(256*512 + 255) / 256, 256>>>(W2, pW2th, pW2tl, 512, 200, 256);

    // 4: GEMM1 (ncu capture slot) -- Hh/Hl = split(GELU(X @ W1 + b1))
    gemm_hmma<true><<<dim3(8, M_ / 256), 256, GEMM_SMEM>>>(
        pXh, pXl, pW1th, pW1tl, b1, 512, pHh, pHl, nullptr);

    // 5: GEMM2 -- patches = H @ W2 + b2
    gemm_hmma<false><<<dim3(4, M_ / 256), 256, GEMM_SMEM>>>(
        pHh, pHl, pW2th, pW2tl, b2, 200, nullptr, nullptr, pPatches);

    // 6: overlap-add
    overlap_add_v3<<<dim3((L_ + 255) / 256, B_), 256>>>(pPatches, pRech, pRecl);

    // 7-12: conv weight preps + convs
    w1c_prep_kernel<<<(32*128 + 255) / 256, 256>>>(rw1, pCw1h, pCw1l);
    conv1_hmma<<<dim3(convGrid, B_), 256, C1SM>>>(pRech, pRecl, pCw1h, pCw1l, rb1,
                                                  pR1h, pR1l);
    w2_prep_kernel<<<(16*480 + 255) / 256, 256>>>(rw2, pW2h, pW2l);
    conv2_hmma<<<dim3(convGrid, B_), 256, C2SM>>>(pR1h, pR1l, pW2h, pW2l, rb2,
                                                  pR2h, pR2l);
    w3c_prep_kernel<<<(8*240 + 255) / 256, 256>>>(rw3, pCw3h, pCw3l);
    conv3_hmma<<<dim3(convGrid, B_), 256, C3SM>>>(pR2h, pR2l, pCw3h, pCw3l, rb3,
                                                  pRech, pRecl, pw, pb, out);
}

// round 13
// speedup vs baseline: 1.2775x; 1.2775x over previous
#include <cuda_runtime.h>
#include <cuda_bf16.h>
#include <math.h>
#include <stdint.h>

#define B_      1024
#define P_      11
#define C_      8
#define H_      512
#define T_      200
#define L_      2000
#define STRIDE_ 180
#define M_      (B_*P_*C_)

typedef unsigned long long u64;
typedef unsigned int u32;
typedef __nv_bfloat16 bf16;

// ---------------- scratch (device globals) ----------------
__device__ bf16 g_Hh[(size_t)M_ * 512];
__device__ bf16 g_Hl[(size_t)M_ * 512];
__device__ bf16 g_W1th[512 * 512];
__device__ bf16 g_W1tl[512 * 512];
__device__ bf16 g_W2th[256 * 512];
__device__ bf16 g_W2tl[256 * 512];
__device__ float g_patches[(size_t)M_ * T_];
__device__ bf16 g_rech[(size_t)B_ * L_ * 8];
__device__ bf16 g_recl[(size_t)B_ * L_ * 8];
__device__ bf16 g_r1h[(size_t)B_ * L_ * 32];   // conv1 out, single bf16
__device__ bf16 g_r2h[(size_t)B_ * L_ * 16];   // conv2 out, single bf16
__device__ bf16 g_cw1h[32 * 128];
__device__ bf16 g_w2h[16 * 480];
__device__ bf16 g_cw3h[8 * 240];

__device__ __forceinline__ float gelu_erf(float x) {
    return 0.5f * x * (1.0f + erff(x * 0.7071067811865476f));
}

// ---------------- warp MMA primitives ----------------
__device__ __forceinline__ uint32_t smem_u32(const void* p) {
    uint32_t a;
    asm("{ .reg .u64 t; cvta.to.shared.u64 t, %1; cvt.u32.u64 %0, t; }" : "=r"(a) : "l"(p));
    return a;
}
__device__ __forceinline__ void ldsm_x4(u32& r0, u32& r1, u32& r2, u32& r3, u32 addr) {
    asm volatile("ldmatrix.sync.aligned.m8n8.x4.shared.b16 {%0,%1,%2,%3}, [%4];"
        : "=r"(r0), "=r"(r1), "=r"(r2), "=r"(r3) : "r"(addr));
}
__device__ __forceinline__ void ldsm_x2(u32& r0, u32& r1, u32 addr) {
    asm volatile("ldmatrix.sync.aligned.m8n8.x2.shared.b16 {%0,%1}, [%2];"
        : "=r"(r0), "=r"(r1) : "r"(addr));
}
__device__ __forceinline__ void mma_bf16(float* d, const u32* a, const u32* b) {
    asm volatile("mma.sync.aligned.m16n8k16.row.col.f32.bf16.bf16.f32 "
        "{%0,%1,%2,%3}, {%4,%5,%6,%7}, {%8,%9}, {%0,%1,%2,%3};"
        : "+f"(d[0]), "+f"(d[1]), "+f"(d[2]), "+f"(d[3])
        : "r"(a[0]), "r"(a[1]), "r"(a[2]), "r"(a[3]), "r"(b[0]), "r"(b[1]));
}
__device__ __forceinline__ void split_bf16(float v, bf16& h, bf16& l) {
    h = __float2bfloat16(v);
    l = __float2bfloat16(v - __bfloat162float(h));
}

// ================= prep kernels (weights only) =================
__global__ void transp_split_kernel(const float* __restrict__ W,
                                    bf16* __restrict__ th, bf16* __restrict__ tl,
                                    int Kdim, int Nsrc, int Npad)
{
    int idx = blockIdx.x * 256 + threadIdx.x;
    if (idx >= Npad * Kdim) return;
    int n = idx / Kdim, k = idx - n * Kdim;
    float f = (n < Nsrc) ? W[(size_t)k * Nsrc + n] : 0.0f;
    split_bf16(f, th[idx], tl[idx]);
}

__global__ void w1c_prep_kernel(const float* __restrict__ w, bf16* __restrict__ wh)
{
    int idx = blockIdx.x * 256 + threadIdx.x;
    if (idx >= 32 * 128) return;
    int co = idx >> 7, c = idx & 127;
    int ks = c >> 4, rem = c & 15;
    int tap = 2 * ks + (rem >> 3);
    int ic = rem & 7;
    float f = (tap < 15) ? w[((size_t)co * 8 + ic) * 15 + tap] : 0.0f;
    wh[idx] = __float2bfloat16(f);
}

__global__ void w2_prep_kernel(const float* __restrict__ w, bf16* __restrict__ wh)
{
    int idx = blockIdx.x * 256 + threadIdx.x;
    if (idx >= 16 * 480) return;
    int co = idx / 480, c = idx - co * 480;
    int k = c >> 5, ic = c & 31;
    wh[idx] = __float2bfloat16(w[((size_t)co * 32 + ic) * 15 + k]);
}

__global__ void w3c_prep_kernel(const float* __restrict__ w, bf16* __restrict__ wh)
{
    int idx = blockIdx.x * 256 + threadIdx.x;
    if (idx >= 8 * 240) return;
    int co = idx / 240, c = idx - co * 240;
    int k = c >> 4, ic = c & 15;
    wh[idx] = __float2bfloat16(w[((size_t)co * 16 + ic) * 15 + k]);
}

// ================= HMMA GEMM (R11 config: 128x64 block, dbuf, fused fp32 split) =================
#define ASTR 40
#define A_ELE (128 * ASTR)
#define B_ELE (64 * ASTR)
#define GEMM_SMEM ((2 * A_ELE * 2 + 2 * B_ELE * 2) * 2)

template<bool A_FP32, bool GELU_SPLIT>
__global__ void __launch_bounds__(256, 2) gemm_hmma(
    const float* __restrict__ Af,
    const bf16* __restrict__ Ah, const bf16* __restrict__ Al,
    const bf16* __restrict__ Bh, const bf16* __restrict__ Bl,
    const float* __restrict__ bias, int Nvalid,
    bf16* __restrict__ outHh, bf16* __restrict__ outHl, float* __restrict__ outF)
{
    extern __shared__ __align__(16) char dynsm[];
    bf16* sAh = (bf16*)dynsm;
    bf16* sAl = sAh + 2 * A_ELE;
    bf16* sBh = sAl + 2 * A_ELE;
    bf16* sBl = sBh + 2 * B_ELE;

    const int tid  = threadIdx.x;
    const int lane = tid & 31;
    const int wid  = tid >> 5;
    const int wm   = wid & 3;
    const int wn   = wid >> 2;
    const int bm   = blockIdx.y * 128;
    const int bn   = blockIdx.x * 64;

    float acc[2][4][4];
#pragma unroll
    for (int i = 0; i < 2; i++)
#pragma unroll
        for (int j = 0; j < 4; j++)
#pragma unroll
            for (int q = 0; q < 4; q++) acc[i][j][q] = 0.0f;

    const int ar = tid >> 2;
    const int aq = (tid & 3) * 8;
    const size_t gA0 = (size_t)(bm + ar) * 512 + aq;
    const size_t gA1 = (size_t)(bm + ar + 64) * 512 + aq;
    const size_t gB0 = (size_t)(bn + ar) * 512 + aq;

    const u32 sbAh = smem_u32(sAh), sbAl = smem_u32(sAl);
    const u32 sbBh = smem_u32(sBh), sbBl = smem_u32(sBl);

    const int lrow = lane & 15;
    const int lhalf = (lane >> 4) * 8;
    const u32 aoffA0 = ((wm * 32 +      lrow) * ASTR + lhalf) * 2;
    const u32 aoffA1 = ((wm * 32 + 16 + lrow) * ASTR + lhalf) * 2;
    const u32 aoffB0 = ((wn * 32 +      lrow) * ASTR + lhalf) * 2;
    const u32 aoffB1 = ((wn * 32 + 16 + lrow) * ASTR + lhalf) * 2;

    uint4 pah0, pah1, pal0, pal1;
    float4 fa0, fa1, fb0, fb1;
    uint4 pbh, pbl;

    if (A_FP32) {
        fa0 = *(const float4*)(Af + gA0); fa1 = *(const float4*)(Af + gA0 + 4);
        fb0 = *(const float4*)(Af + gA1); fb1 = *(const float4*)(Af + gA1 + 4);
    } else {
        pah0 = *(const uint4*)(Ah + gA0); pah1 = *(const uint4*)(Ah + gA1);
        pal0 = *(const uint4*)(Al + gA0); pal1 = *(const uint4*)(Al + gA1);
    }
    pbh = *(const uint4*)(Bh + gB0); pbl = *(const uint4*)(Bl + gB0);

    const int sA0 = ar * ASTR + aq, sA1 = (ar + 64) * ASTR + aq, sB0 = ar * ASTR + aq;

    for (int kt = 0; kt < 16; kt++) {
        const int cur = kt & 1;
        const int aBuf = cur * A_ELE, bBuf = cur * B_ELE;

        if (A_FP32) {
            float f0[8] = {fa0.x, fa0.y, fa0.z, fa0.w, fa1.x, fa1.y, fa1.z, fa1.w};
            float f1[8] = {fb0.x, fb0.y, fb0.z, fb0.w, fb1.x, fb1.y, fb1.z, fb1.w};
            unsigned short h0[8], l0[8], h1[8], l1[8];
#pragma unroll
            for (int j = 0; j < 8; j++) {
                bf16 h, l;
                split_bf16(f0[j], h, l);
                h0[j] = __bfloat16_as_ushort(h); l0[j] = __bfloat16_as_ushort(l);
                split_bf16(f1[j], h, l);
                h1[j] = __bfloat16_as_ushort(h); l1[j] = __bfloat16_as_ushort(l);
            }
            *(uint4*)(sAh + aBuf + sA0) = *(uint4*)h0; *(uint4*)(sAl + aBuf + sA0) = *(uint4*)l0;
            *(uint4*)(sAh + aBuf + sA1) = *(uint4*)h1; *(uint4*)(sAl + aBuf + sA1) = *(uint4*)l1;
        } else {
            *(uint4*)(sAh + aBuf + sA0) = pah0; *(uint4*)(sAh + aBuf + sA1) = pah1;
            *(uint4*)(sAl + aBuf + sA0) = pal0; *(uint4*)(sAl + aBuf + sA1) = pal1;
        }
        *(uint4*)(sBh + bBuf + sB0) = pbh; *(uint4*)(sBl + bBuf + sB0) = pbl;
        __syncthreads();

        if (kt < 15) {
            int k0 = (kt + 1) * 32;
            if (A_FP32) {
                fa0 = *(const float4*)(Af + gA0 + k0); fa1 = *(const float4*)(Af + gA0 + k0 + 4);
                fb0 = *(const float4*)(Af + gA1 + k0); fb1 = *(const float4*)(Af + gA1 + k0 + 4);
            } else {
                pah0 = *(const uint4*)(Ah + gA0 + k0); pah1 = *(const uint4*)(Ah + gA1 + k0);
                pal0 = *(const uint4*)(Al + gA0 + k0); pal1 = *(const uint4*)(Al + gA1 + k0);
            }
            pbh = *(const uint4*)(Bh + gB0 + k0); pbl = *(const uint4*)(Bl + gB0 + k0);
        }

        const u32 aByte = (u32)(aBuf * 2), bByte = (u32)(bBuf * 2);
#pragma unroll
        for (int kk = 0; kk < 2; kk++) {
            const u32 kadd = kk * 32;
            u32 a_h[2][4], a_l[2][4];
            ldsm_x4(a_h[0][0], a_h[0][1], a_h[0][2], a_h[0][3], sbAh + aByte + aoffA0 + kadd);
            ldsm_x4(a_h[1][0], a_h[1][1], a_h[1][2], a_h[1][3], sbAh + aByte + aoffA1 + kadd);
            ldsm_x4(a_l[0][0], a_l[0][1], a_l[0][2], a_l[0][3], sbAl + aByte + aoffA0 + kadd);
            ldsm_x4(a_l[1][0], a_l[1][1], a_l[1][2], a_l[1][3], sbAl + aByte + aoffA1 + kadd);

            u32 t0, t1, t2, t3;
            u32 b_h[4][2], b_l[4][2];
            ldsm_x4(t0, t1, t2, t3, sbBh + bByte + aoffB0 + kadd);
            b_h[0][0] = t0; b_h[0][1] = t2; b_h[1][0] = t1; b_h[1][1] = t3;
            ldsm_x4(t0, t1, t2, t3, sbBh + bByte + aoffB1 + kadd);
            b_h[2][0] = t0; b_h[2][1] = t2; b_h[3][0] = t1; b_h[3][1] = t3;
            ldsm_x4(t0, t1, t2, t3, sbBl + bByte + aoffB0 + kadd);
            b_l[0][0] = t0; b_l[0][1] = t2; b_l[1][0] = t1; b_l[1][1] = t3;
            ldsm_x4(t0, t1, t2, t3, sbBl + bByte + aoffB1 + kadd);
            b_l[2][0] = t0; b_l[2][1] = t2; b_l[3][0] = t1; b_l[3][1] = t3;

#pragma unroll
            for (int s = 0; s < 3; s++) {
#pragma unroll
                for (int mi = 0; mi < 2; mi++)
#pragma unroll
                    for (int ni = 0; ni < 4; ni++) {
                        const u32* aa = (s == 2) ? a_l[mi] : a_h[mi];
                        const u32* bb = (s == 1) ? b_l[ni] : b_h[ni];
                        mma_bf16(acc[mi][ni], aa, bb);
                    }
            }
        }
    }

    const int grp = lane >> 2;
    const int qc  = (lane & 3) * 2;
#pragma unroll
    for (int mi = 0; mi < 2; mi++) {
        const int r0 = bm + wm * 32 + mi * 16 + grp;
        const int r1 = r0 + 8;
#pragma unroll
        for (int ni = 0; ni < 4; ni++) {
            const int col = bn + wn * 32 + ni * 8 + qc;
            float bv0 = __ldg(&bias[col]), bv1 = __ldg(&bias[col + 1]);
            float v00 = acc[mi][ni][0] + bv0, v01 = acc[mi][ni][1] + bv1;
            float v10 = acc[mi][ni][2] + bv0, v11 = acc[mi][ni][3] + bv1;
            if (GELU_SPLIT) {
                v00 = gelu_erf(v00); v01 = gelu_erf(v01);
                v10 = gelu_erf(v10); v11 = gelu_erf(v11);
                bf16 h0, h1, l0, l1;
                split_bf16(v00, h0, l0); split_bf16(v01, h1, l1);
                size_t i0 = (size_t)r0 * 256 + (col >> 1);
                reinterpret_cast<__nv_bfloat162*>(outHh)[i0] = __halves2bfloat162(h0, h1);
                reinterpret_cast<__nv_bfloat162*>(outHl)[i0] = __halves2bfloat162(l0, l1);
                split_bf16(v10, h0, l0); split_bf16(v11, h1, l1);
                size_t i1 = (size_t)r1 * 256 + (col >> 1);
                reinterpret_cast<__nv_bfloat162*>(outHh)[i1] = __halves2bfloat162(h0, h1);
                reinterpret_cast<__nv_bfloat162*>(outHl)[i1] = __halves2bfloat162(l0, l1);
            } else {
                if (col < Nvalid) {
                    *(float2*)(outF + (size_t)r0 * Nvalid + col) = make_float2(v00, v01);
                    *(float2*)(outF + (size_t)r1 * Nvalid + col) = make_float2(v10, v11);
                }
            }
        }
    }
}

// ================= overlap-add -> rec bf16 split [b][l][8] =================
__global__ void overlap_add_v3(const float* __restrict__ patches,
                               bf16* __restrict__ rech, bf16* __restrict__ recl)
{
    const int b  = blockIdx.y;
    const int l  = blockIdx.x * 256 + threadIdx.x;
    if (l >= L_) return;

    int i_lo = l - (T_ - 1);
    i_lo = (i_lo > 0) ? (i_lo + STRIDE_ - 1) / STRIDE_ : 0;
    int i_hi = l / STRIDE_;
    if (i_hi > P_ - 1) i_hi = P_ - 1;

    int np = 0, pi[2], pt[2];
    float wv[2], ws = 0.0f;
    for (int i = i_lo; i <= i_hi; i++) {
        int t = l - i * STRIDE_;
        float w;
        if (t < 50)        w = (float)t * (1.0f / 49.0f);
        else if (t >= 150) w = (float)(199 - t) * (1.0f / 49.0f);
        else               w = 1.0f;
        pi[np] = i; pt[np] = t; wv[np] = w; ws += w; np++;
    }
    float ews = fmaxf(ws, 1e-8f);

    unsigned short hh[8], ll[8];
#pragma unroll
    for (int c = 0; c < 8; c++) {
        float v = 0.0f;
        for (int j = 0; j < np; j++)
            v += patches[(((size_t)b * P_ + pi[j]) * C_ + c) * T_ + pt[j]] * wv[j];
        v = v / ews;
        bf16 h, lo; split_bf16(v, h, lo);
        hh[c] = __bfloat16_as_ushort(h);
        ll[c] = __bfloat16_as_ushort(lo);
    }
    size_t o = ((size_t)b * L_ + l) * 8;
    *(uint4*)(rech + o) = *(uint4*)hh;
    *(uint4*)(recl + o) = *(uint4*)ll;
}

// ================= conv1: 8->32 k15, single-bf16 HMMA =================
#define C1ROWS 271
#define C1SM (C1ROWS * 40 * 2 + 32 * 136 * 2)
__global__ void __launch_bounds__(256) conv1_hmma(
    const bf16* __restrict__ rech,
    const bf16* __restrict__ wh,
    const float* __restrict__ bias,
    bf16* __restrict__ r1h)
{
    extern __shared__ __align__(16) char dsm1[];
    bf16* sXh = (bf16*)dsm1;
    bf16* sWh = sXh + C1ROWS * 40;

    const int tid  = threadIdx.x;
    const int lane = tid & 31;
    const int wm   = tid >> 5;
    const int b    = blockIdx.y;
    const int t0   = blockIdx.x * 256;

    for (int i = tid; i < 32 * 64; i += 256) {
        int r = i >> 6, q = i & 63;
        ((u32*)sWh)[r * 68 + q] = ((const u32*)wh)[r * 64 + q];
    }
    for (int i = tid; i < C1ROWS * 2; i += 256) {
        int r = i >> 1, half = i & 1;
        int gp = t0 + r - 7 + half;
        uint4 vh = make_uint4(0,0,0,0);
        if (gp >= 0 && gp < L_) {
            size_t o = ((size_t)b * L_ + gp) * 8;
            vh = *(const uint4*)(rech + o);
        }
        *(uint4*)(sXh + r * 40 + half * 8) = vh;
    }
    __syncthreads();

    const u32 sbXh = smem_u32(sXh);
    const u32 sbWh = smem_u32(sWh);
    const int lrow = lane & 15;
    const int lhalf = (lane >> 4) * 8;
    const int grp = lane >> 2, qc = (lane & 3) * 2;

    float acc[2][4][4];
#pragma unroll
    for (int mi = 0; mi < 2; mi++)
#pragma unroll
        for (int ni = 0; ni < 4; ni++)
#pragma unroll
            for (int q = 0; q < 4; q++) acc[mi][ni][q] = 0.0f;

#pragma unroll
    for (int k = 0; k < 8; k++) {
        u32 ah[2][4];
#pragma unroll
        for (int mi = 0; mi < 2; mi++) {
            u32 aadd = (u32)((wm * 32 + mi * 16 + lrow + 2 * k) * 40 + lhalf) * 2;
            ldsm_x4(ah[mi][0], ah[mi][1], ah[mi][2], ah[mi][3], sbXh + aadd);
        }
        u32 t0r, t1r, t2r, t3r;
        u32 bh[4][2];
#pragma unroll
        for (int na2 = 0; na2 < 2; na2++) {
            u32 badd = (u32)((na2 * 16 + lrow) * 136 + k * 16 + lhalf) * 2;
            ldsm_x4(t0r, t1r, t2r, t3r, sbWh + badd);
            bh[na2*2][0] = t0r; bh[na2*2][1] = t2r;
            bh[na2*2+1][0] = t1r; bh[na2*2+1][1] = t3r;
        }
#pragma unroll
        for (int mi = 0; mi < 2; mi++)
#pragma unroll
            for (int ni = 0; ni < 4; ni++)
                mma_bf16(acc[mi][ni], ah[mi], bh[ni]);
    }
    __syncthreads();

    u32* stgh = (u32*)sXh;   // 256*17 u32 = 17408B
#pragma unroll
    for (int mi = 0; mi < 2; mi++)
#pragma unroll
        for (int ni = 0; ni < 4; ni++) {
            int ch = ni * 8 + qc;
            float bv0 = __ldg(&bias[ch]), bv1 = __ldg(&bias[ch + 1]);
            int p0 = wm * 32 + mi * 16 + grp, p1 = p0 + 8;
            float v00 = gelu_erf(acc[mi][ni][0] + bv0), v01 = gelu_erf(acc[mi][ni][1] + bv1);
            float v10 = gelu_erf(acc[mi][ni][2] + bv0), v11 = gelu_erf(acc[mi][ni][3] + bv1);
            __nv_bfloat162 th = __halves2bfloat162(__float2bfloat16(v00), __float2bfloat16(v01));
            stgh[p0 * 17 + ni * 4 + (lane & 3)] = *(u32*)&th;
            th = __halves2bfloat162(__float2bfloat16(v10), __float2bfloat16(v11));
            stgh[p1 * 17 + ni * 4 + (lane & 3)] = *(u32*)&th;
        }
    __syncthreads();
    for (int i = tid; i < 256 * 16; i += 256) {
        int p = i >> 4, q = i & 15;
        int l = t0 + p;
        if (l < L_)
            ((u32*)r1h)[((size_t)b * L_ + l) * 16 + q] = stgh[p * 17 + q];
    }
}

// ================= conv2: 32->16 k15, single-bf16 HMMA =================
#define C2ROWS 272
#define C2SM (C2ROWS * 40 * 2 + 16 * 488 * 2)
__global__ void __launch_bounds__(256) conv2_hmma(
    const bf16* __restrict__ r1h,
    const bf16* __restrict__ wh,
    const float* __restrict__ bias,
    bf16* __restrict__ r2h)
{
    extern __shared__ __align__(16) char dsm2[];
    bf16* sXh = (bf16*)dsm2;
    bf16* sWh = sXh + C2ROWS * 40;

    const int tid  = threadIdx.x;
    const int lane = tid & 31;
    const int wm   = tid >> 5;
    const int b    = blockIdx.y;
    const int t0   = blockIdx.x * 256;

    for (int i = tid; i < 16 * 240; i += 256) {
        int r = i / 240, c = i - r * 240;
        ((u32*)sWh)[r * 244 + c] = ((const u32*)wh)[r * 240 + c];
    }
    for (int i = tid; i < C2ROWS * 4; i += 256) {
        int r = i >> 2, q = i & 3;
        int gp = t0 + r - 7;
        uint4 vh = make_uint4(0,0,0,0);
        if (gp >= 0 && gp < L_) {
            size_t o = ((size_t)b * L_ + gp) * 32 + q * 8;
            vh = *(const uint4*)(r1h + o);
        }
        *(uint4*)(sXh + r * 40 + q * 8) = vh;
    }
    __syncthreads();

    const u32 sbXh = smem_u32(sXh);
    const u32 sbWh = smem_u32(sWh);
    const int lrow = lane & 15;
    const int lhalf = (lane >> 4) * 8;
    const u32 boff = sbWh + ((lane & 15) * 488 + lhalf) * 2;
    const int grp = lane >> 2, qc = (lane & 3) * 2;

    float acc[2][2][4];
#pragma unroll
    for (int mi = 0; mi < 2; mi++)
#pragma unroll
        for (int ni = 0; ni < 2; ni++)
#pragma unroll
            for (int q = 0; q < 4; q++) acc[mi][ni][q] = 0.0f;

#pragma unroll 2
    for (int ks = 0; ks < 30; ks++) {
        const int k   = ks >> 1;
        const int icb = (ks & 1) * 16;
        u32 ah[2][4];
#pragma unroll
        for (int mi = 0; mi < 2; mi++) {
            u32 aadd = (u32)((wm * 32 + mi * 16 + lrow + k) * 40 + icb + lhalf) * 2;
            ldsm_x4(ah[mi][0], ah[mi][1], ah[mi][2], ah[mi][3], sbXh + aadd);
        }
        u32 t0r, t1r, t2r, t3r;
        u32 bh[2][2];
        ldsm_x4(t0r, t1r, t2r, t3r, boff + ks * 32);
        bh[0][0] = t0r; bh[0][1] = t2r; bh[1][0] = t1r; bh[1][1] = t3r;

#pragma unroll
        for (int mi = 0; mi < 2; mi++)
#pragma unroll
            for (int ni = 0; ni < 2; ni++)
                mma_bf16(acc[mi][ni], ah[mi], bh[ni]);
    }
    __syncthreads();

    u32* stgh = (u32*)sXh;   // 256*9 u32
#pragma unroll
    for (int mi = 0; mi < 2; mi++)
#pragma unroll
        for (int ni = 0; ni < 2; ni++) {
            int ch = ni * 8 + qc;
            float bv0 = __ldg(&bias[ch]), bv1 = __ldg(&bias[ch + 1]);
            int p0 = wm * 32 + mi * 16 + grp, p1 = p0 + 8;
            float v00 = gelu_erf(acc[mi][ni][0] + bv0), v01 = gelu_erf(acc[mi][ni][1] + bv1);
            float v10 = gelu_erf(acc[mi][ni][2] + bv0), v11 = gelu_erf(acc[mi][ni][3] + bv1);
            __nv_bfloat162 th = __halves2bfloat162(__float2bfloat16(v00), __float2bfloat16(v01));
            stgh[p0 * 9 + ni * 4 + (lane & 3)] = *(u32*)&th;
            th = __halves2bfloat162(__float2bfloat16(v10), __float2bfloat16(v11));
            stgh[p1 * 9 + ni * 4 + (lane & 3)] = *(u32*)&th;
        }
    __syncthreads();
    for (int i = tid; i < 256 * 8; i += 256) {
        int p = i >> 3, q = i & 7;
        int l = t0 + p;
        if (l < L_)
            ((u32*)r2h)[((size_t)b * L_ + l) * 8 + q] = stgh[p * 9 + q];
    }
}

// ================= conv3: 16->8 k15 single-bf16 + residual + pointwise =================
#define C3ROWS 271
#define C3SM (C3ROWS * 40 * 2 + 8 * 248 * 2 + 256 * 9 * 4)
__global__ void __launch_bounds__(256) conv3_hmma(
    const bf16* __restrict__ r2h,
    const bf16* __restrict__ wh,
    const float* __restrict__ bias,
    const bf16* __restrict__ rech, const bf16* __restrict__ recl,
    const float* __restrict__ pw, const float* __restrict__ pb,
    float* __restrict__ out)
{
    extern __shared__ __align__(16) char dsm3[];
    bf16* sXh = (bf16*)dsm3;
    bf16* sWh = sXh + C3ROWS * 40;
    float* sF = (float*)(sWh + 8 * 248);

    const int tid  = threadIdx.x;
    const int lane = tid & 31;
    const int wm   = tid >> 5;
    const int b    = blockIdx.y;
    const int t0   = blockIdx.x * 256;

    for (int i = tid; i < 8 * 120; i += 256) {
        int r = i / 120, c = i - r * 120;
        ((u32*)sWh)[r * 124 + c] = ((const u32*)wh)[r * 120 + c];
    }
    for (int i = tid; i < C3ROWS * 2; i += 256) {
        int r = i >> 1, q = i & 1;
        int gp = t0 + r - 7;
        uint4 vh = make_uint4(0,0,0,0);
        if (gp >= 0 && gp < L_) {
            size_t o = ((size_t)b * L_ + gp) * 16 + q * 8;
            vh = *(const uint4*)(r2h + o);
        }
        *(uint4*)(sXh + r * 40 + q * 8) = vh;
    }
    __syncthreads();

    const u32 sbXh = smem_u32(sXh);
    const u32 sbWh = smem_u32(sWh);
    const int lrow = lane & 15;
    const int lhalf = (lane >> 4) * 8;
    const u32 bbase = ((lane & 7) * 248 + ((lane >> 3) & 1) * 8) * 2;
    const int grp = lane >> 2, qc = (lane & 3) * 2;

    float acc[2][4];
#pragma unroll
    for (int mi = 0; mi < 2; mi++)
#pragma unroll
        for (int q = 0; q < 4; q++) acc[mi][q] = 0.0f;

#pragma unroll
    for (int k = 0; k < 15; k++) {
        u32 ah[2][4];
#pragma unroll
        for (int mi = 0; mi < 2; mi++) {
            u32 aadd = (u32)((wm * 32 + mi * 16 + lrow + k) * 40 + lhalf) * 2;
            ldsm_x4(ah[mi][0], ah[mi][1], ah[mi][2], ah[mi][3], sbXh + aadd);
        }
        u32 bh[2];
        ldsm_x2(bh[0], bh[1], sbWh + bbase + k * 32);
#pragma unroll
        for (int mi = 0; mi < 2; mi++) mma_bf16(acc[mi], ah[mi], bh);
    }
    __syncthreads();

    {
        float bv0 = __ldg(&bias[qc]), bv1 = __ldg(&bias[qc + 1]);
#pragma unroll
        for (int mi = 0; mi < 2; mi++) {
            int p0 = wm * 32 + mi * 16 + grp, p1 = p0 + 8;
            sF[p0 * 9 + qc]     = acc[mi][0] + bv0;
            sF[p0 * 9 + qc + 1] = acc[mi][1] + bv1;
            sF[p1 * 9 + qc]     = acc[mi][2] + bv0;
            sF[p1 * 9 + qc + 1] = acc[mi][3] + bv1;
        }
    }
    __syncthreads();

    {
        int l = t0 + tid;
        if (l < L_) {
            size_t ro = ((size_t)b * L_ + l) * 8;
            uint4 vh = *(const uint4*)(rech + ro);
            uint4 vl = *(const uint4*)(recl + ro);
            const unsigned short* hs = (const unsigned short*)&vh;
            const unsigned short* ls = (const unsigned short*)&vl;
            float resid[8];
#pragma unroll
            for (int c = 0; c < 8; c++) {
                float rv = __bfloat162float(__ushort_as_bfloat16(hs[c]))
                         + __bfloat162float(__ushort_as_bfloat16(ls[c]));
                resid[c] = rv + sF[tid * 9 + c];
            }
#pragma unroll
            for (int o = 0; o < 8; o++) {
                float v = __ldg(&pb[o]);
#pragma unroll
                for (int c = 0; c < 8; c++)
                    v += __ldg(&pw[o * C_ + c]) * resid[c];
                out[((size_t)b * C_ + o) * L_ + l] = v;
            }
        }
    }
}

// ---------------- launcher ----------------
extern "C" void kernel_launch(void* const* d_in, const int* in_sizes, int n_in,
                              void* d_out, int out_size)
{
    const float* X   = (const float*)d_in[0];
    const float* W1  = (const float*)d_in[1];
    const float* b1  = (const float*)d_in[2];
    const float* W2  = (const float*)d_in[3];
    const float* b2  = (const float*)d_in[4];
    const float* rw1 = (const float*)d_in[5];
    const float* rb1 = (const float*)d_in[6];
    const float* rw2 = (const float*)d_in[7];
    const float* rb2 = (const float*)d_in[8];
    const float* rw3 = (const float*)d_in[9];
    const float* rb3 = (const float*)d_in[10];
    const float* pw  = (const float*)d_in[11];
    const float* pb  = (const float*)d_in[12];
    float* out = (float*)d_out;

    bf16 *pHh, *pHl, *pW1th, *pW1tl, *pW2th, *pW2tl;
    bf16 *pRech, *pRecl, *pR1h, *pR2h;
    bf16 *pCw1h, *pW2h, *pCw3h;
    float *pPatches;
    cudaGetSymbolAddress((void**)&pHh,   g_Hh);
    cudaGetSymbolAddress((void**)&pHl,   g_Hl);
    cudaGetSymbolAddress((void**)&pW1th, g_W1th);
    cudaGetSymbolAddress((void**)&pW1tl, g_W1tl);
    cudaGetSymbolAddress((void**)&pW2th, g_W2th);
    cudaGetSymbolAddress((void**)&pW2tl, g_W2tl);
    cudaGetSymbolAddress((void**)&pPatches, g_patches);
    cudaGetSymbolAddress((void**)&pRech, g_rech);
    cudaGetSymbolAddress((void**)&pRecl, g_recl);
    cudaGetSymbolAddress((void**)&pR1h,  g_r1h);
    cudaGetSymbolAddress((void**)&pR2h,  g_r2h);
    cudaGetSymbolAddress((void**)&pCw1h, g_cw1h);
    cudaGetSymbolAddress((void**)&pW2h,  g_w2h);
    cudaGetSymbolAddress((void**)&pCw3h, g_cw3h);

    cudaFuncSetAttribute(gemm_hmma<true,  true>,
                         cudaFuncAttributeMaxDynamicSharedMemorySize, GEMM_SMEM);
    cudaFuncSetAttribute(gemm_hmma<false, false>,
                         cudaFuncAttributeMaxDynamicSharedMemorySize, GEMM_SMEM);
    cudaFuncSetAttribute(conv1_hmma, cudaFuncAttributeMaxDynamicSharedMemorySize, C1SM);
    cudaFuncSetAttribute(conv2_hmma, cudaFuncAttributeMaxDynamicSharedMemorySize, C2SM);
    cudaFuncSetAttribute(conv3_hmma, cudaFuncAttributeMaxDynamicSharedMemorySize, C3SM);

    const int convGrid = (L_ + 255) / 256;   // 8

    // order: GEMM1 stays in ncu capture slot (#4)
    transp_split_kernel<<<(512*512 + 255) / 256, 256>>>(W1, pW1th, pW1tl, 512, 512, 512); // 1
    transp_split_kernel<<<(256*512 + 255) / 256, 256>>>(W2, pW2th, pW2tl, 512, 200, 256); // 2
    w1c_prep_kernel<<<(32*128 + 255) / 256, 256>>>(rw1, pCw1h);                           // 3

    // 4: GEMM1 -- Hh/Hl = split(GELU(X @ W1 + b1)), fp32-split fused in loader
    gemm_hmma<true, true><<<dim3(8, M_ / 128), 256, GEMM_SMEM>>>(
        X, nullptr, nullptr, pW1th, pW1tl, b1, 512, pHh, pHl, nullptr);

    w2_prep_kernel<<<(16*480 + 255) / 256, 256>>>(rw2, pW2h);                             // 5
    w3c_prep_kernel<<<(8*240 + 255) / 256, 256>>>(rw3, pCw3h);                            // 6

    // 7: GEMM2 -- patches = H @ W2 + b2
    gemm_hmma<false, false><<<dim3(4, M_ / 128), 256, GEMM_SMEM>>>(
        nullptr, pHh, pHl, pW2th, pW2tl, b2, 200, nullptr, nullptr, pPatches);

    // 8: overlap-add -> rec (hi/lo kept: residual path needs full precision)
    overlap_add_v3<<<dim3((L_ + 255) / 256, B_), 256>>>(pPatches, pRech, pRecl);

    // 9-11: single-bf16 convs (error attenuated ~65x by small residual-path gain)
    conv1_hmma<<<dim3(convGrid, B_), 256, C1SM>>>(pRech, pCw1h, rb1, pR1h);
    conv2_hmma<<<dim3(convGrid, B_), 256, C2SM>>>(pR1h, pW2h, rb2, pR2h);
    conv3_hmma<<<dim3(convGrid, B_), 256, C3SM>>>(pR2h, pCw3h, rb3,
                                                  pRech, pRecl, pw, pb, out);
}

// round 14
// speedup vs baseline: 1.4860x; 1.1632x over previous
#include <cuda_runtime.h>
#include <cuda_bf16.h>
#include <cuda_fp16.h>
#include <math.h>
#include <stdint.h>

#define B_      1024
#define P_      11
#define C_      8
#define H_      512
#define T_      200
#define L_      2000
#define STRIDE_ 180
#define M_      (B_*P_*C_)

typedef unsigned long long u64;
typedef unsigned int u32;
typedef __nv_bfloat16 bf16;
typedef __half f16;

// ---------------- scratch (device globals) ----------------
__device__ f16 g_Hh[(size_t)M_ * 512];
__device__ f16 g_Hl[(size_t)M_ * 512];
__device__ f16 g_W1t[512 * 512];
__device__ f16 g_W2t[256 * 512];
__device__ float g_patches[(size_t)M_ * T_];
__device__ bf16 g_rech[(size_t)B_ * L_ * 8];
__device__ bf16 g_recl[(size_t)B_ * L_ * 8];
__device__ bf16 g_r1h[(size_t)B_ * L_ * 32];
__device__ bf16 g_r2h[(size_t)B_ * L_ * 16];
__device__ bf16 g_cw1h[32 * 128];
__device__ bf16 g_w2h[16 * 480];
__device__ bf16 g_cw3h[8 * 240];

__device__ __forceinline__ float gelu_erf(float x) {
    return 0.5f * x * (1.0f + erff(x * 0.7071067811865476f));
}

// ---------------- warp MMA primitives ----------------
__device__ __forceinline__ uint32_t smem_u32(const void* p) {
    uint32_t a;
    asm("{ .reg .u64 t; cvta.to.shared.u64 t, %1; cvt.u32.u64 %0, t; }" : "=r"(a) : "l"(p));
    return a;
}
__device__ __forceinline__ void ldsm_x4(u32& r0, u32& r1, u32& r2, u32& r3, u32 addr) {
    asm volatile("ldmatrix.sync.aligned.m8n8.x4.shared.b16 {%0,%1,%2,%3}, [%4];"
        : "=r"(r0), "=r"(r1), "=r"(r2), "=r"(r3) : "r"(addr));
}
__device__ __forceinline__ void ldsm_x2(u32& r0, u32& r1, u32 addr) {
    asm volatile("ldmatrix.sync.aligned.m8n8.x2.shared.b16 {%0,%1}, [%2];"
        : "=r"(r0), "=r"(r1) : "r"(addr));
}
__device__ __forceinline__ void mma_bf16(float* d, const u32* a, const u32* b) {
    asm volatile("mma.sync.aligned.m16n8k16.row.col.f32.bf16.bf16.f32 "
        "{%0,%1,%2,%3}, {%4,%5,%6,%7}, {%8,%9}, {%0,%1,%2,%3};"
        : "+f"(d[0]), "+f"(d[1]), "+f"(d[2]), "+f"(d[3])
        : "r"(a[0]), "r"(a[1]), "r"(a[2]), "r"(a[3]), "r"(b[0]), "r"(b[1]));
}
__device__ __forceinline__ void mma_f16(float* d, const u32* a, const u32* b) {
    asm volatile("mma.sync.aligned.m16n8k16.row.col.f32.f16.f16.f32 "
        "{%0,%1,%2,%3}, {%4,%5,%6,%7}, {%8,%9}, {%0,%1,%2,%3};"
        : "+f"(d[0]), "+f"(d[1]), "+f"(d[2]), "+f"(d[3])
        : "r"(a[0]), "r"(a[1]), "r"(a[2]), "r"(a[3]), "r"(b[0]), "r"(b[1]));
}
__device__ __forceinline__ void split_bf16(float v, bf16& h, bf16& l) {
    h = __float2bfloat16(v);
    l = __float2bfloat16(v - __bfloat162float(h));
}
__device__ __forceinline__ void split_f16(float v, f16& h, f16& l) {
    h = __float2half(v);
    l = __float2half(v - __half2float(h));
}

// ================= prep kernels (weights only) =================
__global__ void transp_f16_kernel(const float* __restrict__ W,
                                  f16* __restrict__ t,
                                  int Kdim, int Nsrc, int Npad)
{
    int idx = blockIdx.x * 256 + threadIdx.x;
    if (idx >= Npad * Kdim) return;
    int n = idx / Kdim, k = idx - n * Kdim;
    float f = (n < Nsrc) ? W[(size_t)k * Nsrc + n] : 0.0f;
    t[idx] = __float2half(f);
}

__global__ void w1c_prep_kernel(const float* __restrict__ w, bf16* __restrict__ wh)
{
    int idx = blockIdx.x * 256 + threadIdx.x;
    if (idx >= 32 * 128) return;
    int co = idx >> 7, c = idx & 127;
    int ks = c >> 4, rem = c & 15;
    int tap = 2 * ks + (rem >> 3);
    int ic = rem & 7;
    float f = (tap < 15) ? w[((size_t)co * 8 + ic) * 15 + tap] : 0.0f;
    wh[idx] = __float2bfloat16(f);
}

__global__ void w2_prep_kernel(const float* __restrict__ w, bf16* __restrict__ wh)
{
    int idx = blockIdx.x * 256 + threadIdx.x;
    if (idx >= 16 * 480) return;
    int co = idx / 480, c = idx - co * 480;
    int k = c >> 5, ic = c & 31;
    wh[idx] = __float2bfloat16(w[((size_t)co * 32 + ic) * 15 + k]);
}

__global__ void w3c_prep_kernel(const float* __restrict__ w, bf16* __restrict__ wh)
{
    int idx = blockIdx.x * 256 + threadIdx.x;
    if (idx >= 8 * 240) return;
    int co = idx / 240, c = idx - co * 240;
    int k = c >> 4, ic = c & 15;
    wh[idx] = __float2bfloat16(w[((size_t)co * 16 + ic) * 15 + k]);
}

// ================= fp16 2-MMA GEMM: 128x64 block, dbuf, A = hi+lo fp16, B single fp16 =================
#define ASTR 40
#define A_ELE (128 * ASTR)
#define B_ELE (64 * ASTR)
#define GEMM_SMEM ((2 * A_ELE * 2 + 2 * B_ELE) * 2)   // Ah, Al double-buffered + B double-buffered

template<bool A_FP32, bool GELU_SPLIT>
__global__ void __launch_bounds__(256, 2) gemm_hmma(
    const float* __restrict__ Af,
    const f16* __restrict__ Ah, const f16* __restrict__ Al,
    const f16* __restrict__ Bt,
    const float* __restrict__ bias, int Nvalid,
    f16* __restrict__ outHh, f16* __restrict__ outHl, float* __restrict__ outF)
{
    extern __shared__ __align__(16) char dynsm[];
    f16* sAh = (f16*)dynsm;
    f16* sAl = sAh + 2 * A_ELE;
    f16* sB  = sAl + 2 * A_ELE;

    const int tid  = threadIdx.x;
    const int lane = tid & 31;
    const int wid  = tid >> 5;
    const int wm   = wid & 3;
    const int wn   = wid >> 2;
    const int bm   = blockIdx.y * 128;
    const int bn   = blockIdx.x * 64;

    float acc[2][4][4];
#pragma unroll
    for (int i = 0; i < 2; i++)
#pragma unroll
        for (int j = 0; j < 4; j++)
#pragma unroll
            for (int q = 0; q < 4; q++) acc[i][j][q] = 0.0f;

    const int ar = tid >> 2;
    const int aq = (tid & 3) * 8;
    const size_t gA0 = (size_t)(bm + ar) * 512 + aq;
    const size_t gA1 = (size_t)(bm + ar + 64) * 512 + aq;
    const size_t gB0 = (size_t)(bn + ar) * 512 + aq;

    const u32 sbAh = smem_u32(sAh), sbAl = smem_u32(sAl);
    const u32 sbB  = smem_u32(sB);

    const int lrow = lane & 15;
    const int lhalf = (lane >> 4) * 8;
    const u32 aoffA0 = ((wm * 32 +      lrow) * ASTR + lhalf) * 2;
    const u32 aoffA1 = ((wm * 32 + 16 + lrow) * ASTR + lhalf) * 2;
    const u32 aoffB0 = ((wn * 32 +      lrow) * ASTR + lhalf) * 2;
    const u32 aoffB1 = ((wn * 32 + 16 + lrow) * ASTR + lhalf) * 2;

    uint4 pah0, pah1, pal0, pal1;
    float4 fa0, fa1, fb0, fb1;
    uint4 pb;

    if (A_FP32) {
        fa0 = *(const float4*)(Af + gA0); fa1 = *(const float4*)(Af + gA0 + 4);
        fb0 = *(const float4*)(Af + gA1); fb1 = *(const float4*)(Af + gA1 + 4);
    } else {
        pah0 = *(const uint4*)(Ah + gA0); pah1 = *(const uint4*)(Ah + gA1);
        pal0 = *(const uint4*)(Al + gA0); pal1 = *(const uint4*)(Al + gA1);
    }
    pb = *(const uint4*)(Bt + gB0);

    const int sA0 = ar * ASTR + aq, sA1 = (ar + 64) * ASTR + aq, sB0 = ar * ASTR + aq;

    for (int kt = 0; kt < 16; kt++) {
        const int cur = kt & 1;
        const int aBuf = cur * A_ELE, bBuf = cur * B_ELE;

        if (A_FP32) {
            float f0[8] = {fa0.x, fa0.y, fa0.z, fa0.w, fa1.x, fa1.y, fa1.z, fa1.w};
            float f1[8] = {fb0.x, fb0.y, fb0.z, fb0.w, fb1.x, fb1.y, fb1.z, fb1.w};
            unsigned short h0[8], l0[8], h1[8], l1[8];
#pragma unroll
            for (int j = 0; j < 8; j++) {
                f16 h, l;
                split_f16(f0[j], h, l);
                h0[j] = __half_as_ushort(h); l0[j] = __half_as_ushort(l);
                split_f16(f1[j], h, l);
                h1[j] = __half_as_ushort(h); l1[j] = __half_as_ushort(l);
            }
            *(uint4*)(sAh + aBuf + sA0) = *(uint4*)h0; *(uint4*)(sAl + aBuf + sA0) = *(uint4*)l0;
            *(uint4*)(sAh + aBuf + sA1) = *(uint4*)h1; *(uint4*)(sAl + aBuf + sA1) = *(uint4*)l1;
        } else {
            *(uint4*)(sAh + aBuf + sA0) = pah0; *(uint4*)(sAh + aBuf + sA1) = pah1;
            *(uint4*)(sAl + aBuf + sA0) = pal0; *(uint4*)(sAl + aBuf + sA1) = pal1;
        }
        *(uint4*)(sB + bBuf + sB0) = pb;
        __syncthreads();

        if (kt < 15) {
            int k0 = (kt + 1) * 32;
            if (A_FP32) {
                fa0 = *(const float4*)(Af + gA0 + k0); fa1 = *(const float4*)(Af + gA0 + k0 + 4);
                fb0 = *(const float4*)(Af + gA1 + k0); fb1 = *(const float4*)(Af + gA1 + k0 + 4);
            } else {
                pah0 = *(const uint4*)(Ah + gA0 + k0); pah1 = *(const uint4*)(Ah + gA1 + k0);
                pal0 = *(const uint4*)(Al + gA0 + k0); pal1 = *(const uint4*)(Al + gA1 + k0);
            }
            pb = *(const uint4*)(Bt + gB0 + k0);
        }

        const u32 aByte = (u32)(aBuf * 2), bByte = (u32)(bBuf * 2);
#pragma unroll
        for (int kk = 0; kk < 2; kk++) {
            const u32 kadd = kk * 32;
            u32 a_h[2][4], a_l[2][4];
            ldsm_x4(a_h[0][0], a_h[0][1], a_h[0][2], a_h[0][3], sbAh + aByte + aoffA0 + kadd);
            ldsm_x4(a_h[1][0], a_h[1][1], a_h[1][2], a_h[1][3], sbAh + aByte + aoffA1 + kadd);
            ldsm_x4(a_l[0][0], a_l[0][1], a_l[0][2], a_l[0][3], sbAl + aByte + aoffA0 + kadd);
            ldsm_x4(a_l[1][0], a_l[1][1], a_l[1][2], a_l[1][3], sbAl + aByte + aoffA1 + kadd);

            u32 t0, t1, t2, t3;
            u32 b[4][2];
            ldsm_x4(t0, t1, t2, t3, sbB + bByte + aoffB0 + kadd);
            b[0][0] = t0; b[0][1] = t2; b[1][0] = t1; b[1][1] = t3;
            ldsm_x4(t0, t1, t2, t3, sbB + bByte + aoffB1 + kadd);
            b[2][0] = t0; b[2][1] = t2; b[3][0] = t1; b[3][1] = t3;

#pragma unroll
            for (int s = 0; s < 2; s++) {
#pragma unroll
                for (int mi = 0; mi < 2; mi++)
#pragma unroll
                    for (int ni = 0; ni < 4; ni++) {
                        const u32* aa = (s == 1) ? a_l[mi] : a_h[mi];
                        mma_f16(acc[mi][ni], aa, b[ni]);
                    }
            }
        }
    }

    const int grp = lane >> 2;
    const int qc  = (lane & 3) * 2;
#pragma unroll
    for (int mi = 0; mi < 2; mi++) {
        const int r0 = bm + wm * 32 + mi * 16 + grp;
        const int r1 = r0 + 8;
#pragma unroll
        for (int ni = 0; ni < 4; ni++) {
            const int col = bn + wn * 32 + ni * 8 + qc;
            float bv0 = __ldg(&bias[col]), bv1 = __ldg(&bias[col + 1]);
            float v00 = acc[mi][ni][0] + bv0, v01 = acc[mi][ni][1] + bv1;
            float v10 = acc[mi][ni][2] + bv0, v11 = acc[mi][ni][3] + bv1;
            if (GELU_SPLIT) {
                v00 = gelu_erf(v00); v01 = gelu_erf(v01);
                v10 = gelu_erf(v10); v11 = gelu_erf(v11);
                f16 h0, h1, l0, l1;
                split_f16(v00, h0, l0); split_f16(v01, h1, l1);
                size_t i0 = (size_t)r0 * 256 + (col >> 1);
                reinterpret_cast<__half2*>(outHh)[i0] = __halves2half2(h0, h1);
                reinterpret_cast<__half2*>(outHl)[i0] = __halves2half2(l0, l1);
                split_f16(v10, h0, l0); split_f16(v11, h1, l1);
                size_t i1 = (size_t)r1 * 256 + (col >> 1);
                reinterpret_cast<__half2*>(outHh)[i1] = __halves2half2(h0, h1);
                reinterpret_cast<__half2*>(outHl)[i1] = __halves2half2(l0, l1);
            } else {
                if (col < Nvalid) {
                    *(float2*)(outF + (size_t)r0 * Nvalid + col) = make_float2(v00, v01);
                    *(float2*)(outF + (size_t)r1 * Nvalid + col) = make_float2(v10, v11);
                }
            }
        }
    }
}

// ================= overlap-add -> rec bf16 split [b][l][8] =================
__global__ void overlap_add_v3(const float* __restrict__ patches,
                               bf16* __restrict__ rech, bf16* __restrict__ recl)
{
    const int b  = blockIdx.y;
    const int l  = blockIdx.x * 256 + threadIdx.x;
    if (l >= L_) return;

    int i_lo = l - (T_ - 1);
    i_lo = (i_lo > 0) ? (i_lo + STRIDE_ - 1) / STRIDE_ : 0;
    int i_hi = l / STRIDE_;
    if (i_hi > P_ - 1) i_hi = P_ - 1;

    int np = 0, pi[2], pt[2];
    float wv[2], ws = 0.0f;
    for (int i = i_lo; i <= i_hi; i++) {
        int t = l - i * STRIDE_;
        float w;
        if (t < 50)        w = (float)t * (1.0f / 49.0f);
        else if (t >= 150) w = (float)(199 - t) * (1.0f / 49.0f);
        else               w = 1.0f;
        pi[np] = i; pt[np] = t; wv[np] = w; ws += w; np++;
    }
    float ews = fmaxf(ws, 1e-8f);

    unsigned short hh[8], ll[8];
#pragma unroll
    for (int c = 0; c < 8; c++) {
        float v = 0.0f;
        for (int j = 0; j < np; j++)
            v += patches[(((size_t)b * P_ + pi[j]) * C_ + c) * T_ + pt[j]] * wv[j];
        v = v / ews;
        bf16 h, lo; split_bf16(v, h, lo);
        hh[c] = __bfloat16_as_ushort(h);
        ll[c] = __bfloat16_as_ushort(lo);
    }
    size_t o = ((size_t)b * L_ + l) * 8;
    *(uint4*)(rech + o) = *(uint4*)hh;
    *(uint4*)(recl + o) = *(uint4*)ll;
}

// ================= conv1: 8->32 k15, single-bf16 HMMA =================
#define C1ROWS 271
#define C1SM (C1ROWS * 40 * 2 + 32 * 136 * 2)
__global__ void __launch_bounds__(256) conv1_hmma(
    const bf16* __restrict__ rech,
    const bf16* __restrict__ wh,
    const float* __restrict__ bias,
    bf16* __restrict__ r1h)
{
    extern __shared__ __align__(16) char dsm1[];
    bf16* sXh = (bf16*)dsm1;
    bf16* sWh = sXh + C1ROWS * 40;

    const int tid  = threadIdx.x;
    const int lane = tid & 31;
    const int wm   = tid >> 5;
    const int b    = blockIdx.y;
    const int t0   = blockIdx.x * 256;

    for (int i = tid; i < 32 * 64; i += 256) {
        int r = i >> 6, q = i & 63;
        ((u32*)sWh)[r * 68 + q] = ((const u32*)wh)[r * 64 + q];
    }
    for (int i = tid; i < C1ROWS * 2; i += 256) {
        int r = i >> 1, half = i & 1;
        int gp = t0 + r - 7 + half;
        uint4 vh = make_uint4(0,0,0,0);
        if (gp >= 0 && gp < L_) {
            size_t o = ((size_t)b * L_ + gp) * 8;
            vh = *(const uint4*)(rech + o);
        }
        *(uint4*)(sXh + r * 40 + half * 8) = vh;
    }
    __syncthreads();

    const u32 sbXh = smem_u32(sXh);
    const u32 sbWh = smem_u32(sWh);
    const int lrow = lane & 15;
    const int lhalf = (lane >> 4) * 8;
    const int grp = lane >> 2, qc = (lane & 3) * 2;

    float acc[2][4][4];
#pragma unroll
    for (int mi = 0; mi < 2; mi++)
#pragma unroll
        for (int ni = 0; ni < 4; ni++)
#pragma unroll
            for (int q = 0; q < 4; q++) acc[mi][ni][q] = 0.0f;

#pragma unroll
    for (int k = 0; k < 8; k++) {
        u32 ah[2][4];
#pragma unroll
        for (int mi = 0; mi < 2; mi++) {
            u32 aadd = (u32)((wm * 32 + mi * 16 + lrow + 2 * k) * 40 + lhalf) * 2;
            ldsm_x4(ah[mi][0], ah[mi][1], ah[mi][2], ah[mi][3], sbXh + aadd);
        }
        u32 t0r, t1r, t2r, t3r;
        u32 bh[4][2];
#pragma unroll
        for (int na2 = 0; na2 < 2; na2++) {
            u32 badd = (u32)((na2 * 16 + lrow) * 136 + k * 16 + lhalf) * 2;
            ldsm_x4(t0r, t1r, t2r, t3r, sbWh + badd);
            bh[na2*2][0] = t0r; bh[na2*2][1] = t2r;
            bh[na2*2+1][0] = t1r; bh[na2*2+1][1] = t3r;
        }
#pragma unroll
        for (int mi = 0; mi < 2; mi++)
#pragma unroll
            for (int ni = 0; ni < 4; ni++)
                mma_bf16(acc[mi][ni], ah[mi], bh[ni]);
    }
    __syncthreads();

    u32* stgh = (u32*)sXh;
#pragma unroll
    for (int mi = 0; mi < 2; mi++)
#pragma unroll
        for (int ni = 0; ni < 4; ni++) {
            int ch = ni * 8 + qc;
            float bv0 = __ldg(&bias[ch]), bv1 = __ldg(&bias[ch + 1]);
            int p0 = wm * 32 + mi * 16 + grp, p1 = p0 + 8;
            float v00 = gelu_erf(acc[mi][ni][0] + bv0), v01 = gelu_erf(acc[mi][ni][1] + bv1);
            float v10 = gelu_erf(acc[mi][ni][2] + bv0), v11 = gelu_erf(acc[mi][ni][3] + bv1);
            __nv_bfloat162 th = __halves2bfloat162(__float2bfloat16(v00), __float2bfloat16(v01));
            stgh[p0 * 17 + ni * 4 + (lane & 3)] = *(u32*)&th;
            th = __halves2bfloat162(__float2bfloat16(v10), __float2bfloat16(v11));
            stgh[p1 * 17 + ni * 4 + (lane & 3)] = *(u32*)&th;
        }
    __syncthreads();
    for (int i = tid; i < 256 * 16; i += 256) {
        int p = i >> 4, q = i & 15;
        int l = t0 + p;
        if (l < L_)
            ((u32*)r1h)[((size_t)b * L_ + l) * 16 + q] = stgh[p * 17 + q];
    }
}

// ================= conv2: 32->16 k15, single-bf16 HMMA =================
#define C2ROWS 272
#define C2SM (C2ROWS * 40 * 2 + 16 * 488 * 2)
__global__ void __launch_bounds__(256) conv2_hmma(
    const bf16* __restrict__ r1h,
    const bf16* __restrict__ wh,
    const float* __restrict__ bias,
    bf16* __restrict__ r2h)
{
    extern __shared__ __align__(16) char dsm2[];
    bf16* sXh = (bf16*)dsm2;
    bf16* sWh = sXh + C2ROWS * 40;

    const int tid  = threadIdx.x;
    const int lane = tid & 31;
    const int wm   = tid >> 5;
    const int b    = blockIdx.y;
    const int t0   = blockIdx.x * 256;

    for (int i = tid; i < 16 * 240; i += 256) {
        int r = i / 240, c = i - r * 240;
        ((u32*)sWh)[r * 244 + c] = ((const u32*)wh)[r * 240 + c];
    }
    for (int i = tid; i < C2ROWS * 4; i += 256) {
        int r = i >> 2, q = i & 3;
        int gp = t0 + r - 7;
        uint4 vh = make_uint4(0,0,0,0);
        if (gp >= 0 && gp < L_) {
            size_t o = ((size_t)b * L_ + gp) * 32 + q * 8;
            vh = *(const uint4*)(r1h + o);
        }
        *(uint4*)(sXh + r * 40 + q * 8) = vh;
    }
    __syncthreads();

    const u32 sbXh = smem_u32(sXh);
    const u32 sbWh = smem_u32(sWh);
    const int lrow = lane & 15;
    const int lhalf = (lane >> 4) * 8;
    const u32 boff = sbWh + ((lane & 15) * 488 + lhalf) * 2;
    const int grp = lane >> 2, qc = (lane & 3) * 2;

    float acc[2][2][4];
#pragma unroll
    for (int mi = 0; mi < 2; mi++)
#pragma unroll
        for (int ni = 0; ni < 2; ni++)
#pragma unroll
            for (int q = 0; q < 4; q++) acc[mi][ni][q] = 0.0f;

#pragma unroll 2
    for (int ks = 0; ks < 30; ks++) {
        const int k   = ks >> 1;
        const int icb = (ks & 1) * 16;
        u32 ah[2][4];
#pragma unroll
        for (int mi = 0; mi < 2; mi++) {
            u32 aadd = (u32)((wm * 32 + mi * 16 + lrow + k) * 40 + icb + lhalf) * 2;
            ldsm_x4(ah[mi][0], ah[mi][1], ah[mi][2], ah[mi][3], sbXh + aadd);
        }
        u32 t0r, t1r, t2r, t3r;
        u32 bh[2][2];
        ldsm_x4(t0r, t1r, t2r, t3r, boff + ks * 32);
        bh[0][0] = t0r; bh[0][1] = t2r; bh[1][0] = t1r; bh[1][1] = t3r;

#pragma unroll
        for (int mi = 0; mi < 2; mi++)
#pragma unroll
            for (int ni = 0; ni < 2; ni++)
                mma_bf16(acc[mi][ni], ah[mi], bh[ni]);
    }
    __syncthreads();

    u32* stgh = (u32*)sXh;
#pragma unroll
    for (int mi = 0; mi < 2; mi++)
#pragma unroll
        for (int ni = 0; ni < 2; ni++) {
            int ch = ni * 8 + qc;
            float bv0 = __ldg(&bias[ch]), bv1 = __ldg(&bias[ch + 1]);
            int p0 = wm * 32 + mi * 16 + grp, p1 = p0 + 8;
            float v00 = gelu_erf(acc[mi][ni][0] + bv0), v01 = gelu_erf(acc[mi][ni][1] + bv1);
            float v10 = gelu_erf(acc[mi][ni][2] + bv0), v11 = gelu_erf(acc[mi][ni][3] + bv1);
            __nv_bfloat162 th = __halves2bfloat162(__float2bfloat16(v00), __float2bfloat16(v01));
            stgh[p0 * 9 + ni * 4 + (lane & 3)] = *(u32*)&th;
            th = __halves2bfloat162(__float2bfloat16(v10), __float2bfloat16(v11));
            stgh[p1 * 9 + ni * 4 + (lane & 3)] = *(u32*)&th;
        }
    __syncthreads();
    for (int i = tid; i < 256 * 8; i += 256) {
        int p = i >> 3, q = i & 7;
        int l = t0 + p;
        if (l < L_)
            ((u32*)r2h)[((size_t)b * L_ + l) * 8 + q] = stgh[p * 9 + q];
    }
}

// ================= conv3: 16->8 k15 single-bf16 + residual + pointwise =================
#define C3ROWS 271
#define C3SM (C3ROWS * 40 * 2 + 8 * 248 * 2 + 256 * 9 * 4)
__global__ void __launch_bounds__(256) conv3_hmma(
    const bf16* __restrict__ r2h,
    const bf16* __restrict__ wh,
    const float* __restrict__ bias,
    const bf16* __restrict__ rech, const bf16* __restrict__ recl,
    const float* __restrict__ pw, const float* __restrict__ pb,
    float* __restrict__ out)
{
    extern __shared__ __align__(16) char dsm3[];
    bf16* sXh = (bf16*)dsm3;
    bf16* sWh = sXh + C3ROWS * 40;
    float* sF = (float*)(sWh + 8 * 248);

    const int tid  = threadIdx.x;
    const int lane = tid & 31;
    const int wm   = tid >> 5;
    const int b    = blockIdx.y;
    const int t0   = blockIdx.x * 256;

    for (int i = tid; i < 8 * 120; i += 256) {
        int r = i / 120, c = i - r * 120;
        ((u32*)sWh)[r * 124 + c] = ((const u32*)wh)[r * 120 + c];
    }
    for (int i = tid; i < C3ROWS * 2; i += 256) {
        int r = i >> 1, q = i & 1;
        int gp = t0 + r - 7;
        uint4 vh = make_uint4(0,0,0,0);
        if (gp >= 0 && gp < L_) {
            size_t o = ((size_t)b * L_ + gp) * 16 + q * 8;
            vh = *(const uint4*)(r2h + o);
        }
        *(uint4*)(sXh + r * 40 + q * 8) = vh;
    }
    __syncthreads();

    const u32 sbXh = smem_u32(sXh);
    const u32 sbWh = smem_u32(sWh);
    const int lrow = lane & 15;
    const int lhalf = (lane >> 4) * 8;
    const u32 bbase = ((lane & 7) * 248 + ((lane >> 3) & 1) * 8) * 2;
    const int grp = lane >> 2, qc = (lane & 3) * 2;

    float acc[2][4];
#pragma unroll
    for (int mi = 0; mi < 2; mi++)
#pragma unroll
        for (int q = 0; q < 4; q++) acc[mi][q] = 0.0f;

#pragma unroll
    for (int k = 0; k < 15; k++) {
        u32 ah[2][4];
#pragma unroll
        for (int mi = 0; mi < 2; mi++) {
            u32 aadd = (u32)((wm * 32 + mi * 16 + lrow + k) * 40 + lhalf) * 2;
            ldsm_x4(ah[mi][0], ah[mi][1], ah[mi][2], ah[mi][3], sbXh + aadd);
        }
        u32 bh[2];
        ldsm_x2(bh[0], bh[1], sbWh + bbase + k * 32);
#pragma unroll
        for (int mi = 0; mi < 2; mi++) mma_bf16(acc[mi], ah[mi], bh);
    }
    __syncthreads();

    {
        float bv0 = __ldg(&bias[qc]), bv1 = __ldg(&bias[qc + 1]);
#pragma unroll
        for (int mi = 0; mi < 2; mi++) {
            int p0 = wm * 32 + mi * 16 + grp, p1 = p0 + 8;
            sF[p0 * 9 + qc]     = acc[mi][0] + bv0;
            sF[p0 * 9 + qc + 1] = acc[mi][1] + bv1;
            sF[p1 * 9 + qc]     = acc[mi][2] + bv0;
            sF[p1 * 9 + qc + 1] = acc[mi][3] + bv1;
        }
    }
    __syncthreads();

    {
        int l = t0 + tid;
        if (l < L_) {
            size_t ro = ((size_t)b * L_ + l) * 8;
            uint4 vh = *(const uint4*)(rech + ro);
            uint4 vl = *(const uint4*)(recl + ro);
            const unsigned short* hs = (const unsigned short*)&vh;
            const unsigned short* ls = (const unsigned short*)&vl;
            float resid[8];
#pragma unroll
            for (int c = 0; c < 8; c++) {
                float rv = __bfloat162float(__ushort_as_bfloat16(hs[c]))
                         + __bfloat162float(__ushort_as_bfloat16(ls[c]));
                resid[c] = rv + sF[tid * 9 + c];
            }
#pragma unroll
            for (int o = 0; o < 8; o++) {
                float v = __ldg(&pb[o]);
#pragma unroll
                for (int c = 0; c < 8; c++)
                    v += __ldg(&pw[o * C_ + c]) * resid[c];
                out[((size_t)b * C_ + o) * L_ + l] = v;
            }
        }
    }
}

// ---------------- launcher ----------------
extern "C" void kernel_launch(void* const* d_in, const int* in_sizes, int n_in,
                              void* d_out, int out_size)
{
    const float* X   = (const float*)d_in[0];
    const float* W1  = (const float*)d_in[1];
    const float* b1  = (const float*)d_in[2];
    const float* W2  = (const float*)d_in[3];
    const float* b2  = (const float*)d_in[4];
    const float* rw1 = (const float*)d_in[5];
    const float* rb1 = (const float*)d_in[6];
    const float* rw2 = (const float*)d_in[7];
    const float* rb2 = (const float*)d_in[8];
    const float* rw3 = (const float*)d_in[9];
    const float* rb3 = (const float*)d_in[10];
    const float* pw  = (const float*)d_in[11];
    const float* pb  = (const float*)d_in[12];
    float* out = (float*)d_out;

    f16 *pHh, *pHl, *pW1t, *pW2t;
    bf16 *pRech, *pRecl, *pR1h, *pR2h;
    bf16 *pCw1h, *pW2h, *pCw3h;
    float *pPatches;
    cudaGetSymbolAddress((void**)&pHh,   g_Hh);
    cudaGetSymbolAddress((void**)&pHl,   g_Hl);
    cudaGetSymbolAddress((void**)&pW1t,  g_W1t);
    cudaGetSymbolAddress((void**)&pW2t,  g_W2t);
    cudaGetSymbolAddress((void**)&pPatches, g_patches);
    cudaGetSymbolAddress((void**)&pRech, g_rech);
    cudaGetSymbolAddress((void**)&pRecl, g_recl);
    cudaGetSymbolAddress((void**)&pR1h,  g_r1h);
    cudaGetSymbolAddress((void**)&pR2h,  g_r2h);
    cudaGetSymbolAddress((void**)&pCw1h, g_cw1h);
    cudaGetSymbolAddress((void**)&pW2h,  g_w2h);
    cudaGetSymbolAddress((void**)&pCw3h, g_cw3h);

    cudaFuncSetAttribute(gemm_hmma<true,  true>,
                         cudaFuncAttributeMaxDynamicSharedMemorySize, GEMM_SMEM);
    cudaFuncSetAttribute(gemm_hmma<false, false>,
                         cudaFuncAttributeMaxDynamicSharedMemorySize, GEMM_SMEM);
    cudaFuncSetAttribute(conv1_hmma, cudaFuncAttributeMaxDynamicSharedMemorySize, C1SM);
    cudaFuncSetAttribute(conv2_hmma, cudaFuncAttributeMaxDynamicSharedMemorySize, C2SM);
    cudaFuncSetAttribute(conv3_hmma, cudaFuncAttributeMaxDynamicSharedMemorySize, C3SM);

    const int convGrid = (L_ + 255) / 256;   // 8

    // order: GEMM1 stays in ncu capture slot (#4)
    transp_f16_kernel<<<(512*512 + 255) / 256, 256>>>(W1, pW1t, 512, 512, 512);  // 1
    transp_f16_kernel<<<(256*512 + 255) / 256, 256>>>(W2, pW2t, 512, 200, 256);  // 2
    w1c_prep_kernel<<<(32*128 + 255) / 256, 256>>>(rw1, pCw1h);                  // 3

    // 4: GEMM1 -- Hh/Hl = split_f16(GELU(X @ W1 + b1)), fp32-split fused in loader
    gemm_hmma<true, true><<<dim3(8, M_ / 128), 256, GEMM_SMEM>>>(
        X, nullptr, nullptr, pW1t, b1, 512, pHh, pHl, nullptr);

    w2_prep_kernel<<<(16*480 + 255) / 256, 256>>>(rw2, pW2h);                    // 5
    w3c_prep_kernel<<<(8*240 + 255) / 256, 256>>>(rw3, pCw3h);                   // 6

    // 7: GEMM2 -- patches = H @ W2 + b2
    gemm_hmma<false, false><<<dim3(4, M_ / 128), 256, GEMM_SMEM>>>(
        nullptr, pHh, pHl, pW2t, b2, 200, nullptr, nullptr, pPatches);

    // 8: overlap-add -> rec (bf16 hi/lo: residual path keeps full precision)
    overlap_add_v3<<<dim3((L_ + 255) / 256, B_), 256>>>(pPatches, pRech, pRecl);

    // 9-11: single-bf16 convs
    conv1_hmma<<<dim3(convGrid, B_), 256, C1SM>>>(pRech, pCw1h, rb1, pR1h);
    conv2_hmma<<<dim3(convGrid, B_), 256, C2SM>>>(pR1h, pW2h, rb2, pR2h);
    conv3_hmma<<<dim3(convGrid, B_), 256, C3SM>>>(pR2h, pCw3h, rb3,
                                                  pRech, pRecl, pw, pb, out);
}

// round 15
// speedup vs baseline: 1.7968x; 1.2092x over previous
#include <cuda_runtime.h>
#include <cuda_bf16.h>
#include <cuda_fp16.h>
#include <math.h>
#include <stdint.h>

#define B_      1024
#define P_      11
#define C_      8
#define H_      512
#define T_      200
#define L_      2000
#define STRIDE_ 180
#define M_      (B_*P_*C_)

typedef unsigned long long u64;
typedef unsigned int u32;
typedef __nv_bfloat16 bf16;
typedef __half f16;

// ---------------- scratch (device globals) ----------------
__device__ f16 g_H[(size_t)M_ * 512];     // single fp16 now
__device__ f16 g_W1t[512 * 512];
__device__ f16 g_W2t[256 * 512];
__device__ float g_patches[(size_t)M_ * T_];
__device__ bf16 g_rech[(size_t)B_ * L_ * 8];
__device__ bf16 g_recl[(size_t)B_ * L_ * 8];
__device__ bf16 g_r1h[(size_t)B_ * L_ * 32];
__device__ bf16 g_r2h[(size_t)B_ * L_ * 16];
__device__ bf16 g_cw1h[32 * 128];
__device__ bf16 g_w2h[16 * 480];
__device__ bf16 g_cw3h[8 * 240];

__device__ __forceinline__ float gelu_erf(float x) {
    return 0.5f * x * (1.0f + erff(x * 0.7071067811865476f));
}

// ---------------- warp MMA primitives ----------------
__device__ __forceinline__ uint32_t smem_u32(const void* p) {
    uint32_t a;
    asm("{ .reg .u64 t; cvta.to.shared.u64 t, %1; cvt.u32.u64 %0, t; }" : "=r"(a) : "l"(p));
    return a;
}
__device__ __forceinline__ void ldsm_x4(u32& r0, u32& r1, u32& r2, u32& r3, u32 addr) {
    asm volatile("ldmatrix.sync.aligned.m8n8.x4.shared.b16 {%0,%1,%2,%3}, [%4];"
        : "=r"(r0), "=r"(r1), "=r"(r2), "=r"(r3) : "r"(addr));
}
__device__ __forceinline__ void ldsm_x2(u32& r0, u32& r1, u32 addr) {
    asm volatile("ldmatrix.sync.aligned.m8n8.x2.shared.b16 {%0,%1}, [%2];"
        : "=r"(r0), "=r"(r1) : "r"(addr));
}
__device__ __forceinline__ void mma_bf16(float* d, const u32* a, const u32* b) {
    asm volatile("mma.sync.aligned.m16n8k16.row.col.f32.bf16.bf16.f32 "
        "{%0,%1,%2,%3}, {%4,%5,%6,%7}, {%8,%9}, {%0,%1,%2,%3};"
        : "+f"(d[0]), "+f"(d[1]), "+f"(d[2]), "+f"(d[3])
        : "r"(a[0]), "r"(a[1]), "r"(a[2]), "r"(a[3]), "r"(b[0]), "r"(b[1]));
}
__device__ __forceinline__ void mma_f16(float* d, const u32* a, const u32* b) {
    asm volatile("mma.sync.aligned.m16n8k16.row.col.f32.f16.f16.f32 "
        "{%0,%1,%2,%3}, {%4,%5,%6,%7}, {%8,%9}, {%0,%1,%2,%3};"
        : "+f"(d[0]), "+f"(d[1]), "+f"(d[2]), "+f"(d[3])
        : "r"(a[0]), "r"(a[1]), "r"(a[2]), "r"(a[3]), "r"(b[0]), "r"(b[1]));
}
__device__ __forceinline__ void split_bf16(float v, bf16& h, bf16& l) {
    h = __float2bfloat16(v);
    l = __float2bfloat16(v - __bfloat162float(h));
}

// ================= prep kernels (weights only) =================
__global__ void transp_f16_kernel(const float* __restrict__ W,
                                  f16* __restrict__ t,
                                  int Kdim, int Nsrc, int Npad)
{
    int idx = blockIdx.x * 256 + threadIdx.x;
    if (idx >= Npad * Kdim) return;
    int n = idx / Kdim, k = idx - n * Kdim;
    float f = (n < Nsrc) ? W[(size_t)k * Nsrc + n] : 0.0f;
    t[idx] = __float2half(f);
}

__global__ void w1c_prep_kernel(const float* __restrict__ w, bf16* __restrict__ wh)
{
    int idx = blockIdx.x * 256 + threadIdx.x;
    if (idx >= 32 * 128) return;
    int co = idx >> 7, c = idx & 127;
    int ks = c >> 4, rem = c & 15;
    int tap = 2 * ks + (rem >> 3);
    int ic = rem & 7;
    float f = (tap < 15) ? w[((size_t)co * 8 + ic) * 15 + tap] : 0.0f;
    wh[idx] = __float2bfloat16(f);
}

__global__ void w2_prep_kernel(const float* __restrict__ w, bf16* __restrict__ wh)
{
    int idx = blockIdx.x * 256 + threadIdx.x;
    if (idx >= 16 * 480) return;
    int co = idx / 480, c = idx - co * 480;
    int k = c >> 5, ic = c & 31;
    wh[idx] = __float2bfloat16(w[((size_t)co * 32 + ic) * 15 + k]);
}

__global__ void w3c_prep_kernel(const float* __restrict__ w, bf16* __restrict__ wh)
{
    int idx = blockIdx.x * 256 + threadIdx.x;
    if (idx >= 8 * 240) return;
    int co = idx / 240, c = idx - co * 240;
    int k = c >> 4, ic = c & 15;
    wh[idx] = __float2bfloat16(w[((size_t)co * 16 + ic) * 15 + k]);
}

// ================= single-fp16 GEMM: 128x64 block, dbuf =================
#define ASTR 40
#define A_ELE (128 * ASTR)
#define B_ELE (64 * ASTR)
#define GEMM_SMEM ((2 * A_ELE + 2 * B_ELE) * 2)   // 30720 bytes

template<bool A_FP32, bool GELU_STORE>
__global__ void __launch_bounds__(256, 2) gemm_hmma(
    const float* __restrict__ Af,
    const f16* __restrict__ Ax,
    const f16* __restrict__ Bt,
    const float* __restrict__ bias, int Nvalid,
    f16* __restrict__ outH, float* __restrict__ outF)
{
    extern __shared__ __align__(16) char dynsm[];
    f16* sA = (f16*)dynsm;
    f16* sB = sA + 2 * A_ELE;

    const int tid  = threadIdx.x;
    const int lane = tid & 31;
    const int wid  = tid >> 5;
    const int wm   = wid & 3;
    const int wn   = wid >> 2;
    const int bm   = blockIdx.y * 128;
    const int bn   = blockIdx.x * 64;

    float acc[2][4][4];
#pragma unroll
    for (int i = 0; i < 2; i++)
#pragma unroll
        for (int j = 0; j < 4; j++)
#pragma unroll
            for (int q = 0; q < 4; q++) acc[i][j][q] = 0.0f;

    const int ar = tid >> 2;
    const int aq = (tid & 3) * 8;
    const size_t gA0 = (size_t)(bm + ar) * 512 + aq;
    const size_t gA1 = (size_t)(bm + ar + 64) * 512 + aq;
    const size_t gB0 = (size_t)(bn + ar) * 512 + aq;

    const u32 sbA = smem_u32(sA);
    const u32 sbB = smem_u32(sB);

    const int lrow = lane & 15;
    const int lhalf = (lane >> 4) * 8;
    const u32 aoffA0 = ((wm * 32 +      lrow) * ASTR + lhalf) * 2;
    const u32 aoffA1 = ((wm * 32 + 16 + lrow) * ASTR + lhalf) * 2;
    const u32 aoffB0 = ((wn * 32 +      lrow) * ASTR + lhalf) * 2;
    const u32 aoffB1 = ((wn * 32 + 16 + lrow) * ASTR + lhalf) * 2;

    uint4 pa0, pa1, pb;
    float4 fa0, fa1, fb0, fb1;

    if (A_FP32) {
        fa0 = *(const float4*)(Af + gA0); fa1 = *(const float4*)(Af + gA0 + 4);
        fb0 = *(const float4*)(Af + gA1); fb1 = *(const float4*)(Af + gA1 + 4);
    } else {
        pa0 = *(const uint4*)(Ax + gA0); pa1 = *(const uint4*)(Ax + gA1);
    }
    pb = *(const uint4*)(Bt + gB0);

    const int sA0 = ar * ASTR + aq, sA1 = (ar + 64) * ASTR + aq, sB0 = ar * ASTR + aq;

    for (int kt = 0; kt < 16; kt++) {
        const int cur = kt & 1;
        const int aBuf = cur * A_ELE, bBuf = cur * B_ELE;

        if (A_FP32) {
            float f0[8] = {fa0.x, fa0.y, fa0.z, fa0.w, fa1.x, fa1.y, fa1.z, fa1.w};
            float f1[8] = {fb0.x, fb0.y, fb0.z, fb0.w, fb1.x, fb1.y, fb1.z, fb1.w};
            unsigned short h0[8], h1[8];
#pragma unroll
            for (int j = 0; j < 8; j++) {
                h0[j] = __half_as_ushort(__float2half(f0[j]));
                h1[j] = __half_as_ushort(__float2half(f1[j]));
            }
            *(uint4*)(sA + aBuf + sA0) = *(uint4*)h0;
            *(uint4*)(sA + aBuf + sA1) = *(uint4*)h1;
        } else {
            *(uint4*)(sA + aBuf + sA0) = pa0;
            *(uint4*)(sA + aBuf + sA1) = pa1;
        }
        *(uint4*)(sB + bBuf + sB0) = pb;
        __syncthreads();

        if (kt < 15) {
            int k0 = (kt + 1) * 32;
            if (A_FP32) {
                fa0 = *(const float4*)(Af + gA0 + k0); fa1 = *(const float4*)(Af + gA0 + k0 + 4);
                fb0 = *(const float4*)(Af + gA1 + k0); fb1 = *(const float4*)(Af + gA1 + k0 + 4);
            } else {
                pa0 = *(const uint4*)(Ax + gA0 + k0); pa1 = *(const uint4*)(Ax + gA1 + k0);
            }
            pb = *(const uint4*)(Bt + gB0 + k0);
        }

        const u32 aByte = (u32)(aBuf * 2), bByte = (u32)(bBuf * 2);
#pragma unroll
        for (int kk = 0; kk < 2; kk++) {
            const u32 kadd = kk * 32;
            u32 a[2][4];
            ldsm_x4(a[0][0], a[0][1], a[0][2], a[0][3], sbA + aByte + aoffA0 + kadd);
            ldsm_x4(a[1][0], a[1][1], a[1][2], a[1][3], sbA + aByte + aoffA1 + kadd);

            u32 t0, t1, t2, t3;
            u32 b[4][2];
            ldsm_x4(t0, t1, t2, t3, sbB + bByte + aoffB0 + kadd);
            b[0][0] = t0; b[0][1] = t2; b[1][0] = t1; b[1][1] = t3;
            ldsm_x4(t0, t1, t2, t3, sbB + bByte + aoffB1 + kadd);
            b[2][0] = t0; b[2][1] = t2; b[3][0] = t1; b[3][1] = t3;

#pragma unroll
            for (int mi = 0; mi < 2; mi++)
#pragma unroll
                for (int ni = 0; ni < 4; ni++)
                    mma_f16(acc[mi][ni], a[mi], b[ni]);
        }
    }

    const int grp = lane >> 2;
    const int qc  = (lane & 3) * 2;
#pragma unroll
    for (int mi = 0; mi < 2; mi++) {
        const int r0 = bm + wm * 32 + mi * 16 + grp;
        const int r1 = r0 + 8;
#pragma unroll
        for (int ni = 0; ni < 4; ni++) {
            const int col = bn + wn * 32 + ni * 8 + qc;
            float bv0 = __ldg(&bias[col]), bv1 = __ldg(&bias[col + 1]);
            float v00 = acc[mi][ni][0] + bv0, v01 = acc[mi][ni][1] + bv1;
            float v10 = acc[mi][ni][2] + bv0, v11 = acc[mi][ni][3] + bv1;
            if (GELU_STORE) {
                v00 = gelu_erf(v00); v01 = gelu_erf(v01);
                v10 = gelu_erf(v10); v11 = gelu_erf(v11);
                size_t i0 = (size_t)r0 * 256 + (col >> 1);
                size_t i1 = (size_t)r1 * 256 + (col >> 1);
                reinterpret_cast<__half2*>(outH)[i0] =
                    __halves2half2(__float2half(v00), __float2half(v01));
                reinterpret_cast<__half2*>(outH)[i1] =
                    __halves2half2(__float2half(v10), __float2half(v11));
            } else {
                if (col < Nvalid) {
                    *(float2*)(outF + (size_t)r0 * Nvalid + col) = make_float2(v00, v01);
                    *(float2*)(outF + (size_t)r1 * Nvalid + col) = make_float2(v10, v11);
                }
            }
        }
    }
}

// ================= overlap-add -> rec bf16 split [b][l][8] =================
__global__ void overlap_add_v3(const float* __restrict__ patches,
                               bf16* __restrict__ rech, bf16* __restrict__ recl)
{
    const int b  = blockIdx.y;
    const int l  = blockIdx.x * 256 + threadIdx.x;
    if (l >= L_) return;

    int i_lo = l - (T_ - 1);
    i_lo = (i_lo > 0) ? (i_lo + STRIDE_ - 1) / STRIDE_ : 0;
    int i_hi = l / STRIDE_;
    if (i_hi > P_ - 1) i_hi = P_ - 1;

    int np = 0, pi[2], pt[2];
    float wv[2], ws = 0.0f;
    for (int i = i_lo; i <= i_hi; i++) {
        int t = l - i * STRIDE_;
        float w;
        if (t < 50)        w = (float)t * (1.0f / 49.0f);
        else if (t >= 150) w = (float)(199 - t) * (1.0f / 49.0f);
        else               w = 1.0f;
        pi[np] = i; pt[np] = t; wv[np] = w; ws += w; np++;
    }
    float ews = fmaxf(ws, 1e-8f);

    unsigned short hh[8], ll[8];
#pragma unroll
    for (int c = 0; c < 8; c++) {
        float v = 0.0f;
        for (int j = 0; j < np; j++)
            v += patches[(((size_t)b * P_ + pi[j]) * C_ + c) * T_ + pt[j]] * wv[j];
        v = v / ews;
        bf16 h, lo; split_bf16(v, h, lo);
        hh[c] = __bfloat16_as_ushort(h);
        ll[c] = __bfloat16_as_ushort(lo);
    }
    size_t o = ((size_t)b * L_ + l) * 8;
    *(uint4*)(rech + o) = *(uint4*)hh;
    *(uint4*)(recl + o) = *(uint4*)ll;
}

// ================= conv1: 8->32 k15, single-bf16 HMMA =================
#define C1ROWS 271
#define C1SM (C1ROWS * 40 * 2 + 32 * 136 * 2)
__global__ void __launch_bounds__(256) conv1_hmma(
    const bf16* __restrict__ rech,
    const bf16* __restrict__ wh,
    const float* __restrict__ bias,
    bf16* __restrict__ r1h)
{
    extern __shared__ __align__(16) char dsm1[];
    bf16* sXh = (bf16*)dsm1;
    bf16* sWh = sXh + C1ROWS * 40;

    const int tid  = threadIdx.x;
    const int lane = tid & 31;
    const int wm   = tid >> 5;
    const int b    = blockIdx.y;
    const int t0   = blockIdx.x * 256;

    for (int i = tid; i < 32 * 64; i += 256) {
        int r = i >> 6, q = i & 63;
        ((u32*)sWh)[r * 68 + q] = ((const u32*)wh)[r * 64 + q];
    }
    for (int i = tid; i < C1ROWS * 2; i += 256) {
        int r = i >> 1, half = i & 1;
        int gp = t0 + r - 7 + half;
        uint4 vh = make_uint4(0,0,0,0);
        if (gp >= 0 && gp < L_) {
            size_t o = ((size_t)b * L_ + gp) * 8;
            vh = *(const uint4*)(rech + o);
        }
        *(uint4*)(sXh + r * 40 + half * 8) = vh;
    }
    __syncthreads();

    const u32 sbXh = smem_u32(sXh);
    const u32 sbWh = smem_u32(sWh);
    const int lrow = lane & 15;
    const int lhalf = (lane >> 4) * 8;
    const int grp = lane >> 2, qc = (lane & 3) * 2;

    float acc[2][4][4];
#pragma unroll
    for (int mi = 0; mi < 2; mi++)
#pragma unroll
        for (int ni = 0; ni < 4; ni++)
#pragma unroll
            for (int q = 0; q < 4; q++) acc[mi][ni][q] = 0.0f;

#pragma unroll
    for (int k = 0; k < 8; k++) {
        u32 ah[2][4];
#pragma unroll
        for (int mi = 0; mi < 2; mi++) {
            u32 aadd = (u32)((wm * 32 + mi * 16 + lrow + 2 * k) * 40 + lhalf) * 2;
            ldsm_x4(ah[mi][0], ah[mi][1], ah[mi][2], ah[mi][3], sbXh + aadd);
        }
        u32 t0r, t1r, t2r, t3r;
        u32 bh[4][2];
#pragma unroll
        for (int na2 = 0; na2 < 2; na2++) {
            u32 badd = (u32)((na2 * 16 + lrow) * 136 + k * 16 + lhalf) * 2;
            ldsm_x4(t0r, t1r, t2r, t3r, sbWh + badd);
            bh[na2*2][0] = t0r; bh[na2*2][1] = t2r;
            bh[na2*2+1][0] = t1r; bh[na2*2+1][1] = t3r;
        }
#pragma unroll
        for (int mi = 0; mi < 2; mi++)
#pragma unroll
            for (int ni = 0; ni < 4; ni++)
                mma_bf16(acc[mi][ni], ah[mi], bh[ni]);
    }
    __syncthreads();

    u32* stgh = (u32*)sXh;
#pragma unroll
    for (int mi = 0; mi < 2; mi++)
#pragma unroll
        for (int ni = 0; ni < 4; ni++) {
            int ch = ni * 8 + qc;
            float bv0 = __ldg(&bias[ch]), bv1 = __ldg(&bias[ch + 1]);
            int p0 = wm * 32 + mi * 16 + grp, p1 = p0 + 8;
            float v00 = gelu_erf(acc[mi][ni][0] + bv0), v01 = gelu_erf(acc[mi][ni][1] + bv1);
            float v10 = gelu_erf(acc[mi][ni][2] + bv0), v11 = gelu_erf(acc[mi][ni][3] + bv1);
            __nv_bfloat162 th = __halves2bfloat162(__float2bfloat16(v00), __float2bfloat16(v01));
            stgh[p0 * 17 + ni * 4 + (lane & 3)] = *(u32*)&th;
            th = __halves2bfloat162(__float2bfloat16(v10), __float2bfloat16(v11));
            stgh[p1 * 17 + ni * 4 + (lane & 3)] = *(u32*)&th;
        }
    __syncthreads();
    for (int i = tid; i < 256 * 16; i += 256) {
        int p = i >> 4, q = i & 15;
        int l = t0 + p;
        if (l < L_)
            ((u32*)r1h)[((size_t)b * L_ + l) * 16 + q] = stgh[p * 17 + q];
    }
}

// ================= conv2: 32->16 k15, single-bf16 HMMA =================
#define C2ROWS 272
#define C2SM (C2ROWS * 40 * 2 + 16 * 488 * 2)
__global__ void __launch_bounds__(256) conv2_hmma(
    const bf16* __restrict__ r1h,
    const bf16* __restrict__ wh,
    const float* __restrict__ bias,
    bf16* __restrict__ r2h)
{
    extern __shared__ __align__(16) char dsm2[];
    bf16* sXh = (bf16*)dsm2;
    bf16* sWh = sXh + C2ROWS * 40;

    const int tid  = threadIdx.x;
    const int lane = tid & 31;
    const int wm   = tid >> 5;
    const int b    = blockIdx.y;
    const int t0   = blockIdx.x * 256;

    for (int i = tid; i < 16 * 240; i += 256) {
        int r = i / 240, c = i - r * 240;
        ((u32*)sWh)[r * 244 + c] = ((const u32*)wh)[r * 240 + c];
    }
    for (int i = tid; i < C2ROWS * 4; i += 256) {
        int r = i >> 2, q = i & 3;
        int gp = t0 + r - 7;
        uint4 vh = make_uint4(0,0,0,0);
        if (gp >= 0 && gp < L_) {
            size_t o = ((size_t)b * L_ + gp) * 32 + q * 8;
            vh = *(const uint4*)(r1h + o);
        }
        *(uint4*)(sXh + r * 40 + q * 8) = vh;
    }
    __syncthreads();

    const u32 sbXh = smem_u32(sXh);
    const u32 sbWh = smem_u32(sWh);
    const int lrow = lane & 15;
    const int lhalf = (lane >> 4) * 8;
    const u32 boff = sbWh + ((lane & 15) * 488 + lhalf) * 2;
    const int grp = lane >> 2, qc = (lane & 3) * 2;

    float acc[2][2][4];
#pragma unroll
    for (int mi = 0; mi < 2; mi++)
#pragma unroll
        for (int ni = 0; ni < 2; ni++)
#pragma unroll
            for (int q = 0; q < 4; q++) acc[mi][ni][q] = 0.0f;

#pragma unroll 2
    for (int ks = 0; ks < 30; ks++) {
        const int k   = ks >> 1;
        const int icb = (ks & 1) * 16;
        u32 ah[2][4];
#pragma unroll
        for (int mi = 0; mi < 2; mi++) {
            u32 aadd = (u32)((wm * 32 + mi * 16 + lrow + k) * 40 + icb + lhalf) * 2;
            ldsm_x4(ah[mi][0], ah[mi][1], ah[mi][2], ah[mi][3], sbXh + aadd);
        }
        u32 t0r, t1r, t2r, t3r;
        u32 bh[2][2];
        ldsm_x4(t0r, t1r, t2r, t3r, boff + ks * 32);
        bh[0][0] = t0r; bh[0][1] = t2r; bh[1][0] = t1r; bh[1][1] = t3r;

#pragma unroll
        for (int mi = 0; mi < 2; mi++)
#pragma unroll
            for (int ni = 0; ni < 2; ni++)
                mma_bf16(acc[mi][ni], ah[mi], bh[ni]);
    }
    __syncthreads();

    u32* stgh = (u32*)sXh;
#pragma unroll
    for (int mi = 0; mi < 2; mi++)
#pragma unroll
        for (int ni = 0; ni < 2; ni++) {
            int ch = ni * 8 + qc;
            float bv0 = __ldg(&bias[ch]), bv1 = __ldg(&bias[ch + 1]);
            int p0 = wm * 32 + mi * 16 + grp, p1 = p0 + 8;
            float v00 = gelu_erf(acc[mi][ni][0] + bv0), v01 = gelu_erf(acc[mi][ni][1] + bv1);
            float v10 = gelu_erf(acc[mi][ni][2] + bv0), v11 = gelu_erf(acc[mi][ni][3] + bv1);
            __nv_bfloat162 th = __halves2bfloat162(__float2bfloat16(v00), __float2bfloat16(v01));
            stgh[p0 * 9 + ni * 4 + (lane & 3)] = *(u32*)&th;
            th = __halves2bfloat162(__float2bfloat16(v10), __float2bfloat16(v11));
            stgh[p1 * 9 + ni * 4 + (lane & 3)] = *(u32*)&th;
        }
    __syncthreads();
    for (int i = tid; i < 256 * 8; i += 256) {
        int p = i >> 3, q = i & 7;
        int l = t0 + p;
        if (l < L_)
            ((u32*)r2h)[((size_t)b * L_ + l) * 8 + q] = stgh[p * 9 + q];
    }
}

// ================= conv3: 16->8 k15 single-bf16 + residual + pointwise =================
#define C3ROWS 271
#define C3SM (C3ROWS * 40 * 2 + 8 * 248 * 2 + 256 * 9 * 4)
__global__ void __launch_bounds__(256) conv3_hmma(
    const bf16* __restrict__ r2h,
    const bf16* __restrict__ wh,
    const float* __restrict__ bias,
    const bf16* __restrict__ rech, const bf16* __restrict__ recl,
    const float* __restrict__ pw, const float* __restrict__ pb,
    float* __restrict__ out)
{
    extern __shared__ __align__(16) char dsm3[];
    bf16* sXh = (bf16*)dsm3;
    bf16* sWh = sXh + C3ROWS * 40;
    float* sF = (float*)(sWh + 8 * 248);

    const int tid  = threadIdx.x;
    const int lane = tid & 31;
    const int wm   = tid >> 5;
    const int b    = blockIdx.y;
    const int t0   = blockIdx.x * 256;

    for (int i = tid; i < 8 * 120; i += 256) {
        int r = i / 120, c = i - r * 120;
        ((u32*)sWh)[r * 124 + c] = ((const u32*)wh)[r * 120 + c];
    }
    for (int i = tid; i < C3ROWS * 2; i += 256) {
        int r = i >> 1, q = i & 1;
        int gp = t0 + r - 7;
        uint4 vh = make_uint4(0,0,0,0);
        if (gp >= 0 && gp < L_) {
            size_t o = ((size_t)b * L_ + gp) * 16 + q * 8;
            vh = *(const uint4*)(r2h + o);
        }
        *(uint4*)(sXh + r * 40 + q * 8) = vh;
    }
    __syncthreads();

    const u32 sbXh = smem_u32(sXh);
    const u32 sbWh = smem_u32(sWh);
    const int lrow = lane & 15;
    const int lhalf = (lane >> 4) * 8;
    const u32 bbase = ((lane & 7) * 248 + ((lane >> 3) & 1) * 8) * 2;
    const int grp = lane >> 2, qc = (lane & 3) * 2;

    float acc[2][4];
#pragma unroll
    for (int mi = 0; mi < 2; mi++)
#pragma unroll
        for (int q = 0; q < 4; q++) acc[mi][q] = 0.0f;

#pragma unroll
    for (int k = 0; k < 15; k++) {
        u32 ah[2][4];
#pragma unroll
        for (int mi = 0; mi < 2; mi++) {
            u32 aadd = (u32)((wm * 32 + mi * 16 + lrow + k) * 40 + lhalf) * 2;
            ldsm_x4(ah[mi][0], ah[mi][1], ah[mi][2], ah[mi][3], sbXh + aadd);
        }
        u32 bh[2];
        ldsm_x2(bh[0], bh[1], sbWh + bbase + k * 32);
#pragma unroll
        for (int mi = 0; mi < 2; mi++) mma_bf16(acc[mi], ah[mi], bh);
    }
    __syncthreads();

    {
        float bv0 = __ldg(&bias[qc]), bv1 = __ldg(&bias[qc + 1]);
#pragma unroll
        for (int mi = 0; mi < 2; mi++) {
            int p0 = wm * 32 + mi * 16 + grp, p1 = p0 + 8;
            sF[p0 * 9 + qc]     = acc[mi][0] + bv0;
            sF[p0 * 9 + qc + 1] = acc[mi][1] + bv1;
            sF[p1 * 9 + qc]     = acc[mi][2] + bv0;
            sF[p1 * 9 + qc + 1] = acc[mi][3] + bv1;
        }
    }
    __syncthreads();

    {
        int l = t0 + tid;
        if (l < L_) {
            size_t ro = ((size_t)b * L_ + l) * 8;
            uint4 vh = *(const uint4*)(rech + ro);
            uint4 vl = *(const uint4*)(recl + ro);
            const unsigned short* hs = (const unsigned short*)&vh;
            const unsigned short* ls = (const unsigned short*)&vl;
            float resid[8];
#pragma unroll
            for (int c = 0; c < 8; c++) {
                float rv = __bfloat162float(__ushort_as_bfloat16(hs[c]))
                         + __bfloat162float(__ushort_as_bfloat16(ls[c]));
                resid[c] = rv + sF[tid * 9 + c];
            }
#pragma unroll
            for (int o = 0; o < 8; o++) {
                float v = __ldg(&pb[o]);
#pragma unroll
                for (int c = 0; c < 8; c++)
                    v += __ldg(&pw[o * C_ + c]) * resid[c];
                out[((size_t)b * C_ + o) * L_ + l] = v;
            }
        }
    }
}

// ---------------- launcher ----------------
extern "C" void kernel_launch(void* const* d_in, const int* in_sizes, int n_in,
                              void* d_out, int out_size)
{
    const float* X   = (const float*)d_in[0];
    const float* W1  = (const float*)d_in[1];
    const float* b1  = (const float*)d_in[2];
    const float* W2  = (const float*)d_in[3];
    const float* b2  = (const float*)d_in[4];
    const float* rw1 = (const float*)d_in[5];
    const float* rb1 = (const float*)d_in[6];
    const float* rw2 = (const float*)d_in[7];
    const float* rb2 = (const float*)d_in[8];
    const float* rw3 = (const float*)d_in[9];
    const float* rb3 = (const float*)d_in[10];
    const float* pw  = (const float*)d_in[11];
    const float* pb  = (const float*)d_in[12];
    float* out = (float*)d_out;

    f16 *pH, *pW1t, *pW2t;
    bf16 *pRech, *pRecl, *pR1h, *pR2h;
    bf16 *pCw1h, *pW2h, *pCw3h;
    float *pPatches;
    cudaGetSymbolAddress((void**)&pH,    g_H);
    cudaGetSymbolAddress((void**)&pW1t,  g_W1t);
    cudaGetSymbolAddress((void**)&pW2t,  g_W2t);
    cudaGetSymbolAddress((void**)&pPatches, g_patches);
    cudaGetSymbolAddress((void**)&pRech, g_rech);
    cudaGetSymbolAddress((void**)&pRecl, g_recl);
    cudaGetSymbolAddress((void**)&pR1h,  g_r1h);
    cudaGetSymbolAddress((void**)&pR2h,  g_r2h);
    cudaGetSymbolAddress((void**)&pCw1h, g_cw1h);
    cudaGetSymbolAddress((void**)&pW2h,  g_w2h);
    cudaGetSymbolAddress((void**)&pCw3h, g_cw3h);

    cudaFuncSetAttribute(gemm_hmma<true,  true>,
                         cudaFuncAttributeMaxDynamicSharedMemorySize, GEMM_SMEM);
    cudaFuncSetAttribute(gemm_hmma<false, false>,
                         cudaFuncAttributeMaxDynamicSharedMemorySize, GEMM_SMEM);
    cudaFuncSetAttribute(conv1_hmma, cudaFuncAttributeMaxDynamicSharedMemorySize, C1SM);
    cudaFuncSetAttribute(conv2_hmma, cudaFuncAttributeMaxDynamicSharedMemorySize, C2SM);
    cudaFuncSetAttribute(conv3_hmma, cudaFuncAttributeMaxDynamicSharedMemorySize, C3SM);

    const int convGrid = (L_ + 255) / 256;   // 8

    // order: GEMM1 stays in ncu capture slot (#4)
    transp_f16_kernel<<<(512*512 + 255) / 256, 256>>>(W1, pW1t, 512, 512, 512);  // 1
    transp_f16_kernel<<<(256*512 + 255) / 256, 256>>>(W2, pW2t, 512, 200, 256);  // 2
    w1c_prep_kernel<<<(32*128 + 255) / 256, 256>>>(rw1, pCw1h);                  // 3

    // 4: GEMM1 -- H = f16(GELU(X @ W1 + b1)), fp32->fp16 fused in loader
    gemm_hmma<true, true><<<dim3(8, M_ / 128), 256, GEMM_SMEM>>>(
        X, nullptr, pW1t, b1, 512, pH, nullptr);

    w2_prep_kernel<<<(16*480 + 255) / 256, 256>>>(rw2, pW2h);                    // 5
    w3c_prep_kernel<<<(8*240 + 255) / 256, 256>>>(rw3, pCw3h);                   // 6

    // 7: GEMM2 -- patches = H @ W2 + b2
    gemm_hmma<false, false><<<dim3(4, M_ / 128), 256, GEMM_SMEM>>>(
        nullptr, pH, pW2t, b2, 200, nullptr, pPatches);

    // 8: overlap-add -> rec (bf16 hi/lo: residual path keeps full precision)
    overlap_add_v3<<<dim3((L_ + 255) / 256, B_), 256>>>(pPatches, pRech, pRecl);

    // 9-11: single-bf16 convs
    conv1_hmma<<<dim3(convGrid, B_), 256, C1SM>>>(pRech, pCw1h, rb1, pR1h);
    conv2_hmma<<<dim3(convGrid, B_), 256, C2SM>>>(pR1h, pW2h, rb2, pR2h);
    conv3_hmma<<<dim3(convGrid, B_), 256, C3SM>>>(pR2h, pCw3h, rb3,
                                                  pRech, pRecl, pw, pb, out);
}

// round 16
// speedup vs baseline: 1.8481x; 1.0286x over previous
#include <cuda_runtime.h>
#include <cuda_bf16.h>
#include <cuda_fp16.h>
#include <math.h>
#include <stdint.h>

#define B_      1024
#define P_      11
#define C_      8
#define H_      512
#define T_      200
#define L_      2000
#define STRIDE_ 180
#define M_      (B_*P_*C_)

typedef unsigned long long u64;
typedef unsigned int u32;
typedef __nv_bfloat16 bf16;
typedef __half f16;

// ---------------- scratch (device globals) ----------------
__device__ f16 g_H[(size_t)M_ * 512];
__device__ f16 g_W1t[512 * 512];
__device__ f16 g_W2t[256 * 512];
__device__ float g_patches[(size_t)M_ * T_];
__device__ bf16 g_rech[(size_t)B_ * L_ * 8];
__device__ bf16 g_recl[(size_t)B_ * L_ * 8];
__device__ bf16 g_r1h[(size_t)B_ * L_ * 32];
__device__ bf16 g_r2h[(size_t)B_ * L_ * 16];
__device__ bf16 g_cw1h[32 * 128];
__device__ bf16 g_w2h[16 * 480];
__device__ bf16 g_cw3h[8 * 240];

__device__ __forceinline__ float gelu_erf(float x) {
    return 0.5f * x * (1.0f + erff(x * 0.7071067811865476f));
}

// ---------------- warp MMA primitives ----------------
__device__ __forceinline__ uint32_t smem_u32(const void* p) {
    uint32_t a;
    asm("{ .reg .u64 t; cvta.to.shared.u64 t, %1; cvt.u32.u64 %0, t; }" : "=r"(a) : "l"(p));
    return a;
}
__device__ __forceinline__ void ldsm_x4(u32& r0, u32& r1, u32& r2, u32& r3, u32 addr) {
    asm volatile("ldmatrix.sync.aligned.m8n8.x4.shared.b16 {%0,%1,%2,%3}, [%4];"
        : "=r"(r0), "=r"(r1), "=r"(r2), "=r"(r3) : "r"(addr));
}
__device__ __forceinline__ void ldsm_x2(u32& r0, u32& r1, u32 addr) {
    asm volatile("ldmatrix.sync.aligned.m8n8.x2.shared.b16 {%0,%1}, [%2];"
        : "=r"(r0), "=r"(r1) : "r"(addr));
}
__device__ __forceinline__ void mma_bf16(float* d, const u32* a, const u32* b) {
    asm volatile("mma.sync.aligned.m16n8k16.row.col.f32.bf16.bf16.f32 "
        "{%0,%1,%2,%3}, {%4,%5,%6,%7}, {%8,%9}, {%0,%1,%2,%3};"
        : "+f"(d[0]), "+f"(d[1]), "+f"(d[2]), "+f"(d[3])
        : "r"(a[0]), "r"(a[1]), "r"(a[2]), "r"(a[3]), "r"(b[0]), "r"(b[1]));
}
__device__ __forceinline__ void mma_f16(float* d, const u32* a, const u32* b) {
    asm volatile("mma.sync.aligned.m16n8k16.row.col.f32.f16.f16.f32 "
        "{%0,%1,%2,%3}, {%4,%5,%6,%7}, {%8,%9}, {%0,%1,%2,%3};"
        : "+f"(d[0]), "+f"(d[1]), "+f"(d[2]), "+f"(d[3])
        : "r"(a[0]), "r"(a[1]), "r"(a[2]), "r"(a[3]), "r"(b[0]), "r"(b[1]));
}
__device__ __forceinline__ void split_bf16(float v, bf16& h, bf16& l) {
    h = __float2bfloat16(v);
    l = __float2bfloat16(v - __bfloat162float(h));
}

// ================= prep kernels (weights only) =================
__global__ void transp_f16_kernel(const float* __restrict__ W,
                                  f16* __restrict__ t,
                                  int Kdim, int Nsrc, int Npad)
{
    int idx = blockIdx.x * 256 + threadIdx.x;
    if (idx >= Npad * Kdim) return;
    int n = idx / Kdim, k = idx - n * Kdim;
    float f = (n < Nsrc) ? W[(size_t)k * Nsrc + n] : 0.0f;
    t[idx] = __float2half(f);
}

__global__ void w1c_prep_kernel(const float* __restrict__ w, bf16* __restrict__ wh)
{
    int idx = blockIdx.x * 256 + threadIdx.x;
    if (idx >= 32 * 128) return;
    int co = idx >> 7, c = idx & 127;
    int ks = c >> 4, rem = c & 15;
    int tap = 2 * ks + (rem >> 3);
    int ic = rem & 7;
    float f = (tap < 15) ? w[((size_t)co * 8 + ic) * 15 + tap] : 0.0f;
    wh[idx] = __float2bfloat16(f);
}

__global__ void w2_prep_kernel(const float* __restrict__ w, bf16* __restrict__ wh)
{
    int idx = blockIdx.x * 256 + threadIdx.x;
    if (idx >= 16 * 480) return;
    int co = idx / 480, c = idx - co * 480;
    int k = c >> 5, ic = c & 31;
    wh[idx] = __float2bfloat16(w[((size_t)co * 32 + ic) * 15 + k]);
}

__global__ void w3c_prep_kernel(const float* __restrict__ w, bf16* __restrict__ wh)
{
    int idx = blockIdx.x * 256 + threadIdx.x;
    if (idx >= 8 * 240) return;
    int co = idx / 240, c = idx - co * 240;
    int k = c >> 4, ic = c & 15;
    wh[idx] = __float2bfloat16(w[((size_t)co * 16 + ic) * 15 + k]);
}

// ================= fp16 GEMM v5: block 128x128, warp 32x64, dbuf =================
#define ASTR 40
#define A_ELE (128 * ASTR)
#define B_ELE (128 * ASTR)
#define GEMM_SMEM ((2 * A_ELE + 2 * B_ELE) * 2)   // 40960 bytes

template<bool A_FP32, bool GELU_STORE>
__global__ void __launch_bounds__(256, 2) gemm_hmma(
    const float* __restrict__ Af,
    const f16* __restrict__ Ax,
    const f16* __restrict__ Bt,
    const float* __restrict__ bias, int Nvalid,
    f16* __restrict__ outH, float* __restrict__ outF)
{
    extern __shared__ __align__(16) char dynsm[];
    f16* sA = (f16*)dynsm;
    f16* sB = sA + 2 * A_ELE;

    const int tid  = threadIdx.x;
    const int lane = tid & 31;
    const int wid  = tid >> 5;
    const int wm   = wid & 3;             // 4 m-warps (32 rows each)
    const int wn   = wid >> 2;            // 2 n-warps (64 cols each)
    const int bm   = blockIdx.y * 128;
    const int bn   = blockIdx.x * 128;

    float acc[2][8][4];
#pragma unroll
    for (int i = 0; i < 2; i++)
#pragma unroll
        for (int j = 0; j < 8; j++)
#pragma unroll
            for (int q = 0; q < 4; q++) acc[i][j][q] = 0.0f;

    // loader mapping: each thread owns one row-half (16 elements)
    const int ar = tid >> 1;              // 0..127
    const int ac = (tid & 1) * 16;        // 0 or 16
    const size_t gA = (size_t)(bm + ar) * 512 + ac;
    const size_t gB = (size_t)(bn + ar) * 512 + ac;

    const u32 sbA = smem_u32(sA);
    const u32 sbB = smem_u32(sB);

    const int lrow = lane & 15;
    const int lhalf = (lane >> 4) * 8;
    const u32 aoffA0 = ((wm * 32 +      lrow) * ASTR + lhalf) * 2;
    const u32 aoffA1 = ((wm * 32 + 16 + lrow) * ASTR + lhalf) * 2;
    u32 aoffB[4];
#pragma unroll
    for (int f = 0; f < 4; f++)
        aoffB[f] = ((wn * 64 + f * 16 + lrow) * ASTR + lhalf) * 2;

    float4 fa[4];
    uint4 pa[2], pb[2];

    if (A_FP32) {
#pragma unroll
        for (int j = 0; j < 4; j++) fa[j] = *(const float4*)(Af + gA + j * 4);
    } else {
        pa[0] = *(const uint4*)(Ax + gA); pa[1] = *(const uint4*)(Ax + gA + 8);
    }
    pb[0] = *(const uint4*)(Bt + gB); pb[1] = *(const uint4*)(Bt + gB + 8);

    const int sOff = ar * ASTR + ac;

    for (int kt = 0; kt < 16; kt++) {
        const int cur = kt & 1;
        const int aBuf = cur * A_ELE, bBuf = cur * B_ELE;

        if (A_FP32) {
            unsigned short h[16];
            const float* ff = (const float*)fa;
#pragma unroll
            for (int j = 0; j < 16; j++)
                h[j] = __half_as_ushort(__float2half(ff[j]));
            *(uint4*)(sA + aBuf + sOff)     = *(uint4*)(h);
            *(uint4*)(sA + aBuf + sOff + 8) = *(uint4*)(h + 8);
        } else {
            *(uint4*)(sA + aBuf + sOff)     = pa[0];
            *(uint4*)(sA + aBuf + sOff + 8) = pa[1];
        }
        *(uint4*)(sB + bBuf + sOff)     = pb[0];
        *(uint4*)(sB + bBuf + sOff + 8) = pb[1];
        __syncthreads();

        if (kt < 15) {
            int k0 = (kt + 1) * 32;
            if (A_FP32) {
#pragma unroll
                for (int j = 0; j < 4; j++) fa[j] = *(const float4*)(Af + gA + k0 + j * 4);
            } else {
                pa[0] = *(const uint4*)(Ax + gA + k0); pa[1] = *(const uint4*)(Ax + gA + k0 + 8);
            }
            pb[0] = *(const uint4*)(Bt + gB + k0); pb[1] = *(const uint4*)(Bt + gB + k0 + 8);
        }

        const u32 aByte = (u32)(aBuf * 2), bByte = (u32)(bBuf * 2);
#pragma unroll
        for (int kk = 0; kk < 2; kk++) {
            const u32 kadd = kk * 32;
            u32 a[2][4];
            ldsm_x4(a[0][0], a[0][1], a[0][2], a[0][3], sbA + aByte + aoffA0 + kadd);
            ldsm_x4(a[1][0], a[1][1], a[1][2], a[1][3], sbA + aByte + aoffA1 + kadd);

            u32 b[8][2];
#pragma unroll
            for (int f = 0; f < 4; f++) {
                u32 t0, t1, t2, t3;
                ldsm_x4(t0, t1, t2, t3, sbB + bByte + aoffB[f] + kadd);
                b[2*f][0] = t0; b[2*f][1] = t2;
                b[2*f+1][0] = t1; b[2*f+1][1] = t3;
            }

#pragma unroll
            for (int mi = 0; mi < 2; mi++)
#pragma unroll
                for (int ni = 0; ni < 8; ni++)
                    mma_f16(acc[mi][ni], a[mi], b[ni]);
        }
    }

    const int grp = lane >> 2;
    const int qc  = (lane & 3) * 2;
#pragma unroll
    for (int mi = 0; mi < 2; mi++) {
        const int r0 = bm + wm * 32 + mi * 16 + grp;
        const int r1 = r0 + 8;
#pragma unroll
        for (int ni = 0; ni < 8; ni++) {
            const int col = bn + wn * 64 + ni * 8 + qc;
            float bv0 = __ldg(&bias[col]), bv1 = __ldg(&bias[col + 1]);
            float v00 = acc[mi][ni][0] + bv0, v01 = acc[mi][ni][1] + bv1;
            float v10 = acc[mi][ni][2] + bv0, v11 = acc[mi][ni][3] + bv1;
            if (GELU_STORE) {
                v00 = gelu_erf(v00); v01 = gelu_erf(v01);
                v10 = gelu_erf(v10); v11 = gelu_erf(v11);
                size_t i0 = (size_t)r0 * 256 + (col >> 1);
                size_t i1 = (size_t)r1 * 256 + (col >> 1);
                reinterpret_cast<__half2*>(outH)[i0] =
                    __halves2half2(__float2half(v00), __float2half(v01));
                reinterpret_cast<__half2*>(outH)[i1] =
                    __halves2half2(__float2half(v10), __float2half(v11));
            } else {
                if (col < Nvalid) {
                    *(float2*)(outF + (size_t)r0 * Nvalid + col) = make_float2(v00, v01);
                    *(float2*)(outF + (size_t)r1 * Nvalid + col) = make_float2(v10, v11);
                }
            }
        }
    }
}

// ================= overlap-add -> rec bf16 split [b][l][8] =================
__global__ void overlap_add_v3(const float* __restrict__ patches,
                               bf16* __restrict__ rech, bf16* __restrict__ recl)
{
    const int b  = blockIdx.y;
    const int l  = blockIdx.x * 256 + threadIdx.x;
    if (l >= L_) return;

    int i_lo = l - (T_ - 1);
    i_lo = (i_lo > 0) ? (i_lo + STRIDE_ - 1) / STRIDE_ : 0;
    int i_hi = l / STRIDE_;
    if (i_hi > P_ - 1) i_hi = P_ - 1;

    int np = 0, pi[2], pt[2];
    float wv[2], ws = 0.0f;
    for (int i = i_lo; i <= i_hi; i++) {
        int t = l - i * STRIDE_;
        float w;
        if (t < 50)        w = (float)t * (1.0f / 49.0f);
        else if (t >= 150) w = (float)(199 - t) * (1.0f / 49.0f);
        else               w = 1.0f;
        pi[np] = i; pt[np] = t; wv[np] = w; ws += w; np++;
    }
    float ews = fmaxf(ws, 1e-8f);

    unsigned short hh[8], ll[8];
#pragma unroll
    for (int c = 0; c < 8; c++) {
        float v = 0.0f;
        for (int j = 0; j < np; j++)
            v += patches[(((size_t)b * P_ + pi[j]) * C_ + c) * T_ + pt[j]] * wv[j];
        v = v / ews;
        bf16 h, lo; split_bf16(v, h, lo);
        hh[c] = __bfloat16_as_ushort(h);
        ll[c] = __bfloat16_as_ushort(lo);
    }
    size_t o = ((size_t)b * L_ + l) * 8;
    *(uint4*)(rech + o) = *(uint4*)hh;
    *(uint4*)(recl + o) = *(uint4*)ll;
}

// ================= conv1: 8->32 k15, single-bf16 HMMA =================
#define C1ROWS 271
#define C1SM (C1ROWS * 40 * 2 + 32 * 136 * 2)
__global__ void __launch_bounds__(256) conv1_hmma(
    const bf16* __restrict__ rech,
    const bf16* __restrict__ wh,
    const float* __restrict__ bias,
    bf16* __restrict__ r1h)
{
    extern __shared__ __align__(16) char dsm1[];
    bf16* sXh = (bf16*)dsm1;
    bf16* sWh = sXh + C1ROWS * 40;

    const int tid  = threadIdx.x;
    const int lane = tid & 31;
    const int wm   = tid >> 5;
    const int b    = blockIdx.y;
    const int t0   = blockIdx.x * 256;

    for (int i = tid; i < 32 * 64; i += 256) {
        int r = i >> 6, q = i & 63;
        ((u32*)sWh)[r * 68 + q] = ((const u32*)wh)[r * 64 + q];
    }
    for (int i = tid; i < C1ROWS * 2; i += 256) {
        int r = i >> 1, half = i & 1;
        int gp = t0 + r - 7 + half;
        uint4 vh = make_uint4(0,0,0,0);
        if (gp >= 0 && gp < L_) {
            size_t o = ((size_t)b * L_ + gp) * 8;
            vh = *(const uint4*)(rech + o);
        }
        *(uint4*)(sXh + r * 40 + half * 8) = vh;
    }
    __syncthreads();

    const u32 sbXh = smem_u32(sXh);
    const u32 sbWh = smem_u32(sWh);
    const int lrow = lane & 15;
    const int lhalf = (lane >> 4) * 8;
    const int grp = lane >> 2, qc = (lane & 3) * 2;

    float acc[2][4][4];
#pragma unroll
    for (int mi = 0; mi < 2; mi++)
#pragma unroll
        for (int ni = 0; ni < 4; ni++)
#pragma unroll
            for (int q = 0; q < 4; q++) acc[mi][ni][q] = 0.0f;

#pragma unroll
    for (int k = 0; k < 8; k++) {
        u32 ah[2][4];
#pragma unroll
        for (int mi = 0; mi < 2; mi++) {
            u32 aadd = (u32)((wm * 32 + mi * 16 + lrow + 2 * k) * 40 + lhalf) * 2;
            ldsm_x4(ah[mi][0], ah[mi][1], ah[mi][2], ah[mi][3], sbXh + aadd);
        }
        u32 t0r, t1r, t2r, t3r;
        u32 bh[4][2];
#pragma unroll
        for (int na2 = 0; na2 < 2; na2++) {
            u32 badd = (u32)((na2 * 16 + lrow) * 136 + k * 16 + lhalf) * 2;
            ldsm_x4(t0r, t1r, t2r, t3r, sbWh + badd);
            bh[na2*2][0] = t0r; bh[na2*2][1] = t2r;
            bh[na2*2+1][0] = t1r; bh[na2*2+1][1] = t3r;
        }
#pragma unroll
        for (int mi = 0; mi < 2; mi++)
#pragma unroll
            for (int ni = 0; ni < 4; ni++)
                mma_bf16(acc[mi][ni], ah[mi], bh[ni]);
    }
    __syncthreads();

    u32* stgh = (u32*)sXh;
#pragma unroll
    for (int mi = 0; mi < 2; mi++)
#pragma unroll
        for (int ni = 0; ni < 4; ni++) {
            int ch = ni * 8 + qc;
            float bv0 = __ldg(&bias[ch]), bv1 = __ldg(&bias[ch + 1]);
            int p0 = wm * 32 + mi * 16 + grp, p1 = p0 + 8;
            float v00 = gelu_erf(acc[mi][ni][0] + bv0), v01 = gelu_erf(acc[mi][ni][1] + bv1);
            float v10 = gelu_erf(acc[mi][ni][2] + bv0), v11 = gelu_erf(acc[mi][ni][3] + bv1);
            __nv_bfloat162 th = __halves2bfloat162(__float2bfloat16(v00), __float2bfloat16(v01));
            stgh[p0 * 17 + ni * 4 + (lane & 3)] = *(u32*)&th;
            th = __halves2bfloat162(__float2bfloat16(v10), __float2bfloat16(v11));
            stgh[p1 * 17 + ni * 4 + (lane & 3)] = *(u32*)&th;
        }
    __syncthreads();
    for (int i = tid; i < 256 * 16; i += 256) {
        int p = i >> 4, q = i & 15;
        int l = t0 + p;
        if (l < L_)
            ((u32*)r1h)[((size_t)b * L_ + l) * 16 + q] = stgh[p * 17 + q];
    }
}

// ================= conv2: 32->16 k15, single-bf16 HMMA =================
#define C2ROWS 272
#define C2SM (C2ROWS * 40 * 2 + 16 * 488 * 2)
__global__ void __launch_bounds__(256) conv2_hmma(
    const bf16* __restrict__ r1h,
    const bf16* __restrict__ wh,
    const float* __restrict__ bias,
    bf16* __restrict__ r2h)
{
    extern __shared__ __align__(16) char dsm2[];
    bf16* sXh = (bf16*)dsm2;
    bf16* sWh = sXh + C2ROWS * 40;

    const int tid  = threadIdx.x;
    const int lane = tid & 31;
    const int wm   = tid >> 5;
    const int b    = blockIdx.y;
    const int t0   = blockIdx.x * 256;

    for (int i = tid; i < 16 * 240; i += 256) {
        int r = i / 240, c = i - r * 240;
        ((u32*)sWh)[r * 244 + c] = ((const u32*)wh)[r * 240 + c];
    }
    for (int i = tid; i < C2ROWS * 4; i += 256) {
        int r = i >> 2, q = i & 3;
        int gp = t0 + r - 7;
        uint4 vh = make_uint4(0,0,0,0);
        if (gp >= 0 && gp < L_) {
            size_t o = ((size_t)b * L_ + gp) * 32 + q * 8;
            vh = *(const uint4*)(r1h + o);
        }
        *(uint4*)(sXh + r * 40 + q * 8) = vh;
    }
    __syncthreads();

    const u32 sbXh = smem_u32(sXh);
    const u32 sbWh = smem_u32(sWh);
    const int lrow = lane & 15;
    const int lhalf = (lane >> 4) * 8;
    const u32 boff = sbWh + ((lane & 15) * 488 + lhalf) * 2;
    const int grp = lane >> 2, qc = (lane & 3) * 2;

    float acc[2][2][4];
#pragma unroll
    for (int mi = 0; mi < 2; mi++)
#pragma unroll
        for (int ni = 0; ni < 2; ni++)
#pragma unroll
            for (int q = 0; q < 4; q++) acc[mi][ni][q] = 0.0f;

#pragma unroll 2
    for (int ks = 0; ks < 30; ks++) {
        const int k   = ks >> 1;
        const int icb = (ks & 1) * 16;
        u32 ah[2][4];
#pragma unroll
        for (int mi = 0; mi < 2; mi++) {
            u32 aadd = (u32)((wm * 32 + mi * 16 + lrow + k) * 40 + icb + lhalf) * 2;
            ldsm_x4(ah[mi][0], ah[mi][1], ah[mi][2], ah[mi][3], sbXh + aadd);
        }
        u32 t0r, t1r, t2r, t3r;
        u32 bh[2][2];
        ldsm_x4(t0r, t1r, t2r, t3r, boff + ks * 32);
        bh[0][0] = t0r; bh[0][1] = t2r; bh[1][0] = t1r; bh[1][1] = t3r;

#pragma unroll
        for (int mi = 0; mi < 2; mi++)
#pragma unroll
            for (int ni = 0; ni < 2; ni++)
                mma_bf16(acc[mi][ni], ah[mi], bh[ni]);
    }
    __syncthreads();

    u32* stgh = (u32*)sXh;
#pragma unroll
    for (int mi = 0; mi < 2; mi++)
#pragma unroll
        for (int ni = 0; ni < 2; ni++) {
            int ch = ni * 8 + qc;
            float bv0 = __ldg(&bias[ch]), bv1 = __ldg(&bias[ch + 1]);
            int p0 = wm * 32 + mi * 16 + grp, p1 = p0 + 8;
            float v00 = gelu_erf(acc[mi][ni][0] + bv0), v01 = gelu_erf(acc[mi][ni][1] + bv1);
            float v10 = gelu_erf(acc[mi][ni][2] + bv0), v11 = gelu_erf(acc[mi][ni][3] + bv1);
            __nv_bfloat162 th = __halves2bfloat162(__float2bfloat16(v00), __float2bfloat16(v01));
            stgh[p0 * 9 + ni * 4 + (lane & 3)] = *(u32*)&th;
            th = __halves2bfloat162(__float2bfloat16(v10), __float2bfloat16(v11));
            stgh[p1 * 9 + ni * 4 + (lane & 3)] = *(u32*)&th;
        }
    __syncthreads();
    for (int i = tid; i < 256 * 8; i += 256) {
        int p = i >> 3, q = i & 7;
        int l = t0 + p;
        if (l < L_)
            ((u32*)r2h)[((size_t)b * L_ + l) * 8 + q] = stgh[p * 9 + q];
    }
}

// ================= conv3: 16->8 k15 single-bf16 + residual + pointwise =================
#define C3ROWS 271
#define C3SM (C3ROWS * 40 * 2 + 8 * 248 * 2 + 256 * 9 * 4)
__global__ void __launch_bounds__(256) conv3_hmma(
    const bf16* __restrict__ r2h,
    const bf16* __restrict__ wh,
    const float* __restrict__ bias,
    const bf16* __restrict__ rech, const bf16* __restrict__ recl,
    const float* __restrict__ pw, const float* __restrict__ pb,
    float* __restrict__ out)
{
    extern __shared__ __align__(16) char dsm3[];
    bf16* sXh = (bf16*)dsm3;
    bf16* sWh = sXh + C3ROWS * 40;
    float* sF = (float*)(sWh + 8 * 248);

    const int tid  = threadIdx.x;
    const int lane = tid & 31;
    const int wm   = tid >> 5;
    const int b    = blockIdx.y;
    const int t0   = blockIdx.x * 256;

    for (int i = tid; i < 8 * 120; i += 256) {
        int r = i / 120, c = i - r * 120;
        ((u32*)sWh)[r * 124 + c] = ((const u32*)wh)[r * 120 + c];
    }
    for (int i = tid; i < C3ROWS * 2; i += 256) {
        int r = i >> 1, q = i & 1;
        int gp = t0 + r - 7;
        uint4 vh = make_uint4(0,0,0,0);
        if (gp >= 0 && gp < L_) {
            size_t o = ((size_t)b * L_ + gp) * 16 + q * 8;
            vh = *(const uint4*)(r2h + o);
        }
        *(uint4*)(sXh + r * 40 + q * 8) = vh;
    }
    __syncthreads();

    const u32 sbXh = smem_u32(sXh);
    const u32 sbWh = smem_u32(sWh);
    const int lrow = lane & 15;
    const int lhalf = (lane >> 4) * 8;
    const u32 bbase = ((lane & 7) * 248 + ((lane >> 3) & 1) * 8) * 2;
    const int grp = lane >> 2, qc = (lane & 3) * 2;

    float acc[2][4];
#pragma unroll
    for (int mi = 0; mi < 2; mi++)
#pragma unroll
        for (int q = 0; q < 4; q++) acc[mi][q] = 0.0f;

#pragma unroll
    for (int k = 0; k < 15; k++) {
        u32 ah[2][4];
#pragma unroll
        for (int mi = 0; mi < 2; mi++) {
            u32 aadd = (u32)((wm * 32 + mi * 16 + lrow + k) * 40 + lhalf) * 2;
            ldsm_x4(ah[mi][0], ah[mi][1], ah[mi][2], ah[mi][3], sbXh + aadd);
        }
        u32 bh[2];
        ldsm_x2(bh[0], bh[1], sbWh + bbase + k * 32);
#pragma unroll
        for (int mi = 0; mi < 2; mi++) mma_bf16(acc[mi], ah[mi], bh);
    }
    __syncthreads();

    {
        float bv0 = __ldg(&bias[qc]), bv1 = __ldg(&bias[qc + 1]);
#pragma unroll
        for (int mi = 0; mi < 2; mi++) {
            int p0 = wm * 32 + mi * 16 + grp, p1 = p0 + 8;
            sF[p0 * 9 + qc]     = acc[mi][0] + bv0;
            sF[p0 * 9 + qc + 1] = acc[mi][1] + bv1;
            sF[p1 * 9 + qc]     = acc[mi][2] + bv0;
            sF[p1 * 9 + qc + 1] = acc[mi][3] + bv1;
        }
    }
    __syncthreads();

    {
        int l = t0 + tid;
        if (l < L_) {
            size_t ro = ((size_t)b * L_ + l) * 8;
            uint4 vh = *(const uint4*)(rech + ro);
            uint4 vl = *(const uint4*)(recl + ro);
            const unsigned short* hs = (const unsigned short*)&vh;
            const unsigned short* ls = (const unsigned short*)&vl;
            float resid[8];
#pragma unroll
            for (int c = 0; c < 8; c++) {
                float rv = __bfloat162float(__ushort_as_bfloat16(hs[c]))
                         + __bfloat162float(__ushort_as_bfloat16(ls[c]));
                resid[c] = rv + sF[tid * 9 + c];
            }
#pragma unroll
            for (int o = 0; o < 8; o++) {
                float v = __ldg(&pb[o]);
#pragma unroll
                for (int c = 0; c < 8; c++)
                    v += __ldg(&pw[o * C_ + c]) * resid[c];
                out[((size_t)b * C_ + o) * L_ + l] = v;
            }
        }
    }
}

// ---------------- launcher ----------------
extern "C" void kernel_launch(void* const* d_in, const int* in_sizes, int n_in,
                              void* d_out, int out_size)
{
    const float* X   = (const float*)d_in[0];
    const float* W1  = (const float*)d_in[1];
    const float* b1  = (const float*)d_in[2];
    const float* W2  = (const float*)d_in[3];
    const float* b2  = (const float*)d_in[4];
    const float* rw1 = (const float*)d_in[5];
    const float* rb1 = (const float*)d_in[6];
    const float* rw2 = (const float*)d_in[7];
    const float* rb2 = (const float*)d_in[8];
    const float* rw3 = (const float*)d_in[9];
    const float* rb3 = (const float*)d_in[10];
    const float* pw  = (const float*)d_in[11];
    const float* pb  = (const float*)d_in[12];
    float* out = (float*)d_out;

    f16 *pH, *pW1t, *pW2t;
    bf16 *pRech, *pRecl, *pR1h, *pR2h;
    bf16 *pCw1h, *pW2h, *pCw3h;
    float *pPatches;
    cudaGetSymbolAddress((void**)&pH,    g_H);
    cudaGetSymbolAddress((void**)&pW1t,  g_W1t);
    cudaGetSymbolAddress((void**)&pW2t,  g_W2t);
    cudaGetSymbolAddress((void**)&pPatches, g_patches);
    cudaGetSymbolAddress((void**)&pRech, g_rech);
    cudaGetSymbolAddress((void**)&pRecl, g_recl);
    cudaGetSymbolAddress((void**)&pR1h,  g_r1h);
    cudaGetSymbolAddress((void**)&pR2h,  g_r2h);
    cudaGetSymbolAddress((void**)&pCw1h, g_cw1h);
    cudaGetSymbolAddress((void**)&pW2h,  g_w2h);
    cudaGetSymbolAddress((void**)&pCw3h, g_cw3h);

    cudaFuncSetAttribute(gemm_hmma<true,  true>,
                         cudaFuncAttributeMaxDynamicSharedMemorySize, GEMM_SMEM);
    cudaFuncSetAttribute(gemm_hmma<false, false>,
                         cudaFuncAttributeMaxDynamicSharedMemorySize, GEMM_SMEM);
    cudaFuncSetAttribute(conv1_hmma, cudaFuncAttributeMaxDynamicSharedMemorySize, C1SM);
    cudaFuncSetAttribute(conv2_hmma, cudaFuncAttributeMaxDynamicSharedMemorySize, C2SM);
    cudaFuncSetAttribute(conv3_hmma, cudaFuncAttributeMaxDynamicSharedMemorySize, C3SM);

    const int convGrid = (L_ + 255) / 256;   // 8

    // order: GEMM1 stays in ncu capture slot (#4)
    transp_f16_kernel<<<(512*512 + 255) / 256, 256>>>(W1, pW1t, 512, 512, 512);  // 1
    transp_f16_kernel<<<(256*512 + 255) / 256, 256>>>(W2, pW2t, 512, 200, 256);  // 2
    w1c_prep_kernel<<<(32*128 + 255) / 256, 256>>>(rw1, pCw1h);                  // 3

    // 4: GEMM1 -- H = f16(GELU(X @ W1 + b1)), fp32->fp16 fused in loader
    gemm_hmma<true, true><<<dim3(4, M_ / 128), 256, GEMM_SMEM>>>(
        X, nullptr, pW1t, b1, 512, pH, nullptr);

    w2_prep_kernel<<<(16*480 + 255) / 256, 256>>>(rw2, pW2h);                    // 5
    w3c_prep_kernel<<<(8*240 + 255) / 256, 256>>>(rw3, pCw3h);                   // 6

    // 7: GEMM2 -- patches = H @ W2 + b2
    gemm_hmma<false, false><<<dim3(2, M_ / 128), 256, GEMM_SMEM>>>(
        nullptr, pH, pW2t, b2, 200, nullptr, pPatches);

    // 8: overlap-add -> rec (bf16 hi/lo: residual path keeps full precision)
    overlap_add_v3<<<dim3((L_ + 255) / 256, B_), 256>>>(pPatches, pRech, pRecl);

    // 9-11: single-bf16 convs
    conv1_hmma<<<dim3(convGrid, B_), 256, C1SM>>>(pRech, pCw1h, rb1, pR1h);
    conv2_hmma<<<dim3(convGrid, B_), 256, C2SM>>>(pR1h, pW2h, rb2, pR2h);
    conv3_hmma<<<dim3(convGrid, B_), 256, C3SM>>>(pR2h, pCw3h, rb3,
                                                  pRech, pRecl, pw, pb, out);
}

// round 17
// speedup vs baseline: 1.9540x; 1.0573x over previous
#include <cuda_runtime.h>
#include <cuda_bf16.h>
#include <cuda_fp16.h>
#include <math.h>
#include <stdint.h>

#define B_      1024
#define P_      11
#define C_      8
#define H_      512
#define T_      200
#define L_      2000
#define STRIDE_ 180
#define M_      (B_*P_*C_)

typedef unsigned long long u64;
typedef unsigned int u32;
typedef __nv_bfloat16 bf16;
typedef __half f16;

// ---------------- scratch (device globals) ----------------
__device__ f16 g_Xf[(size_t)M_ * 512];
__device__ f16 g_H[(size_t)M_ * 512];
__device__ f16 g_W1t[512 * 512];
__device__ f16 g_W2t[256 * 512];
__device__ float g_patches[(size_t)M_ * T_];
__device__ bf16 g_rech[(size_t)B_ * L_ * 8];
__device__ bf16 g_recl[(size_t)B_ * L_ * 8];
__device__ bf16 g_r1h[(size_t)B_ * L_ * 32];
__device__ bf16 g_r2h[(size_t)B_ * L_ * 16];
__device__ bf16 g_cw1h[32 * 128];
__device__ bf16 g_w2h[16 * 480];
__device__ bf16 g_cw3h[8 * 240];

__device__ __forceinline__ float gelu_erf(float x) {
    return 0.5f * x * (1.0f + erff(x * 0.7071067811865476f));
}

// ---------------- warp MMA primitives ----------------
__device__ __forceinline__ uint32_t smem_u32(const void* p) {
    uint32_t a;
    asm("{ .reg .u64 t; cvta.to.shared.u64 t, %1; cvt.u32.u64 %0, t; }" : "=r"(a) : "l"(p));
    return a;
}
__device__ __forceinline__ void ldsm_x4(u32& r0, u32& r1, u32& r2, u32& r3, u32 addr) {
    asm volatile("ldmatrix.sync.aligned.m8n8.x4.shared.b16 {%0,%1,%2,%3}, [%4];"
        : "=r"(r0), "=r"(r1), "=r"(r2), "=r"(r3) : "r"(addr));
}
__device__ __forceinline__ void ldsm_x2(u32& r0, u32& r1, u32 addr) {
    asm volatile("ldmatrix.sync.aligned.m8n8.x2.shared.b16 {%0,%1}, [%2];"
        : "=r"(r0), "=r"(r1) : "r"(addr));
}
__device__ __forceinline__ void mma_bf16(float* d, const u32* a, const u32* b) {
    asm volatile("mma.sync.aligned.m16n8k16.row.col.f32.bf16.bf16.f32 "
        "{%0,%1,%2,%3}, {%4,%5,%6,%7}, {%8,%9}, {%0,%1,%2,%3};"
        : "+f"(d[0]), "+f"(d[1]), "+f"(d[2]), "+f"(d[3])
        : "r"(a[0]), "r"(a[1]), "r"(a[2]), "r"(a[3]), "r"(b[0]), "r"(b[1]));
}
__device__ __forceinline__ void mma_f16(float* d, const u32* a, const u32* b) {
    asm volatile("mma.sync.aligned.m16n8k16.row.col.f32.f16.f16.f32 "
        "{%0,%1,%2,%3}, {%4,%5,%6,%7}, {%8,%9}, {%0,%1,%2,%3};"
        : "+f"(d[0]), "+f"(d[1]), "+f"(d[2]), "+f"(d[3])
        : "r"(a[0]), "r"(a[1]), "r"(a[2]), "r"(a[3]), "r"(b[0]), "r"(b[1]));
}
__device__ __forceinline__ void split_bf16(float v, bf16& h, bf16& l) {
    h = __float2bfloat16(v);
    l = __float2bfloat16(v - __bfloat162float(h));
}
#define CP_ASYNC16(s, g) \
    asm volatile("cp.async.cg.shared.global [%0], [%1], 16;" :: "r"(s), "l"(g))
#define CP_COMMIT() asm volatile("cp.async.commit_group;")
#define CP_WAIT0()  asm volatile("cp.async.wait_group 0;" ::: "memory")

// ================= prep kernels =================
__global__ void xf16_kernel(const float* __restrict__ x, f16* __restrict__ xf, int n8)
{
    int i = blockIdx.x * 256 + threadIdx.x;
    if (i >= n8) return;
    float4 v0 = reinterpret_cast<const float4*>(x)[2 * i];
    float4 v1 = reinterpret_cast<const float4*>(x)[2 * i + 1];
    unsigned short h[8];
    h[0] = __half_as_ushort(__float2half(v0.x));
    h[1] = __half_as_ushort(__float2half(v0.y));
    h[2] = __half_as_ushort(__float2half(v0.z));
    h[3] = __half_as_ushort(__float2half(v0.w));
    h[4] = __half_as_ushort(__float2half(v1.x));
    h[5] = __half_as_ushort(__float2half(v1.y));
    h[6] = __half_as_ushort(__float2half(v1.z));
    h[7] = __half_as_ushort(__float2half(v1.w));
    reinterpret_cast<uint4*>(xf)[i] = *(uint4*)h;
}

__global__ void transp_f16_kernel(const float* __restrict__ W,
                                  f16* __restrict__ t,
                                  int Kdim, int Nsrc, int Npad)
{
    int idx = blockIdx.x * 256 + threadIdx.x;
    if (idx >= Npad * Kdim) return;
    int n = idx / Kdim, k = idx - n * Kdim;
    float f = (n < Nsrc) ? W[(size_t)k * Nsrc + n] : 0.0f;
    t[idx] = __float2half(f);
}

__global__ void w1c_prep_kernel(const float* __restrict__ w, bf16* __restrict__ wh)
{
    int idx = blockIdx.x * 256 + threadIdx.x;
    if (idx >= 32 * 128) return;
    int co = idx >> 7, c = idx & 127;
    int ks = c >> 4, rem = c & 15;
    int tap = 2 * ks + (rem >> 3);
    int ic = rem & 7;
    float f = (tap < 15) ? w[((size_t)co * 8 + ic) * 15 + tap] : 0.0f;
    wh[idx] = __float2bfloat16(f);
}

__global__ void w2_prep_kernel(const float* __restrict__ w, bf16* __restrict__ wh)
{
    int idx = blockIdx.x * 256 + threadIdx.x;
    if (idx >= 16 * 480) return;
    int co = idx / 480, c = idx - co * 480;
    int k = c >> 5, ic = c & 31;
    wh[idx] = __float2bfloat16(w[((size_t)co * 32 + ic) * 15 + k]);
}

__global__ void w3c_prep_kernel(const float* __restrict__ w, bf16* __restrict__ wh)
{
    int idx = blockIdx.x * 256 + threadIdx.x;
    if (idx >= 8 * 240) return;
    int co = idx / 240, c = idx - co * 240;
    int k = c >> 4, ic = c & 15;
    wh[idx] = __float2bfloat16(w[((size_t)co * 16 + ic) * 15 + k]);
}

// ================= fp16 GEMM v6: block 128x128, warp 32x64, cp.async dbuf =================
#define ASTR 40
#define A_ELE (128 * ASTR)
#define B_ELE (128 * ASTR)
#define A_BYTES (A_ELE * 2)
#define B_BYTES (B_ELE * 2)
#define GEMM_SMEM ((2 * A_ELE + 2 * B_ELE) * 2)   // 40960 bytes

template<bool GELU_STORE, bool GUARD_N>
__global__ void __launch_bounds__(256, 2) gemm_hmma(
    const f16* __restrict__ Ax,
    const f16* __restrict__ Bt,
    const float* __restrict__ bias, int Nvalid,
    f16* __restrict__ outH, float* __restrict__ outF)
{
    extern __shared__ __align__(16) char dynsm[];
    f16* sA = (f16*)dynsm;
    f16* sB = sA + 2 * A_ELE;

    const int tid  = threadIdx.x;
    const int lane = tid & 31;
    const int wid  = tid >> 5;
    const int wm   = wid & 3;
    const int wn   = wid >> 2;
    const int bm   = blockIdx.y * 128;
    const int bn   = blockIdx.x * 128;

    float acc[2][8][4];
#pragma unroll
    for (int i = 0; i < 2; i++)
#pragma unroll
        for (int j = 0; j < 8; j++)
#pragma unroll
            for (int q = 0; q < 4; q++) acc[i][j][q] = 0.0f;

    const int ar = tid >> 1;              // 0..127
    const int ac = (tid & 1) * 16;        // 0 or 16
    const size_t gA = (size_t)(bm + ar) * 512 + ac;
    const size_t gB = (size_t)(bn + ar) * 512 + ac;

    const u32 sbA = smem_u32(sA);
    const u32 sbB = smem_u32(sB);
    const u32 sOffB = (u32)(ar * ASTR + ac) * 2;   // byte offset within a buffer

    const int lrow = lane & 15;
    const int lhalf = (lane >> 4) * 8;
    const u32 aoffA0 = ((wm * 32 +      lrow) * ASTR + lhalf) * 2;
    const u32 aoffA1 = ((wm * 32 + 16 + lrow) * ASTR + lhalf) * 2;
    u32 aoffB[4];
#pragma unroll
    for (int f = 0; f < 4; f++)
        aoffB[f] = ((wn * 64 + f * 16 + lrow) * ASTR + lhalf) * 2;

    // issue tile 0
    {
        CP_ASYNC16(sbA + sOffB,      Ax + gA);
        CP_ASYNC16(sbA + sOffB + 16, Ax + gA + 8);
        CP_ASYNC16(sbB + sOffB,      Bt + gB);
        CP_ASYNC16(sbB + sOffB + 16, Bt + gB + 8);
        CP_COMMIT();
    }

    for (int kt = 0; kt < 16; kt++) {
        const int cur = kt & 1;
        CP_WAIT0();
        __syncthreads();

        if (kt < 15) {
            const int nxt = cur ^ 1;
            const int k0 = (kt + 1) * 32;
            const u32 aB = (u32)(nxt * A_BYTES), bB = (u32)(nxt * B_BYTES);
            CP_ASYNC16(sbA + aB + sOffB,      Ax + gA + k0);
            CP_ASYNC16(sbA + aB + sOffB + 16, Ax + gA + k0 + 8);
            CP_ASYNC16(sbB + bB + sOffB,      Bt + gB + k0);
            CP_ASYNC16(sbB + bB + sOffB + 16, Bt + gB + k0 + 8);
            CP_COMMIT();
        }

        const u32 aByte = (u32)(cur * A_BYTES), bByte = (u32)(cur * B_BYTES);
#pragma unroll
        for (int kk = 0; kk < 2; kk++) {
            const u32 kadd = kk * 32;
            u32 a[2][4];
            ldsm_x4(a[0][0], a[0][1], a[0][2], a[0][3], sbA + aByte + aoffA0 + kadd);
            ldsm_x4(a[1][0], a[1][1], a[1][2], a[1][3], sbA + aByte + aoffA1 + kadd);

            u32 b[8][2];
#pragma unroll
            for (int f = 0; f < 4; f++) {
                if (GUARD_N && bn + wn * 64 + f * 16 >= Nvalid) continue;
                u32 t0, t1, t2, t3;
                ldsm_x4(t0, t1, t2, t3, sbB + bByte + aoffB[f] + kadd);
                b[2*f][0] = t0; b[2*f][1] = t2;
                b[2*f+1][0] = t1; b[2*f+1][1] = t3;
            }

#pragma unroll
            for (int mi = 0; mi < 2; mi++)
#pragma unroll
                for (int ni = 0; ni < 8; ni++) {
                    if (GUARD_N && bn + wn * 64 + ni * 8 >= Nvalid) continue;
                    mma_f16(acc[mi][ni], a[mi], b[ni]);
                }
        }
        __syncthreads();   // reads of buf[cur] complete before next overwrite
    }

    const int grp = lane >> 2;
    const int qc  = (lane & 3) * 2;
#pragma unroll
    for (int mi = 0; mi < 2; mi++) {
        const int r0 = bm + wm * 32 + mi * 16 + grp;
        const int r1 = r0 + 8;
#pragma unroll
        for (int ni = 0; ni < 8; ni++) {
            const int col = bn + wn * 64 + ni * 8 + qc;
            if (GUARD_N && col >= Nvalid) continue;
            float bv0 = __ldg(&bias[col]), bv1 = __ldg(&bias[col + 1]);
            float v00 = acc[mi][ni][0] + bv0, v01 = acc[mi][ni][1] + bv1;
            float v10 = acc[mi][ni][2] + bv0, v11 = acc[mi][ni][3] + bv1;
            if (GELU_STORE) {
                v00 = gelu_erf(v00); v01 = gelu_erf(v01);
                v10 = gelu_erf(v10); v11 = gelu_erf(v11);
                size_t i0 = (size_t)r0 * 256 + (col >> 1);
                size_t i1 = (size_t)r1 * 256 + (col >> 1);
                reinterpret_cast<__half2*>(outH)[i0] =
                    __halves2half2(__float2half(v00), __float2half(v01));
                reinterpret_cast<__half2*>(outH)[i1] =
                    __halves2half2(__float2half(v10), __float2half(v11));
            } else {
                *(float2*)(outF + (size_t)r0 * Nvalid + col) = make_float2(v00, v01);
                *(float2*)(outF + (size_t)r1 * Nvalid + col) = make_float2(v10, v11);
            }
        }
    }
}

// ================= overlap-add -> rec bf16 split [b][l][8] =================
__global__ void overlap_add_v3(const float* __restrict__ patches,
                               bf16* __restrict__ rech, bf16* __restrict__ recl)
{
    const int b  = blockIdx.y;
    const int l  = blockIdx.x * 256 + threadIdx.x;
    if (l >= L_) return;

    int i_lo = l - (T_ - 1);
    i_lo = (i_lo > 0) ? (i_lo + STRIDE_ - 1) / STRIDE_ : 0;
    int i_hi = l / STRIDE_;
    if (i_hi > P_ - 1) i_hi = P_ - 1;

    int np = 0, pi[2], pt[2];
    float wv[2], ws = 0.0f;
    for (int i = i_lo; i <= i_hi; i++) {
        int t = l - i * STRIDE_;
        float w;
        if (t < 50)        w = (float)t * (1.0f / 49.0f);
        else if (t >= 150) w = (float)(199 - t) * (1.0f / 49.0f);
        else               w = 1.0f;
        pi[np] = i; pt[np] = t; wv[np] = w; ws += w; np++;
    }
    float ews = fmaxf(ws, 1e-8f);

    unsigned short hh[8], ll[8];
#pragma unroll
    for (int c = 0; c < 8; c++) {
        float v = 0.0f;
        for (int j = 0; j < np; j++)
            v += patches[(((size_t)b * P_ + pi[j]) * C_ + c) * T_ + pt[j]] * wv[j];
        v = v / ews;
        bf16 h, lo; split_bf16(v, h, lo);
        hh[c] = __bfloat16_as_ushort(h);
        ll[c] = __bfloat16_as_ushort(lo);
    }
    size_t o = ((size_t)b * L_ + l) * 8;
    *(uint4*)(rech + o) = *(uint4*)hh;
    *(uint4*)(recl + o) = *(uint4*)ll;
}

// ================= conv1: 8->32 k15, single-bf16 HMMA =================
#define C1ROWS 271
#define C1SM (C1ROWS * 40 * 2 + 32 * 136 * 2)
__global__ void __launch_bounds__(256) conv1_hmma(
    const bf16* __restrict__ rech,
    const bf16* __restrict__ wh,
    const float* __restrict__ bias,
    bf16* __restrict__ r1h)
{
    extern __shared__ __align__(16) char dsm1[];
    bf16* sXh = (bf16*)dsm1;
    bf16* sWh = sXh + C1ROWS * 40;

    const int tid  = threadIdx.x;
    const int lane = tid & 31;
    const int wm   = tid >> 5;
    const int b    = blockIdx.y;
    const int t0   = blockIdx.x * 256;

    for (int i = tid; i < 32 * 64; i += 256) {
        int r = i >> 6, q = i & 63;
        ((u32*)sWh)[r * 68 + q] = ((const u32*)wh)[r * 64 + q];
    }
    for (int i = tid; i < C1ROWS * 2; i += 256) {
        int r = i >> 1, half = i & 1;
        int gp = t0 + r - 7 + half;
        uint4 vh = make_uint4(0,0,0,0);
        if (gp >= 0 && gp < L_) {
            size_t o = ((size_t)b * L_ + gp) * 8;
            vh = *(const uint4*)(rech + o);
        }
        *(uint4*)(sXh + r * 40 + half * 8) = vh;
    }
    __syncthreads();

    const u32 sbXh = smem_u32(sXh);
    const u32 sbWh = smem_u32(sWh);
    const int lrow = lane & 15;
    const int lhalf = (lane >> 4) * 8;
    const int grp = lane >> 2, qc = (lane & 3) * 2;

    float acc[2][4][4];
#pragma unroll
    for (int mi = 0; mi < 2; mi++)
#pragma unroll
        for (int ni = 0; ni < 4; ni++)
#pragma unroll
            for (int q = 0; q < 4; q++) acc[mi][ni][q] = 0.0f;

#pragma unroll
    for (int k = 0; k < 8; k++) {
        u32 ah[2][4];
#pragma unroll
        for (int mi = 0; mi < 2; mi++) {
            u32 aadd = (u32)((wm * 32 + mi * 16 + lrow + 2 * k) * 40 + lhalf) * 2;
            ldsm_x4(ah[mi][0], ah[mi][1], ah[mi][2], ah[mi][3], sbXh + aadd);
        }
        u32 t0r, t1r, t2r, t3r;
        u32 bh[4][2];
#pragma unroll
        for (int na2 = 0; na2 < 2; na2++) {
            u32 badd = (u32)((na2 * 16 + lrow) * 136 + k * 16 + lhalf) * 2;
            ldsm_x4(t0r, t1r, t2r, t3r, sbWh + badd);
            bh[na2*2][0] = t0r; bh[na2*2][1] = t2r;
            bh[na2*2+1][0] = t1r; bh[na2*2+1][1] = t3r;
        }
#pragma unroll
        for (int mi = 0; mi < 2; mi++)
#pragma unroll
            for (int ni = 0; ni < 4; ni++)
                mma_bf16(acc[mi][ni], ah[mi], bh[ni]);
    }
    __syncthreads();

    u32* stgh = (u32*)sXh;
#pragma unroll
    for (int mi = 0; mi < 2; mi++)
#pragma unroll
        for (int ni = 0; ni < 4; ni++) {
            int ch = ni * 8 + qc;
            float bv0 = __ldg(&bias[ch]), bv1 = __ldg(&bias[ch + 1]);
            int p0 = wm * 32 + mi * 16 + grp, p1 = p0 + 8;
            float v00 = gelu_erf(acc[mi][ni][0] + bv0), v01 = gelu_erf(acc[mi][ni][1] + bv1);
            float v10 = gelu_erf(acc[mi][ni][2] + bv0), v11 = gelu_erf(acc[mi][ni][3] + bv1);
            __nv_bfloat162 th = __halves2bfloat162(__float2bfloat16(v00), __float2bfloat16(v01));
            stgh[p0 * 17 + ni * 4 + (lane & 3)] = *(u32*)&th;
            th = __halves2bfloat162(__float2bfloat16(v10), __float2bfloat16(v11));
            stgh[p1 * 17 + ni * 4 + (lane & 3)] = *(u32*)&th;
        }
    __syncthreads();
    for (int i = tid; i < 256 * 16; i += 256) {
        int p = i >> 4, q = i & 15;
        int l = t0 + p;
        if (l < L_)
            ((u32*)r1h)[((size_t)b * L_ + l) * 16 + q] = stgh[p * 17 + q];
    }
}

// ================= conv2: 32->16 k15, single-bf16 HMMA =================
#define C2ROWS 272
#define C2SM (C2ROWS * 40 * 2 + 16 * 488 * 2)
__global__ void __launch_bounds__(256) conv2_hmma(
    const bf16* __restrict__ r1h,
    const bf16* __restrict__ wh,
    const float* __restrict__ bias,
    bf16* __restrict__ r2h)
{
    extern __shared__ __align__(16) char dsm2[];
    bf16* sXh = (bf16*)dsm2;
    bf16* sWh = sXh + C2ROWS * 40;

    const int tid  = threadIdx.x;
    const int lane = tid & 31;
    const int wm   = tid >> 5;
    const int b    = blockIdx.y;
    const int t0   = blockIdx.x * 256;

    for (int i = tid; i < 16 * 240; i += 256) {
        int r = i / 240, c = i - r * 240;
        ((u32*)sWh)[r * 244 + c] = ((const u32*)wh)[r * 240 + c];
    }
    for (int i = tid; i < C2ROWS * 4; i += 256) {
        int r = i >> 2, q = i & 3;
        int gp = t0 + r - 7;
        uint4 vh = make_uint4(0,0,0,0);
        if (gp >= 0 && gp < L_) {
            size_t o = ((size_t)b * L_ + gp) * 32 + q * 8;
            vh = *(const uint4*)(r1h + o);
        }
        *(uint4*)(sXh + r * 40 + q * 8) = vh;
    }
    __syncthreads();

    const u32 sbXh = smem_u32(sXh);
    const u32 sbWh = smem_u32(sWh);
    const int lrow = lane & 15;
    const int lhalf = (lane >> 4) * 8;
    const u32 boff = sbWh + ((lane & 15) * 488 + lhalf) * 2;
    const int grp = lane >> 2, qc = (lane & 3) * 2;

    float acc[2][2][4];
#pragma unroll
    for (int mi = 0; mi < 2; mi++)
#pragma unroll
        for (int ni = 0; ni < 2; ni++)
#pragma unroll
            for (int q = 0; q < 4; q++) acc[mi][ni][q] = 0.0f;

#pragma unroll 2
    for (int ks = 0; ks < 30; ks++) {
        const int k   = ks >> 1;
        const int icb = (ks & 1) * 16;
        u32 ah[2][4];
#pragma unroll
        for (int mi = 0; mi < 2; mi++) {
            u32 aadd = (u32)((wm * 32 + mi * 16 + lrow + k) * 40 + icb + lhalf) * 2;
            ldsm_x4(ah[mi][0], ah[mi][1], ah[mi][2], ah[mi][3], sbXh + aadd);
        }
        u32 t0r, t1r, t2r, t3r;
        u32 bh[2][2];
        ldsm_x4(t0r, t1r, t2r, t3r, boff + ks * 32);
        bh[0][0] = t0r; bh[0][1] = t2r; bh[1][0] = t1r; bh[1][1] = t3r;

#pragma unroll
        for (int mi = 0; mi < 2; mi++)
#pragma unroll
            for (int ni = 0; ni < 2; ni++)
                mma_bf16(acc[mi][ni], ah[mi], bh[ni]);
    }
    __syncthreads();

    u32* stgh = (u32*)sXh;
#pragma unroll
    for (int mi = 0; mi < 2; mi++)
#pragma unroll
        for (int ni = 0; ni < 2; ni++) {
            int ch = ni * 8 + qc;
            float bv0 = __ldg(&bias[ch]), bv1 = __ldg(&bias[ch + 1]);
            int p0 = wm * 32 + mi * 16 + grp, p1 = p0 + 8;
            float v00 = gelu_erf(acc[mi][ni][0] + bv0), v01 = gelu_erf(acc[mi][ni][1] + bv1);
            float v10 = gelu_erf(acc[mi][ni][2] + bv0), v11 = gelu_erf(acc[mi][ni][3] + bv1);
            __nv_bfloat162 th = __halves2bfloat162(__float2bfloat16(v00), __float2bfloat16(v01));
            stgh[p0 * 9 + ni * 4 + (lane & 3)] = *(u32*)&th;
            th = __halves2bfloat162(__float2bfloat16(v10), __float2bfloat16(v11));
            stgh[p1 * 9 + ni * 4 + (lane & 3)] = *(u32*)&th;
        }
    __syncthreads();
    for (int i = tid; i < 256 * 8; i += 256) {
        int p = i >> 3, q = i & 7;
        int l = t0 + p;
        if (l < L_)
            ((u32*)r2h)[((size_t)b * L_ + l) * 8 + q] = stgh[p * 9 + q];
    }
}

// ================= conv3: 16->8 k15 single-bf16 + residual + pointwise =================
#define C3ROWS 271
#define C3SM (C3ROWS * 40 * 2 + 8 * 248 * 2 + 256 * 9 * 4)
__global__ void __launch_bounds__(256) conv3_hmma(
    const bf16* __restrict__ r2h,
    const bf16* __restrict__ wh,
    const float* __restrict__ bias,
    const bf16* __restrict__ rech, const bf16* __restrict__ recl,
    const float* __restrict__ pw, const float* __restrict__ pb,
    float* __restrict__ out)
{
    extern __shared__ __align__(16) char dsm3[];
    bf16* sXh = (bf16*)dsm3;
    bf16* sWh = sXh + C3ROWS * 40;
    float* sF = (float*)(sWh + 8 * 248);

    const int tid  = threadIdx.x;
    const int lane = tid & 31;
    const int wm   = tid >> 5;
    const int b    = blockIdx.y;
    const int t0   = blockIdx.x * 256;

    for (int i = tid; i < 8 * 120; i += 256) {
        int r = i / 120, c = i - r * 120;
        ((u32*)sWh)[r * 124 + c] = ((const u32*)wh)[r * 120 + c];
    }
    for (int i = tid; i < C3ROWS * 2; i += 256) {
        int r = i >> 1, q = i & 1;
        int gp = t0 + r - 7;
        uint4 vh = make_uint4(0,0,0,0);
        if (gp >= 0 && gp < L_) {
            size_t o = ((size_t)b * L_ + gp) * 16 + q * 8;
            vh = *(const uint4*)(r2h + o);
        }
        *(uint4*)(sXh + r * 40 + q * 8) = vh;
    }
    __syncthreads();

    const u32 sbXh = smem_u32(sXh);
    const u32 sbWh = smem_u32(sWh);
    const int lrow = lane & 15;
    const int lhalf = (lane >> 4) * 8;
    const u32 bbase = ((lane & 7) * 248 + ((lane >> 3) & 1) * 8) * 2;
    const int grp = lane >> 2, qc = (lane & 3) * 2;

    float acc[2][4];
#pragma unroll
    for (int mi = 0; mi < 2; mi++)
#pragma unroll
        for (int q = 0; q < 4; q++) acc[mi][q] = 0.0f;

#pragma unroll
    for (int k = 0; k < 15; k++) {
        u32 ah[2][4];
#pragma unroll
        for (int mi = 0; mi < 2; mi++) {
            u32 aadd = (u32)((wm * 32 + mi * 16 + lrow + k) * 40 + lhalf) * 2;
            ldsm_x4(ah[mi][0], ah[mi][1], ah[mi][2], ah[mi][3], sbXh + aadd);
        }
        u32 bh[2];
        ldsm_x2(bh[0], bh[1], sbWh + bbase + k * 32);
#pragma unroll
        for (int mi = 0; mi < 2; mi++) mma_bf16(acc[mi], ah[mi], bh);
    }
    __syncthreads();

    {
        float bv0 = __ldg(&bias[qc]), bv1 = __ldg(&bias[qc + 1]);
#pragma unroll
        for (int mi = 0; mi < 2; mi++) {
            int p0 = wm * 32 + mi * 16 + grp, p1 = p0 + 8;
            sF[p0 * 9 + qc]     = acc[mi][0] + bv0;
            sF[p0 * 9 + qc + 1] = acc[mi][1] + bv1;
            sF[p1 * 9 + qc]     = acc[mi][2] + bv0;
            sF[p1 * 9 + qc + 1] = acc[mi][3] + bv1;
        }
    }
    __syncthreads();

    {
        int l = t0 + tid;
        if (l < L_) {
            size_t ro = ((size_t)b * L_ + l) * 8;
            uint4 vh = *(const uint4*)(rech + ro);
            uint4 vl = *(const uint4*)(recl + ro);
            const unsigned short* hs = (const unsigned short*)&vh;
            const unsigned short* ls = (const unsigned short*)&vl;
            float resid[8];
#pragma unroll
            for (int c = 0; c < 8; c++) {
                float rv = __bfloat162float(__ushort_as_bfloat16(hs[c]))
                         + __bfloat162float(__ushort_as_bfloat16(ls[c]));
                resid[c] = rv + sF[tid * 9 + c];
            }
#pragma unroll
            for (int o = 0; o < 8; o++) {
                float v = __ldg(&pb[o]);
#pragma unroll
                for (int c = 0; c < 8; c++)
                    v += __ldg(&pw[o * C_ + c]) * resid[c];
                out[((size_t)b * C_ + o) * L_ + l] = v;
            }
        }
    }
}

// ---------------- launcher ----------------
extern "C" void kernel_launch(void* const* d_in, const int* in_sizes, int n_in,
                              void* d_out, int out_size)
{
    const float* X   = (const float*)d_in[0];
    const float* W1  = (const float*)d_in[1];
    const float* b1  = (const float*)d_in[2];
    const float* W2  = (const float*)d_in[3];
    const float* b2  = (const float*)d_in[4];
    const float* rw1 = (const float*)d_in[5];
    const float* rb1 = (const float*)d_in[6];
    const float* rw2 = (const float*)d_in[7];
    const float* rb2 = (const float*)d_in[8];
    const float* rw3 = (const float*)d_in[9];
    const float* rb3 = (const float*)d_in[10];
    const float* pw  = (const float*)d_in[11];
    const float* pb  = (const float*)d_in[12];
    float* out = (float*)d_out;

    f16 *pXf, *pH, *pW1t, *pW2t;
    bf16 *pRech, *pRecl, *pR1h, *pR2h;
    bf16 *pCw1h, *pW2h, *pCw3h;
    float *pPatches;
    cudaGetSymbolAddress((void**)&pXf,   g_Xf);
    cudaGetSymbolAddress((void**)&pH,    g_H);
    cudaGetSymbolAddress((void**)&pW1t,  g_W1t);
    cudaGetSymbolAddress((void**)&pW2t,  g_W2t);
    cudaGetSymbolAddress((void**)&pPatches, g_patches);
    cudaGetSymbolAddress((void**)&pRech, g_rech);
    cudaGetSymbolAddress((void**)&pRecl, g_recl);
    cudaGetSymbolAddress((void**)&pR1h,  g_r1h);
    cudaGetSymbolAddress((void**)&pR2h,  g_r2h);
    cudaGetSymbolAddress((void**)&pCw1h, g_cw1h);
    cudaGetSymbolAddress((void**)&pW2h,  g_w2h);
    cudaGetSymbolAddress((void**)&pCw3h, g_cw3h);

    cudaFuncSetAttribute(gemm_hmma<true,  false>,
                         cudaFuncAttributeMaxDynamicSharedMemorySize, GEMM_SMEM);
    cudaFuncSetAttribute(gemm_hmma<false, true>,
                         cudaFuncAttributeMaxDynamicSharedMemorySize, GEMM_SMEM);
    cudaFuncSetAttribute(conv1_hmma, cudaFuncAttributeMaxDynamicSharedMemorySize, C1SM);
    cudaFuncSetAttribute(conv2_hmma, cudaFuncAttributeMaxDynamicSharedMemorySize, C2SM);
    cudaFuncSetAttribute(conv3_hmma, cudaFuncAttributeMaxDynamicSharedMemorySize, C3SM);

    const int convGrid = (L_ + 255) / 256;   // 8

    // order: GEMM1 stays in ncu capture slot (#4)
    {
        int n8 = (int)((size_t)M_ * 512 / 8);
        xf16_kernel<<<(n8 + 255) / 256, 256>>>(X, pXf, n8);                     // 1
    }
    transp_f16_kernel<<<(512*512 + 255) / 256, 256>>>(W1, pW1t, 512, 512, 512);  // 2
    transp_f16_kernel<<<(256*512 + 255) / 256, 256>>>(W2, pW2t, 512, 200, 256);  // 3

    // 4: GEMM1 -- H = f16(GELU(X @ W1 + b1))
    gemm_hmma<true, false><<<dim3(4, M_ / 128), 256, GEMM_SMEM>>>(
        pXf, pW1t, b1, 512, pH, nullptr);

    w1c_prep_kernel<<<(32*128 + 255) / 256, 256>>>(rw1, pCw1h);                  // 5
    w2_prep_kernel<<<(16*480 + 255) / 256, 256>>>(rw2, pW2h);                    // 6

    // 7: GEMM2 -- patches = H @ W2 + b2  (N-guard skips padded columns)
    gemm_hmma<false, true><<<dim3(2, M_ / 128), 256, GEMM_SMEM>>>(
        pH, pW2t, b2, 200, nullptr, pPatches);

    w3c_prep_kernel<<<(8*240 + 255) / 256, 256>>>(rw3, pCw3h);                   // 8

    // 9: overlap-add -> rec (bf16 hi/lo)
    overlap_add_v3<<<dim3((L_ + 255) / 256, B_), 256>>>(pPatches, pRech, pRecl);

    // 10-12: single-bf16 convs
    conv1_hmma<<<dim3(convGrid, B_), 256, C1SM>>>(pRech, pCw1h, rb1, pR1h);
    conv2_hmma<<<dim3(convGrid, B_), 256, C2SM>>>(pR1h, pW2h, rb2, pR2h);
    conv3_hmma<<<dim3(convGrid, B_), 256, C3SM>>>(pR2h, pCw3h, rb3,
                                                  pRech, pRecl, pw, pb, out);
}